// round 1
// baseline (speedup 1.0000x reference)
#include <cuda_runtime.h>

#define EPSF 1e-5f

// per-batch pooled-key tensor: [b][g][l][c] = 8*4*49*8
__device__ float g_k[8 * 4 * 49 * 8];

// ---------------------------------------------------------------------------
// Kernel 1: adaptive-pool(64->7)^2 + 1x1 conv + BN  ->  g_k[b][g][l][c]
// grid (7, 8) = (pool row p, batch b), 256 threads
// ---------------------------------------------------------------------------
__global__ void k_kernel(const float* __restrict__ x,
                         const float* __restrict__ wk_w,
                         const float* __restrict__ wk_g,
                         const float* __restrict__ wk_b,
                         const float* __restrict__ wk_m,
                         const float* __restrict__ wk_v)
{
    __shared__ float kp[32 * 7];
    const int p = blockIdx.x;   // pool row 0..6
    const int b = blockIdx.y;   // batch
    const int tid = threadIdx.x;

    const int sh = (p * 64) / 7;
    const int eh = ((p + 1) * 64 + 6) / 7;
    const float* xb = x + ((size_t)b * 64 + 32) * 4096;  // context half

    for (int idx = tid; idx < 32 * 7; idx += 256) {
        const int ci = idx / 7, q = idx % 7;
        const int sw = (q * 64) / 7;
        const int ew = ((q + 1) * 64 + 6) / 7;
        const float* base = xb + ci * 4096 + sh * 64 + sw;
        float acc = 0.f;
        for (int u = 0; u < eh - sh; u++) {
            float racc = 0.f;
            for (int v = 0; v < ew - sw; v++)
                racc += base[u * 64 + v];
            acc += racc;
        }
        kp[ci * 7 + q] = acc / (float)((eh - sh) * (ew - sw));
    }
    __syncthreads();

    for (int idx = tid; idx < 32 * 7; idx += 256) {
        const int o = idx / 7, q = idx % 7;
        const float alpha = wk_g[o] * rsqrtf(wk_v[o] + EPSF);
        const float beta  = wk_b[o] - wk_m[o] * alpha;
        float acc = 0.f;
        #pragma unroll
        for (int i = 0; i < 32; i++)
            acc += wk_w[o * 32 + i] * kp[i * 7 + q];
        const float val = alpha * acc + beta;
        const int g = o >> 3, c = o & 7;
        g_k[(((b * 4 + g) * 49) + p * 7 + q) * 8 + c] = val;
    }
}

// ---------------------------------------------------------------------------
// Kernel 2: fully-fused main kernel.
// Block = (b, 8x8 pixel tile). 256 threads = 64 pixels x 4 heads.
// ---------------------------------------------------------------------------
// shared memory layout (floats)
constexpr int SM_XT1 = 0;                    // 12*12*36 = 5184  (x ch 0..31, halo 2)
constexpr int SM_XT2 = 5184;                 // 14*14*36 = 7056  (x ch 32..63, halo 3)
constexpr int SM_WQ  = 12240;                // 32*36 = 1152 (BN+SCALE folded)
constexpr int SM_QB  = 13392;                // 32
constexpr int SM_PW  = 13424;                // 74*52 = 3848 (row pad 52)
constexpr int SM_PB  = 17272;                // 76 (74 + pad)
constexpr int SM_KT  = 17348;                // 4*49*8 = 1568
constexpr int SM_R1  = 18916;                // 324
constexpr int SM_R2  = 19240;                // 676
constexpr int SM_DYW = 19916;                // 64*68 = 4352 (BN folded)
constexpr int SM_DYB = 24268;                // 64
constexpr int SM_OB  = 24332;                // 64*68 = 4352
constexpr int SM_TOTAL = 28684;              // floats -> 114736 bytes

__device__ __forceinline__ float dot49(const float* __restrict__ wrow,
                                       const float* __restrict__ s)
{
    float a0 = 0.f, a1 = 0.f, a2 = 0.f, a3 = 0.f;
    #pragma unroll
    for (int l4 = 0; l4 < 12; l4++) {
        const float4 wv = *(const float4*)(wrow + l4 * 4);
        a0 += wv.x * s[l4 * 4 + 0];
        a1 += wv.y * s[l4 * 4 + 1];
        a2 += wv.z * s[l4 * 4 + 2];
        a3 += wv.w * s[l4 * 4 + 3];
    }
    return (a0 + a1) + (a2 + a3) + wrow[48] * s[48];
}

__global__ void __launch_bounds__(256, 1)
main_kernel(const float* __restrict__ x,
            const float* __restrict__ wq_w, const float* __restrict__ wq_g,
            const float* __restrict__ wq_b, const float* __restrict__ wq_m,
            const float* __restrict__ wq_v,
            const float* __restrict__ proj_w, const float* __restrict__ proj_b,
            const float* __restrict__ rpb1, const float* __restrict__ rpb2,
            const float* __restrict__ dy_w, const float* __restrict__ dy_g,
            const float* __restrict__ dy_b, const float* __restrict__ dy_m,
            const float* __restrict__ dy_v,
            float* __restrict__ out)
{
    extern __shared__ float sm[];
    float* xt1 = sm + SM_XT1;
    float* xt2 = sm + SM_XT2;
    float* wq  = sm + SM_WQ;
    float* qb  = sm + SM_QB;
    float* pw  = sm + SM_PW;
    float* pb  = sm + SM_PB;
    float* kt  = sm + SM_KT;
    float* r1s = sm + SM_R1;
    float* r2s = sm + SM_R2;
    float* dyw = sm + SM_DYW;
    float* dyb = sm + SM_DYB;
    float* ob  = sm + SM_OB;

    const int tid = threadIdx.x;
    const int b  = blockIdx.z;
    const int h0 = blockIdx.y * 8;
    const int w0 = blockIdx.x * 8;
    const float* xb = x + (size_t)b * 64 * 4096;

    // ---- cooperative loads ----
    for (int idx = tid; idx < 32 * 144; idx += 256) {
        const int t = idx % 12, s0 = (idx / 12) % 12, ch = idx / 144;
        const int gr = min(max(h0 - 2 + s0, 0), 63);
        const int gc = min(max(w0 - 2 + t, 0), 63);
        xt1[(s0 * 12 + t) * 36 + ch] = xb[ch * 4096 + gr * 64 + gc];
    }
    for (int idx = tid; idx < 32 * 196; idx += 256) {
        const int t = idx % 14, s0 = (idx / 14) % 14, ch = idx / 196;
        const int gr = min(max(h0 - 3 + s0, 0), 63);
        const int gc = min(max(w0 - 3 + t, 0), 63);
        xt2[(s0 * 14 + t) * 36 + ch] = xb[(32 + ch) * 4096 + gr * 64 + gc];
    }
    for (int idx = tid; idx < 1024; idx += 256) {
        const int o = idx >> 5, i = idx & 31;
        const float alpha = wq_g[o] * rsqrtf(wq_v[o] + EPSF) * 0.25f;  // SCALE folded
        wq[o * 36 + i] = alpha * wq_w[idx];
        if (i == 0) qb[o] = 0.25f * wq_b[o] - wq_m[o] * alpha;
    }
    for (int idx = tid; idx < 74 * 49; idx += 256)
        pw[(idx / 49) * 52 + idx % 49] = proj_w[idx];
    if (tid < 74) pb[tid] = proj_b[tid];
    for (int idx = tid; idx < 1568; idx += 256) kt[idx] = g_k[b * 1568 + idx];
    for (int idx = tid; idx < 324; idx += 256) r1s[idx] = rpb1[idx];
    for (int idx = tid; idx < 676; idx += 256) r2s[idx] = rpb2[idx];
    for (int idx = tid; idx < 4096; idx += 256) {
        const int o = idx >> 6, ch = idx & 63;
        const float alpha = dy_g[o] * rsqrtf(dy_v[o] + EPSF);
        dyw[o * 68 + ch] = alpha * dy_w[idx];
        if (ch == 0) dyb[o] = dy_b[o] - dy_m[o] * alpha;
    }
    __syncthreads();

    // ---- per (pixel, head) compute ----
    {
        const int p   = tid >> 2;        // pixel in tile 0..63
        const int g   = tid & 3;         // head
        const int ph  = p >> 3, pwd = p & 7;
        const int h = h0 + ph, w = w0 + pwd;

        // q = BN(conv1x1(x_lo)) * SCALE, 8 channels of this head
        float q[8];
        {
            const float* xpix = xt1 + ((ph + 2) * 12 + (pwd + 2)) * 36;
            const float* wrow = wq + g * 8 * 36;
            #pragma unroll
            for (int c = 0; c < 8; c++) q[c] = qb[g * 8 + c];
            #pragma unroll
            for (int i4 = 0; i4 < 8; i4++) {
                const float4 xv = *(const float4*)(xpix + i4 * 4);
                #pragma unroll
                for (int c = 0; c < 8; c++) {
                    const float4 wv = *(const float4*)(wrow + c * 36 + i4 * 4);
                    q[c] += wv.x * xv.x + wv.y * xv.y + wv.z * xv.z + wv.w * xv.w;
                }
            }
        }

        // s[l] = q . k[l]
        float s[49];
        {
            const float* ktg = kt + g * 392;
            #pragma unroll
            for (int l = 0; l < 49; l++) {
                const float4 k0 = *(const float4*)(ktg + l * 8);
                const float4 k1 = *(const float4*)(ktg + l * 8 + 4);
                s[l] = ((q[0] * k0.x + q[1] * k0.y) + (q[2] * k0.z + q[3] * k0.w))
                     + ((q[4] * k1.x + q[5] * k1.y) + (q[6] * k1.z + q[7] * k1.w));
            }
        }

        const int ihr = 63 - h, iwr = 63 - w;

        // ================= part 1: 5x5 =================
        {
            const int ih1 = min(ihr, 2) + max(0, ihr - 61);
            const int iw1 = min(iwr, 2) + max(0, iwr - 61);
            const float* r1g = r1s + g * 81 + ih1 * 9 + iw1;

            float e1[25];
            float mx = -3.0e38f;
            #pragma unroll
            for (int ki = 0; ki < 5; ki++) {
                #pragma unroll
                for (int kj = 0; kj < 5; kj++) {
                    const int o = ki * 5 + kj;
                    const float v = pb[o] + dot49(pw + o * 52, s) + r1g[ki * 9 + kj];
                    e1[o] = v;
                    mx = fmaxf(mx, v);
                }
            }
            float sum = 0.f;
            #pragma unroll
            for (int o = 0; o < 25; o++) {
                const float e = __expf(e1[o] - mx);
                e1[o] = e;
                sum += e;
            }
            const int si = min(max(h - 2, 0), 59) - (h0 - 2);
            const int sj = min(max(w - 2, 0), 59) - (w0 - 2);
            float4 accA = make_float4(0, 0, 0, 0), accB = make_float4(0, 0, 0, 0);
            #pragma unroll
            for (int ki = 0; ki < 5; ki++) {
                const float* row = xt1 + ((si + ki) * 12 + sj) * 36 + g * 8;
                #pragma unroll
                for (int kj = 0; kj < 5; kj++) {
                    const float a = e1[ki * 5 + kj];
                    const float4 v0 = *(const float4*)(row + kj * 36);
                    const float4 v1 = *(const float4*)(row + kj * 36 + 4);
                    accA.x += a * v0.x; accA.y += a * v0.y;
                    accA.z += a * v0.z; accA.w += a * v0.w;
                    accB.x += a * v1.x; accB.y += a * v1.y;
                    accB.z += a * v1.z; accB.w += a * v1.w;
                }
            }
            const float inv = 1.0f / sum;
            float* obp = ob + p * 68 + g * 8;
            obp[0] = accA.x * inv; obp[1] = accA.y * inv;
            obp[2] = accA.z * inv; obp[3] = accA.w * inv;
            obp[4] = accB.x * inv; obp[5] = accB.y * inv;
            obp[6] = accB.z * inv; obp[7] = accB.w * inv;
        }

        // ================= part 2: 7x7 =================
        {
            const int ih2 = min(ihr, 3) + max(0, ihr - 60);
            const int iw2 = min(iwr, 3) + max(0, iwr - 60);
            const float* r2g = r2s + g * 169 + ih2 * 13 + iw2;

            float e2[49];
            float mx = -3.0e38f;
            #pragma unroll
            for (int ki = 0; ki < 7; ki++) {
                #pragma unroll
                for (int kj = 0; kj < 7; kj++) {
                    const int o = ki * 7 + kj;
                    const float v = pb[25 + o] + dot49(pw + (25 + o) * 52, s)
                                  + r2g[ki * 13 + kj];
                    e2[o] = v;
                    mx = fmaxf(mx, v);
                }
            }
            float sum = 0.f;
            #pragma unroll
            for (int o = 0; o < 49; o++) {
                const float e = __expf(e2[o] - mx);
                e2[o] = e;
                sum += e;
            }
            const int si = min(max(h - 3, 0), 57) - (h0 - 3);
            const int sj = min(max(w - 3, 0), 57) - (w0 - 3);
            float4 accA = make_float4(0, 0, 0, 0), accB = make_float4(0, 0, 0, 0);
            #pragma unroll
            for (int ki = 0; ki < 7; ki++) {
                const float* row = xt2 + ((si + ki) * 14 + sj) * 36 + g * 8;
                #pragma unroll
                for (int kj = 0; kj < 7; kj++) {
                    const float a = e2[ki * 7 + kj];
                    const float4 v0 = *(const float4*)(row + kj * 36);
                    const float4 v1 = *(const float4*)(row + kj * 36 + 4);
                    accA.x += a * v0.x; accA.y += a * v0.y;
                    accA.z += a * v0.z; accA.w += a * v0.w;
                    accB.x += a * v1.x; accB.y += a * v1.y;
                    accB.z += a * v1.z; accB.w += a * v1.w;
                }
            }
            const float inv = 1.0f / sum;
            float* obp = ob + p * 68 + 32 + g * 8;
            obp[0] = accA.x * inv; obp[1] = accA.y * inv;
            obp[2] = accA.z * inv; obp[3] = accA.w * inv;
            obp[4] = accB.x * inv; obp[5] = accB.y * inv;
            obp[6] = accB.z * inv; obp[7] = accB.w * inv;
        }
    }
    __syncthreads();

    // ---- phase 2: final 1x1 conv (dy) + BN, 16 output channels per thread ----
    {
        const int p = tid >> 2;
        const int r = tid & 3;
        float acc[16];
        #pragma unroll
        for (int j = 0; j < 16; j++) acc[j] = dyb[r + 4 * j];
        const float* obp = ob + p * 68;
        #pragma unroll
        for (int ch4 = 0; ch4 < 16; ch4++) {
            const float4 xv = *(const float4*)(obp + ch4 * 4);
            #pragma unroll
            for (int j = 0; j < 16; j++) {
                const float4 wv = *(const float4*)(dyw + (r + 4 * j) * 68 + ch4 * 4);
                acc[j] += wv.x * xv.x + wv.y * xv.y + wv.z * xv.z + wv.w * xv.w;
            }
        }
        const int h = h0 + (p >> 3), w = w0 + (p & 7);
        float* outp = out + (size_t)b * 64 * 4096 + h * 64 + w;
        #pragma unroll
        for (int j = 0; j < 16; j++)
            outp[(size_t)(r + 4 * j) * 4096] = acc[j];
    }
}

// ---------------------------------------------------------------------------
extern "C" void kernel_launch(void* const* d_in, const int* in_sizes, int n_in,
                              void* d_out, int out_size)
{
    const float* x      = (const float*)d_in[0];
    const float* wq_w   = (const float*)d_in[1];
    const float* wq_g   = (const float*)d_in[2];
    const float* wq_b   = (const float*)d_in[3];
    const float* wq_m   = (const float*)d_in[4];
    const float* wq_v   = (const float*)d_in[5];
    const float* wk_w   = (const float*)d_in[6];
    const float* wk_g   = (const float*)d_in[7];
    const float* wk_b   = (const float*)d_in[8];
    const float* wk_m   = (const float*)d_in[9];
    const float* wk_v   = (const float*)d_in[10];
    const float* proj_w = (const float*)d_in[11];
    const float* proj_b = (const float*)d_in[12];
    const float* rpb1   = (const float*)d_in[13];
    const float* rpb2   = (const float*)d_in[14];
    const float* dy_w   = (const float*)d_in[15];
    const float* dy_g   = (const float*)d_in[16];
    const float* dy_b   = (const float*)d_in[17];
    const float* dy_m   = (const float*)d_in[18];
    const float* dy_v   = (const float*)d_in[19];
    float* out = (float*)d_out;

    cudaFuncSetAttribute(main_kernel,
                         cudaFuncAttributeMaxDynamicSharedMemorySize,
                         SM_TOTAL * (int)sizeof(float));

    dim3 gk(7, 8);
    k_kernel<<<gk, 256>>>(x, wk_w, wk_g, wk_b, wk_m, wk_v);

    dim3 gm(8, 8, 8);  // (w tiles, h tiles, batch)
    main_kernel<<<gm, 256, SM_TOTAL * (int)sizeof(float)>>>(
        x, wq_w, wq_g, wq_b, wq_m, wq_v,
        proj_w, proj_b, rpb1, rpb2,
        dy_w, dy_g, dy_b, dy_m, dy_v, out);
}

// round 2
// speedup vs baseline: 1.4996x; 1.4996x over previous
#include <cuda_runtime.h>

#define EPSF 1e-5f

// per-batch pooled-key tensor: [b][g][l][c] = 8*4*49*8
__device__ float g_k[8 * 4 * 49 * 8];

// ---------------------------------------------------------------------------
// Kernel 1: adaptive-pool(64->7)^2 + 1x1 conv + BN  ->  g_k[b][g][l][c]
// ---------------------------------------------------------------------------
__global__ void k_kernel(const float* __restrict__ x,
                         const float* __restrict__ wk_w,
                         const float* __restrict__ wk_g,
                         const float* __restrict__ wk_b,
                         const float* __restrict__ wk_m,
                         const float* __restrict__ wk_v)
{
    __shared__ float kp[32 * 7];
    const int p = blockIdx.x;   // pool row 0..6
    const int b = blockIdx.y;   // batch
    const int tid = threadIdx.x;

    const int sh = (p * 64) / 7;
    const int eh = ((p + 1) * 64 + 6) / 7;
    const float* xb = x + ((size_t)b * 64 + 32) * 4096;  // context half

    for (int idx = tid; idx < 32 * 7; idx += 256) {
        const int ci = idx / 7, q = idx % 7;
        const int sw = (q * 64) / 7;
        const int ew = ((q + 1) * 64 + 6) / 7;
        const float* base = xb + ci * 4096 + sh * 64 + sw;
        float acc = 0.f;
        for (int u = 0; u < eh - sh; u++) {
            float racc = 0.f;
            for (int v = 0; v < ew - sw; v++)
                racc += base[u * 64 + v];
            acc += racc;
        }
        kp[ci * 7 + q] = acc / (float)((eh - sh) * (ew - sw));
    }
    __syncthreads();

    for (int idx = tid; idx < 32 * 7; idx += 256) {
        const int o = idx / 7, q = idx % 7;
        const float alpha = wk_g[o] * rsqrtf(wk_v[o] + EPSF);
        const float beta  = wk_b[o] - wk_m[o] * alpha;
        float acc = 0.f;
        #pragma unroll
        for (int i = 0; i < 32; i++)
            acc += wk_w[o * 32 + i] * kp[i * 7 + q];
        const float val = alpha * acc + beta;
        const int g = o >> 3, c = o & 7;
        g_k[(((b * 4 + g) * 49) + p * 7 + q) * 8 + c] = val;
    }
}

// ---------------------------------------------------------------------------
// Kernel 2: fully-fused main kernel, 2 CTAs/SM.
// Block = (b, 8x8 pixel tile). 256 threads = 64 pixels x 4 heads.
// ---------------------------------------------------------------------------
// shared memory layout (floats). ob (output buffer, 64*68=4352) ALIASES xt1
// (5184) after all xt reads complete.
constexpr int SM_XT1 = 0;                    // 12*12*36 = 5184  (x ch 0..31, halo 2)
constexpr int SM_XT2 = 5184;                 // 14*14*36 = 7056  (x ch 32..63, halo 3)
constexpr int SM_WQ  = 12240;                // 32*36 (BN+SCALE folded)
constexpr int SM_QB  = 13392;                // 32
constexpr int SM_PW  = 13424;                // 74*52 (row pad 52)
constexpr int SM_PB  = 17272;                // 76
constexpr int SM_KT  = 17348;                // 4*49*8 = 1568
constexpr int SM_R1  = 18916;                // 324
constexpr int SM_R2  = 19240;                // 676
constexpr int SM_DYW = 19916;                // 64*68 = 4352 (BN folded)
constexpr int SM_DYB = 24268;                // 64
constexpr int SM_TOTAL = 24332;              // floats -> 97328 bytes (2 CTAs/SM)

__device__ __forceinline__ float dot49(const float* __restrict__ wrow,
                                       const float* __restrict__ s)
{
    float a0 = 0.f, a1 = 0.f, a2 = 0.f, a3 = 0.f;
    #pragma unroll
    for (int l4 = 0; l4 < 12; l4++) {
        const float4 wv = *(const float4*)(wrow + l4 * 4);
        a0 += wv.x * s[l4 * 4 + 0];
        a1 += wv.y * s[l4 * 4 + 1];
        a2 += wv.z * s[l4 * 4 + 2];
        a3 += wv.w * s[l4 * 4 + 3];
    }
    return (a0 + a1) + (a2 + a3) + wrow[48] * s[48];
}

__global__ void __launch_bounds__(256, 2)
main_kernel(const float* __restrict__ x,
            const float* __restrict__ wq_w, const float* __restrict__ wq_g,
            const float* __restrict__ wq_b, const float* __restrict__ wq_m,
            const float* __restrict__ wq_v,
            const float* __restrict__ proj_w, const float* __restrict__ proj_b,
            const float* __restrict__ rpb1, const float* __restrict__ rpb2,
            const float* __restrict__ dy_w, const float* __restrict__ dy_g,
            const float* __restrict__ dy_b, const float* __restrict__ dy_m,
            const float* __restrict__ dy_v,
            float* __restrict__ out)
{
    extern __shared__ float sm[];
    float* xt1 = sm + SM_XT1;
    float* xt2 = sm + SM_XT2;
    float* wq  = sm + SM_WQ;
    float* qb  = sm + SM_QB;
    float* pw  = sm + SM_PW;
    float* pb  = sm + SM_PB;
    float* kt  = sm + SM_KT;
    float* r1s = sm + SM_R1;
    float* r2s = sm + SM_R2;
    float* dyw = sm + SM_DYW;
    float* dyb = sm + SM_DYB;
    float* ob  = sm + SM_XT1;   // alias: valid only after the post-compute barrier

    const int tid = threadIdx.x;
    const int b  = blockIdx.z;
    const int h0 = blockIdx.y * 8;
    const int w0 = blockIdx.x * 8;
    const float* xb = x + (size_t)b * 64 * 4096;

    // ---- cooperative loads ----
    for (int idx = tid; idx < 32 * 144; idx += 256) {
        const int t = idx % 12, s0 = (idx / 12) % 12, ch = idx / 144;
        const int gr = min(max(h0 - 2 + s0, 0), 63);
        const int gc = min(max(w0 - 2 + t, 0), 63);
        xt1[(s0 * 12 + t) * 36 + ch] = xb[ch * 4096 + gr * 64 + gc];
    }
    for (int idx = tid; idx < 32 * 196; idx += 256) {
        const int t = idx % 14, s0 = (idx / 14) % 14, ch = idx / 196;
        const int gr = min(max(h0 - 3 + s0, 0), 63);
        const int gc = min(max(w0 - 3 + t, 0), 63);
        xt2[(s0 * 14 + t) * 36 + ch] = xb[(32 + ch) * 4096 + gr * 64 + gc];
    }
    for (int idx = tid; idx < 1024; idx += 256) {
        const int o = idx >> 5, i = idx & 31;
        const float alpha = wq_g[o] * rsqrtf(wq_v[o] + EPSF) * 0.25f;  // SCALE folded
        wq[o * 36 + i] = alpha * wq_w[idx];
        if (i == 0) qb[o] = 0.25f * wq_b[o] - wq_m[o] * alpha;
    }
    for (int idx = tid; idx < 74 * 49; idx += 256)
        pw[(idx / 49) * 52 + idx % 49] = proj_w[idx];
    if (tid < 74) pb[tid] = proj_b[tid];
    for (int idx = tid; idx < 1568; idx += 256) kt[idx] = g_k[b * 1568 + idx];
    for (int idx = tid; idx < 324; idx += 256) r1s[idx] = rpb1[idx];
    for (int idx = tid; idx < 676; idx += 256) r2s[idx] = rpb2[idx];
    for (int idx = tid; idx < 4096; idx += 256) {
        const int o = idx >> 6, ch = idx & 63;
        const float alpha = dy_g[o] * rsqrtf(dy_v[o] + EPSF);
        dyw[o * 68 + ch] = alpha * dy_w[idx];
        if (ch == 0) dyb[o] = dy_b[o] - dy_m[o] * alpha;
    }
    __syncthreads();

    // ---- per (pixel, head) compute ----
    const int p   = tid >> 2;        // pixel in tile 0..63
    const int g   = tid & 3;         // head
    float o1[8], o2[8];
    {
        const int ph  = p >> 3, pwd = p & 7;
        const int h = h0 + ph, w = w0 + pwd;

        // q = BN(conv1x1(x_lo)) * SCALE, 8 channels of this head
        float q[8];
        {
            const float* xpix = xt1 + ((ph + 2) * 12 + (pwd + 2)) * 36;
            const float* wrow = wq + g * 8 * 36;
            #pragma unroll
            for (int c = 0; c < 8; c++) q[c] = qb[g * 8 + c];
            #pragma unroll
            for (int i4 = 0; i4 < 8; i4++) {
                const float4 xv = *(const float4*)(xpix + i4 * 4);
                #pragma unroll
                for (int c = 0; c < 8; c++) {
                    const float4 wv = *(const float4*)(wrow + c * 36 + i4 * 4);
                    q[c] += wv.x * xv.x + wv.y * xv.y + wv.z * xv.z + wv.w * xv.w;
                }
            }
        }

        // s[l] = q . k[l]
        float s[49];
        {
            const float* ktg = kt + g * 392;
            #pragma unroll
            for (int l = 0; l < 49; l++) {
                const float4 k0 = *(const float4*)(ktg + l * 8);
                const float4 k1 = *(const float4*)(ktg + l * 8 + 4);
                s[l] = ((q[0] * k0.x + q[1] * k0.y) + (q[2] * k0.z + q[3] * k0.w))
                     + ((q[4] * k1.x + q[5] * k1.y) + (q[6] * k1.z + q[7] * k1.w));
            }
        }

        const int ihr = 63 - h, iwr = 63 - w;

        // ===== part 1: 5x5, fused logit->exp->aggregate (no-max softmax) =====
        {
            const int ih1 = min(ihr, 2) + max(0, ihr - 61);
            const int iw1 = min(iwr, 2) + max(0, iwr - 61);
            const float* r1g = r1s + g * 81 + ih1 * 9 + iw1;
            const int si = min(max(h - 2, 0), 59) - (h0 - 2);
            const int sj = min(max(w - 2, 0), 59) - (w0 - 2);

            float4 accA = make_float4(0, 0, 0, 0), accB = make_float4(0, 0, 0, 0);
            float sum = 0.f;
            #pragma unroll
            for (int ki = 0; ki < 5; ki++) {
                const float* row = xt1 + ((si + ki) * 12 + sj) * 36 + g * 8;
                #pragma unroll
                for (int kj = 0; kj < 5; kj++) {
                    const int o = ki * 5 + kj;
                    const float v = pb[o] + dot49(pw + o * 52, s) + r1g[ki * 9 + kj];
                    const float e = __expf(v);
                    sum += e;
                    const float4 v0 = *(const float4*)(row + kj * 36);
                    const float4 v1 = *(const float4*)(row + kj * 36 + 4);
                    accA.x += e * v0.x; accA.y += e * v0.y;
                    accA.z += e * v0.z; accA.w += e * v0.w;
                    accB.x += e * v1.x; accB.y += e * v1.y;
                    accB.z += e * v1.z; accB.w += e * v1.w;
                }
            }
            const float inv = 1.0f / sum;
            o1[0] = accA.x * inv; o1[1] = accA.y * inv;
            o1[2] = accA.z * inv; o1[3] = accA.w * inv;
            o1[4] = accB.x * inv; o1[5] = accB.y * inv;
            o1[6] = accB.z * inv; o1[7] = accB.w * inv;
        }

        // ===== part 2: 7x7, fused =====
        {
            const int ih2 = min(ihr, 3) + max(0, ihr - 60);
            const int iw2 = min(iwr, 3) + max(0, iwr - 60);
            const float* r2g = r2s + g * 169 + ih2 * 13 + iw2;
            const int si = min(max(h - 3, 0), 57) - (h0 - 3);
            const int sj = min(max(w - 3, 0), 57) - (w0 - 3);

            float4 accA = make_float4(0, 0, 0, 0), accB = make_float4(0, 0, 0, 0);
            float sum = 0.f;
            #pragma unroll
            for (int ki = 0; ki < 7; ki++) {
                const float* row = xt2 + ((si + ki) * 14 + sj) * 36 + g * 8;
                #pragma unroll
                for (int kj = 0; kj < 7; kj++) {
                    const int o = ki * 7 + kj;
                    const float v = pb[25 + o] + dot49(pw + (25 + o) * 52, s)
                                  + r2g[ki * 13 + kj];
                    const float e = __expf(v);
                    sum += e;
                    const float4 v0 = *(const float4*)(row + kj * 36);
                    const float4 v1 = *(const float4*)(row + kj * 36 + 4);
                    accA.x += e * v0.x; accA.y += e * v0.y;
                    accA.z += e * v0.z; accA.w += e * v0.w;
                    accB.x += e * v1.x; accB.y += e * v1.y;
                    accB.z += e * v1.z; accB.w += e * v1.w;
                }
            }
            const float inv = 1.0f / sum;
            o2[0] = accA.x * inv; o2[1] = accA.y * inv;
            o2[2] = accA.z * inv; o2[3] = accA.w * inv;
            o2[4] = accB.x * inv; o2[5] = accB.y * inv;
            o2[6] = accB.z * inv; o2[7] = accB.w * inv;
        }
    }

    __syncthreads();   // all xt1/xt2 reads done -> safe to overwrite with ob

    {
        float* obp = ob + p * 68 + g * 8;
        *(float4*)(obp)     = make_float4(o1[0], o1[1], o1[2], o1[3]);
        *(float4*)(obp + 4) = make_float4(o1[4], o1[5], o1[6], o1[7]);
        *(float4*)(obp + 32)     = make_float4(o2[0], o2[1], o2[2], o2[3]);
        *(float4*)(obp + 32 + 4) = make_float4(o2[4], o2[5], o2[6], o2[7]);
    }
    __syncthreads();

    // ---- phase 2: final 1x1 conv (dy) + BN, 16 output channels per thread ----
    {
        const int r = tid & 3;
        float acc[16];
        #pragma unroll
        for (int j = 0; j < 16; j++) acc[j] = dyb[r + 4 * j];
        const float* obp = ob + p * 68;
        #pragma unroll
        for (int ch4 = 0; ch4 < 16; ch4++) {
            const float4 xv = *(const float4*)(obp + ch4 * 4);
            #pragma unroll
            for (int j = 0; j < 16; j++) {
                const float4 wv = *(const float4*)(dyw + (r + 4 * j) * 68 + ch4 * 4);
                acc[j] += wv.x * xv.x + wv.y * xv.y + wv.z * xv.z + wv.w * xv.w;
            }
        }
        const int h = h0 + (p >> 3), w = w0 + (p & 7);
        float* outp = out + (size_t)b * 64 * 4096 + h * 64 + w;
        #pragma unroll
        for (int j = 0; j < 16; j++)
            outp[(size_t)(r + 4 * j) * 4096] = acc[j];
    }
}

// ---------------------------------------------------------------------------
extern "C" void kernel_launch(void* const* d_in, const int* in_sizes, int n_in,
                              void* d_out, int out_size)
{
    const float* x      = (const float*)d_in[0];
    const float* wq_w   = (const float*)d_in[1];
    const float* wq_g   = (const float*)d_in[2];
    const float* wq_b   = (const float*)d_in[3];
    const float* wq_m   = (const float*)d_in[4];
    const float* wq_v   = (const float*)d_in[5];
    const float* wk_w   = (const float*)d_in[6];
    const float* wk_g   = (const float*)d_in[7];
    const float* wk_b   = (const float*)d_in[8];
    const float* wk_m   = (const float*)d_in[9];
    const float* wk_v   = (const float*)d_in[10];
    const float* proj_w = (const float*)d_in[11];
    const float* proj_b = (const float*)d_in[12];
    const float* rpb1   = (const float*)d_in[13];
    const float* rpb2   = (const float*)d_in[14];
    const float* dy_w   = (const float*)d_in[15];
    const float* dy_g   = (const float*)d_in[16];
    const float* dy_b   = (const float*)d_in[17];
    const float* dy_m   = (const float*)d_in[18];
    const float* dy_v   = (const float*)d_in[19];
    float* out = (float*)d_out;

    cudaFuncSetAttribute(main_kernel,
                         cudaFuncAttributeMaxDynamicSharedMemorySize,
                         SM_TOTAL * (int)sizeof(float));

    dim3 gk(7, 8);
    k_kernel<<<gk, 256>>>(x, wk_w, wk_g, wk_b, wk_m, wk_v);

    dim3 gm(8, 8, 8);  // (w tiles, h tiles, batch)
    main_kernel<<<gm, 256, SM_TOTAL * (int)sizeof(float)>>>(
        x, wq_w, wq_g, wq_b, wq_m, wq_v,
        proj_w, proj_b, rpb1, rpb2,
        dy_w, dy_g, dy_b, dy_m, dy_v, out);
}

// round 3
// speedup vs baseline: 1.5957x; 1.0641x over previous
#include <cuda_runtime.h>

#define EPSF 1e-5f

typedef unsigned long long u64;

__device__ __forceinline__ u64 ffma2(u64 a, u64 b, u64 c) {
    u64 d;
    asm("fma.rn.f32x2 %0, %1, %2, %3;" : "=l"(d) : "l"(a), "l"(b), "l"(c));
    return d;
}
__device__ __forceinline__ u64 fadd2(u64 a, u64 b) {
    u64 d;
    asm("add.rn.f32x2 %0, %1, %2;" : "=l"(d) : "l"(a), "l"(b));
    return d;
}
__device__ __forceinline__ u64 pack2(float lo, float hi) {
    u64 d;
    asm("mov.b64 %0, {%1, %2};" : "=l"(d) : "f"(lo), "f"(hi));
    return d;
}
__device__ __forceinline__ float2 unpack2(u64 a) {
    float2 r;
    asm("mov.b64 {%0, %1}, %2;" : "=f"(r.x), "=f"(r.y) : "l"(a));
    return r;
}

// ---------------------------------------------------------------------------
// device scratch (static allocation only)
// ---------------------------------------------------------------------------
__device__ float g_k[8 * 4 * 49 * 8];     // pooled keys [b][g][l][c]
__device__ float g_wq[32 * 32];           // BN+SCALE folded q weights
__device__ float g_qb[32];
__device__ float g_dyw[64 * 64];          // BN folded dy weights
__device__ float g_dyb[64];
__device__ float g_e[512 * 74 * 256];     // unnormalized exp, [blk][o][tid]
__device__ float g_inv[512 * 2 * 256];    // 1/sum, [blk][part][tid]

// ---------------------------------------------------------------------------
// Kernel 1: pooled-k path + weight folding
// ---------------------------------------------------------------------------
__global__ void k_kernel(const float* __restrict__ x,
                         const float* __restrict__ wk_w,
                         const float* __restrict__ wk_g,
                         const float* __restrict__ wk_b,
                         const float* __restrict__ wk_m,
                         const float* __restrict__ wk_v,
                         const float* __restrict__ wq_w,
                         const float* __restrict__ wq_g,
                         const float* __restrict__ wq_b,
                         const float* __restrict__ wq_m,
                         const float* __restrict__ wq_v,
                         const float* __restrict__ dy_w,
                         const float* __restrict__ dy_g,
                         const float* __restrict__ dy_b,
                         const float* __restrict__ dy_m,
                         const float* __restrict__ dy_v)
{
    __shared__ float kp[32 * 7];
    const int p = blockIdx.x;   // pool row 0..6
    const int b = blockIdx.y;   // batch
    const int tid = threadIdx.x;

    // block (0,0) additionally folds the q and dy weights
    if (p == 0 && b == 0) {
        for (int idx = tid; idx < 1024; idx += 256) {
            const int o = idx >> 5, i = idx & 31;
            const float alpha = wq_g[o] * rsqrtf(wq_v[o] + EPSF) * 0.25f;
            g_wq[idx] = alpha * wq_w[idx];
            if (i == 0) g_qb[o] = 0.25f * wq_b[o] - wq_m[o] * alpha;
        }
        for (int idx = tid; idx < 4096; idx += 256) {
            const int o = idx >> 6;
            const float alpha = dy_g[o] * rsqrtf(dy_v[o] + EPSF);
            g_dyw[idx] = alpha * dy_w[idx];
            if ((idx & 63) == 0) g_dyb[o] = dy_b[o] - dy_m[o] * alpha;
        }
    }

    const int sh = (p * 64) / 7;
    const int eh = ((p + 1) * 64 + 6) / 7;
    const float* xb = x + ((size_t)b * 64 + 32) * 4096;  // context half

    for (int idx = tid; idx < 32 * 7; idx += 256) {
        const int ci = idx / 7, q = idx % 7;
        const int sw = (q * 64) / 7;
        const int ew = ((q + 1) * 64 + 6) / 7;
        const float* base = xb + ci * 4096 + sh * 64 + sw;
        float acc = 0.f;
        for (int u = 0; u < eh - sh; u++) {
            float racc = 0.f;
            for (int v = 0; v < ew - sw; v++)
                racc += base[u * 64 + v];
            acc += racc;
        }
        kp[ci * 7 + q] = acc / (float)((eh - sh) * (ew - sw));
    }
    __syncthreads();

    for (int idx = tid; idx < 32 * 7; idx += 256) {
        const int o = idx / 7, q = idx % 7;
        const float alpha = wk_g[o] * rsqrtf(wk_v[o] + EPSF);
        const float beta  = wk_b[o] - wk_m[o] * alpha;
        float acc = 0.f;
        #pragma unroll
        for (int i = 0; i < 32; i++)
            acc += wk_w[o * 32 + i] * kp[i * 7 + q];
        const float val = alpha * acc + beta;
        const int g = o >> 3, c = o & 7;
        g_k[(((b * 4 + g) * 49) + p * 7 + q) * 8 + c] = val;
    }
}

// ---------------------------------------------------------------------------
// Kernel A: logits + exp.  3 CTAs/SM.
// thread: p = tid & 63 (pixel in 8x8 tile), g = tid >> 6 (head, warp-uniform)
// ---------------------------------------------------------------------------
constexpr int A_WQ = 0;       // 1024
constexpr int A_QB = 1024;    // 32
constexpr int A_KT = 1056;    // 1568
constexpr int A_PW = 2624;    // 74*52 = 3848 (zero padded)
constexpr int A_PB = 6472;    // 76
constexpr int A_R1 = 6548;    // 324
constexpr int A_R2 = 6872;    // 676
constexpr int A_TOT = 7548;   // 30192 bytes

__device__ __forceinline__ float dot49p(const float* __restrict__ wrow,
                                        const u64* __restrict__ sp)
{
    const ulonglong2* wp = (const ulonglong2*)wrow;
    u64 a0 = 0ull, a1 = 0ull, a2 = 0ull, a3 = 0ull;
    #pragma unroll
    for (int j = 0; j < 6; j++) {
        const ulonglong2 w0 = wp[2 * j];
        const ulonglong2 w1 = wp[2 * j + 1];
        a0 = ffma2(w0.x, sp[4 * j + 0], a0);
        a1 = ffma2(w0.y, sp[4 * j + 1], a1);
        a2 = ffma2(w1.x, sp[4 * j + 2], a2);
        a3 = ffma2(w1.y, sp[4 * j + 3], a3);
    }
    const u64 wt = *(const u64*)(wrow + 48);   // elems 48,49 (49 is zero)
    a0 = ffma2(wt, sp[24], a0);
    a0 = fadd2(a0, a1);
    a2 = fadd2(a2, a3);
    a0 = fadd2(a0, a2);
    const float2 f = unpack2(a0);
    return f.x + f.y;
}

__global__ void __launch_bounds__(256, 3)
a_kernel(const float* __restrict__ x,
         const float* __restrict__ proj_w, const float* __restrict__ proj_b,
         const float* __restrict__ rpb1, const float* __restrict__ rpb2)
{
    extern __shared__ float sm[];
    float* wqs = sm + A_WQ;
    float* qbs = sm + A_QB;
    float* kts = sm + A_KT;
    float* pws = sm + A_PW;
    float* pbs = sm + A_PB;
    float* r1s = sm + A_R1;
    float* r2s = sm + A_R2;

    const int tid = threadIdx.x;
    const int b  = blockIdx.z;
    const int h0 = blockIdx.y * 8;
    const int w0 = blockIdx.x * 8;
    const int flat = (b * 8 + blockIdx.y) * 8 + blockIdx.x;

    // stage
    for (int idx = tid; idx < 1024; idx += 256) wqs[idx] = g_wq[idx];
    if (tid < 32) qbs[tid] = g_qb[tid];
    for (int idx = tid; idx < 1568; idx += 256) kts[idx] = g_k[b * 1568 + idx];
    for (int idx = tid; idx < 74 * 52; idx += 256) {
        const int o = idx / 52, l = idx % 52;
        pws[idx] = (l < 49) ? proj_w[o * 49 + l] : 0.f;
    }
    if (tid < 74) pbs[tid] = proj_b[tid];
    for (int idx = tid; idx < 324; idx += 256) r1s[idx] = rpb1[idx];
    for (int idx = tid; idx < 676; idx += 256) r2s[idx] = rpb2[idx];
    __syncthreads();

    const int p = tid & 63;
    const int g = tid >> 6;
    const int ph = p >> 3, pwd = p & 7;
    const int h = h0 + ph, w = w0 + pwd;

    // ---- q (8 channels of this head) ----
    float q[8];
    {
        const float* xpix = x + (size_t)b * 64 * 4096 + h * 64 + w;
        u64 xp[16];
        #pragma unroll
        for (int i = 0; i < 16; i++)
            xp[i] = pack2(xpix[(size_t)(2 * i) * 4096],
                          xpix[(size_t)(2 * i + 1) * 4096]);
        #pragma unroll
        for (int c = 0; c < 8; c++) {
            const ulonglong2* wp = (const ulonglong2*)(wqs + (g * 8 + c) * 32);
            u64 a0 = 0ull, a1 = 0ull;
            #pragma unroll
            for (int j = 0; j < 4; j++) {
                const ulonglong2 w0 = wp[2 * j];
                const ulonglong2 w1 = wp[2 * j + 1];
                a0 = ffma2(w0.x, xp[4 * j + 0], a0);
                a1 = ffma2(w0.y, xp[4 * j + 1], a1);
                a0 = ffma2(w1.x, xp[4 * j + 2], a0);
                a1 = ffma2(w1.y, xp[4 * j + 3], a1);
            }
            const float2 f = unpack2(fadd2(a0, a1));
            q[c] = qbs[g * 8 + c] + f.x + f.y;
        }
    }

    // ---- s[l] = q . k[l], packed into pairs ----
    u64 sp[25];
    {
        u64 qp[4];
        #pragma unroll
        for (int j = 0; j < 4; j++) qp[j] = pack2(q[2 * j], q[2 * j + 1]);
        float sprev = 0.f;
        #pragma unroll
        for (int l = 0; l < 49; l++) {
            const float* krow = kts + (g * 49 + l) * 8;
            const ulonglong2 k0 = *(const ulonglong2*)(krow);
            const ulonglong2 k1 = *(const ulonglong2*)(krow + 4);
            u64 a0 = ffma2(qp[0], k0.x, ffma2(qp[1], k0.y, 0ull));
            u64 a1 = ffma2(qp[2], k1.x, ffma2(qp[3], k1.y, 0ull));
            const float2 f = unpack2(fadd2(a0, a1));
            const float sl = f.x + f.y;
            if (l & 1) sp[l >> 1] = pack2(sprev, sl);
            else sprev = sl;
        }
        sp[24] = pack2(sprev, 0.f);
    }

    const int ihr = 63 - h, iwr = 63 - w;
    float* ep = g_e + (size_t)flat * 74 * 256 + tid;

    // ---- part 1: 25 logits ----
    {
        const int ih1 = min(ihr, 2) + max(0, ihr - 61);
        const int iw1 = min(iwr, 2) + max(0, iwr - 61);
        const float* r1g = r1s + g * 81 + ih1 * 9 + iw1;
        float sum = 0.f;
        #pragma unroll
        for (int ki = 0; ki < 5; ki++) {
            #pragma unroll
            for (int kj = 0; kj < 5; kj++) {
                const int o = ki * 5 + kj;
                const float v = dot49p(pws + o * 52, sp) + pbs[o]
                              + r1g[ki * 9 + kj];
                const float e = __expf(v);
                sum += e;
                ep[o * 256] = e;
            }
        }
        g_inv[(size_t)flat * 512 + tid] = 1.0f / sum;
    }

    // ---- part 2: 49 logits ----
    {
        const int ih2 = min(ihr, 3) + max(0, ihr - 60);
        const int iw2 = min(iwr, 3) + max(0, iwr - 60);
        const float* r2g = r2s + g * 169 + ih2 * 13 + iw2;
        float sum = 0.f;
        #pragma unroll
        for (int ki = 0; ki < 7; ki++) {
            #pragma unroll
            for (int kj = 0; kj < 7; kj++) {
                const int o = 25 + ki * 7 + kj;
                const float v = dot49p(pws + o * 52, sp) + pbs[o]
                              + r2g[ki * 13 + kj];
                const float e = __expf(v);
                sum += e;
                ep[o * 256] = e;
            }
        }
        g_inv[(size_t)flat * 512 + 256 + tid] = 1.0f / sum;
    }
}

// ---------------------------------------------------------------------------
// Kernel B: neighborhood aggregation + dy conv.  3 CTAs/SM.
// ---------------------------------------------------------------------------
constexpr int B_XT1 = 0;       // 12*12*36 = 5184 (ch 0..31, halo 2); ob aliases
constexpr int B_XT2 = 5184;    // 14*14*36 = 7056 (ch 32..63, halo 3)
constexpr int B_DYW = 12240;   // 64*68 = 4352
constexpr int B_DYB = 16592;   // 64
constexpr int B_TOT = 16656;   // 66624 bytes

__global__ void __launch_bounds__(256, 3)
b_kernel(const float* __restrict__ x, float* __restrict__ out)
{
    extern __shared__ float sm[];
    float* xt1 = sm + B_XT1;
    float* xt2 = sm + B_XT2;
    float* dyws = sm + B_DYW;
    float* dybs = sm + B_DYB;
    float* ob = sm + B_XT1;   // alias after barrier

    const int tid = threadIdx.x;
    const int b  = blockIdx.z;
    const int h0 = blockIdx.y * 8;
    const int w0 = blockIdx.x * 8;
    const int flat = (b * 8 + blockIdx.y) * 8 + blockIdx.x;
    const float* xb = x + (size_t)b * 64 * 4096;

    for (int idx = tid; idx < 32 * 144; idx += 256) {
        const int t = idx % 12, s0 = (idx / 12) % 12, ch = idx / 144;
        const int gr = min(max(h0 - 2 + s0, 0), 63);
        const int gc = min(max(w0 - 2 + t, 0), 63);
        xt1[(s0 * 12 + t) * 36 + ch] = xb[ch * 4096 + gr * 64 + gc];
    }
    for (int idx = tid; idx < 32 * 196; idx += 256) {
        const int t = idx % 14, s0 = (idx / 14) % 14, ch = idx / 196;
        const int gr = min(max(h0 - 3 + s0, 0), 63);
        const int gc = min(max(w0 - 3 + t, 0), 63);
        xt2[(s0 * 14 + t) * 36 + ch] = xb[(32 + ch) * 4096 + gr * 64 + gc];
    }
    for (int idx = tid; idx < 4096; idx += 256)
        dyws[(idx >> 6) * 68 + (idx & 63)] = g_dyw[idx];
    if (tid < 64) dybs[tid] = g_dyb[tid];
    __syncthreads();

    const int p = tid & 63;
    const int g = tid >> 6;
    const int ph = p >> 3, pwd = p & 7;
    const int h = h0 + ph, w = w0 + pwd;
    const float* ep = g_e + (size_t)flat * 74 * 256 + tid;

    float o1[8], o2[8];

    // ---- part 1: 5x5 ----
    {
        const int si = min(max(h - 2, 0), 59) - (h0 - 2);
        const int sj = min(max(w - 2, 0), 59) - (w0 - 2);
        u64 c0 = 0ull, c1 = 0ull, c2 = 0ull, c3 = 0ull;
        #pragma unroll
        for (int ki = 0; ki < 5; ki++) {
            const float* row = xt1 + ((si + ki) * 12 + sj) * 36 + g * 8;
            #pragma unroll
            for (int kj = 0; kj < 5; kj++) {
                const float e = ep[(ki * 5 + kj) * 256];
                const u64 ee = pack2(e, e);
                const ulonglong2 v0 = *(const ulonglong2*)(row + kj * 36);
                const ulonglong2 v1 = *(const ulonglong2*)(row + kj * 36 + 4);
                c0 = ffma2(ee, v0.x, c0);
                c1 = ffma2(ee, v0.y, c1);
                c2 = ffma2(ee, v1.x, c2);
                c3 = ffma2(ee, v1.y, c3);
            }
        }
        const float inv = g_inv[(size_t)flat * 512 + tid];
        float2 f;
        f = unpack2(c0); o1[0] = f.x * inv; o1[1] = f.y * inv;
        f = unpack2(c1); o1[2] = f.x * inv; o1[3] = f.y * inv;
        f = unpack2(c2); o1[4] = f.x * inv; o1[5] = f.y * inv;
        f = unpack2(c3); o1[6] = f.x * inv; o1[7] = f.y * inv;
    }

    // ---- part 2: 7x7 ----
    {
        const int si = min(max(h - 3, 0), 57) - (h0 - 3);
        const int sj = min(max(w - 3, 0), 57) - (w0 - 3);
        u64 c0 = 0ull, c1 = 0ull, c2 = 0ull, c3 = 0ull;
        #pragma unroll
        for (int ki = 0; ki < 7; ki++) {
            const float* row = xt2 + ((si + ki) * 14 + sj) * 36 + g * 8;
            #pragma unroll
            for (int kj = 0; kj < 7; kj++) {
                const float e = ep[(25 + ki * 7 + kj) * 256];
                const u64 ee = pack2(e, e);
                const ulonglong2 v0 = *(const ulonglong2*)(row + kj * 36);
                const ulonglong2 v1 = *(const ulonglong2*)(row + kj * 36 + 4);
                c0 = ffma2(ee, v0.x, c0);
                c1 = ffma2(ee, v0.y, c1);
                c2 = ffma2(ee, v1.x, c2);
                c3 = ffma2(ee, v1.y, c3);
            }
        }
        const float inv = g_inv[(size_t)flat * 512 + 256 + tid];
        float2 f;
        f = unpack2(c0); o2[0] = f.x * inv; o2[1] = f.y * inv;
        f = unpack2(c1); o2[2] = f.x * inv; o2[3] = f.y * inv;
        f = unpack2(c2); o2[4] = f.x * inv; o2[5] = f.y * inv;
        f = unpack2(c3); o2[6] = f.x * inv; o2[7] = f.y * inv;
    }

    __syncthreads();   // xt reads done -> reuse as ob
    {
        float* obp = ob + p * 68 + g * 8;
        *(float4*)(obp)          = make_float4(o1[0], o1[1], o1[2], o1[3]);
        *(float4*)(obp + 4)      = make_float4(o1[4], o1[5], o1[6], o1[7]);
        *(float4*)(obp + 32)     = make_float4(o2[0], o2[1], o2[2], o2[3]);
        *(float4*)(obp + 32 + 4) = make_float4(o2[4], o2[5], o2[6], o2[7]);
    }
    __syncthreads();

    // ---- dy conv: thread handles output channels r, r+4, ..., r+60 ----
    {
        const int r = g;
        u64 acc[16];
        #pragma unroll
        for (int j = 0; j < 16; j++) acc[j] = 0ull;
        const float* obr = ob + p * 68;
        #pragma unroll
        for (int c4 = 0; c4 < 16; c4++) {
            const ulonglong2 xv = *(const ulonglong2*)(obr + c4 * 4);
            #pragma unroll
            for (int j = 0; j < 16; j++) {
                const ulonglong2 wv =
                    *(const ulonglong2*)(dyws + (r + 4 * j) * 68 + c4 * 4);
                acc[j] = ffma2(xv.x, wv.x, acc[j]);
                acc[j] = ffma2(xv.y, wv.y, acc[j]);
            }
        }
        float* outp = out + (size_t)b * 64 * 4096 + h * 64 + w;
        #pragma unroll
        for (int j = 0; j < 16; j++) {
            const float2 f = unpack2(acc[j]);
            outp[(size_t)(r + 4 * j) * 4096] = f.x + f.y + dybs[r + 4 * j];
        }
    }
}

// ---------------------------------------------------------------------------
extern "C" void kernel_launch(void* const* d_in, const int* in_sizes, int n_in,
                              void* d_out, int out_size)
{
    const float* x      = (const float*)d_in[0];
    const float* wq_w   = (const float*)d_in[1];
    const float* wq_g   = (const float*)d_in[2];
    const float* wq_b   = (const float*)d_in[3];
    const float* wq_m   = (const float*)d_in[4];
    const float* wq_v   = (const float*)d_in[5];
    const float* wk_w   = (const float*)d_in[6];
    const float* wk_g   = (const float*)d_in[7];
    const float* wk_b   = (const float*)d_in[8];
    const float* wk_m   = (const float*)d_in[9];
    const float* wk_v   = (const float*)d_in[10];
    const float* proj_w = (const float*)d_in[11];
    const float* proj_b = (const float*)d_in[12];
    const float* rpb1   = (const float*)d_in[13];
    const float* rpb2   = (const float*)d_in[14];
    const float* dy_w   = (const float*)d_in[15];
    const float* dy_g   = (const float*)d_in[16];
    const float* dy_b   = (const float*)d_in[17];
    const float* dy_m   = (const float*)d_in[18];
    const float* dy_v   = (const float*)d_in[19];
    float* out = (float*)d_out;

    cudaFuncSetAttribute(a_kernel, cudaFuncAttributeMaxDynamicSharedMemorySize,
                         A_TOT * (int)sizeof(float));
    cudaFuncSetAttribute(b_kernel, cudaFuncAttributeMaxDynamicSharedMemorySize,
                         B_TOT * (int)sizeof(float));

    dim3 gk(7, 8);
    k_kernel<<<gk, 256>>>(x, wk_w, wk_g, wk_b, wk_m, wk_v,
                          wq_w, wq_g, wq_b, wq_m, wq_v,
                          dy_w, dy_g, dy_b, dy_m, dy_v);

    dim3 gm(8, 8, 8);
    a_kernel<<<gm, 256, A_TOT * (int)sizeof(float)>>>(
        x, proj_w, proj_b, rpb1, rpb2);
    b_kernel<<<gm, 256, B_TOT * (int)sizeof(float)>>>(x, out);
}

// round 4
// speedup vs baseline: 1.6046x; 1.0056x over previous
#include <cuda_runtime.h>

#define EPSF 1e-5f

typedef unsigned long long u64;

__device__ __forceinline__ u64 ffma2(u64 a, u64 b, u64 c) {
    u64 d;
    asm("fma.rn.f32x2 %0, %1, %2, %3;" : "=l"(d) : "l"(a), "l"(b), "l"(c));
    return d;
}
__device__ __forceinline__ u64 fadd2(u64 a, u64 b) {
    u64 d;
    asm("add.rn.f32x2 %0, %1, %2;" : "=l"(d) : "l"(a), "l"(b));
    return d;
}
__device__ __forceinline__ u64 pack2(float lo, float hi) {
    u64 d;
    asm("mov.b64 %0, {%1, %2};" : "=l"(d) : "f"(lo), "f"(hi));
    return d;
}
__device__ __forceinline__ float2 unpack2(u64 a) {
    float2 r;
    asm("mov.b64 {%0, %1}, %2;" : "=f"(r.x), "=f"(r.y) : "l"(a));
    return r;
}

// ---------------------------------------------------------------------------
// device scratch (static allocation only)
// ---------------------------------------------------------------------------
__device__ float g_kp[8 * 32 * 49];       // pooled context [b][ci][pos]
__device__ float g_k[8 * 4 * 49 * 8];     // pooled keys [b][g][l][c]
__device__ float g_wq[32 * 32];           // BN+SCALE folded q weights
__device__ float g_qb[32];
__device__ float g_dyw[64 * 64];          // BN folded dy weights
__device__ float g_dyb[64];
__device__ float g_e[512 * 74 * 256];     // unnormalized exp, [blk][o][tid]
__device__ float g_inv[512 * 2 * 256];    // 1/sum, [blk][part][tid]

// ---------------------------------------------------------------------------
// Kernel P: adaptive pool 64x64 -> 7x7, one block per (batch, channel)
// ---------------------------------------------------------------------------
__global__ void __launch_bounds__(256)
pool_kernel(const float* __restrict__ x)
{
    __shared__ float ch[4096];
    __shared__ float rp[64 * 7];

    const int b  = blockIdx.x >> 5;
    const int ci = blockIdx.x & 31;
    const int tid = threadIdx.x;

    const float4* src = (const float4*)(x + ((size_t)b * 64 + 32 + ci) * 4096);
    float4* dst = (float4*)ch;
    #pragma unroll
    for (int j = 0; j < 4; j++)
        dst[tid + 256 * j] = src[tid + 256 * j];
    __syncthreads();

    // row pooling: rp[r][q] = sum of ch[r][sw..ew)
    for (int idx = tid; idx < 64 * 7; idx += 256) {
        const int r = idx / 7, q = idx % 7;
        const int sw = (q * 64) / 7;
        const int ew = ((q + 1) * 64 + 6) / 7;
        float acc = 0.f;
        for (int v = sw; v < ew; v++) acc += ch[r * 64 + v];
        rp[idx] = acc;
    }
    __syncthreads();

    // column pooling + normalize
    if (tid < 49) {
        const int p = tid / 7, q = tid % 7;
        const int sh = (p * 64) / 7;
        const int eh = ((p + 1) * 64 + 6) / 7;
        const int sw = (q * 64) / 7;
        const int ew = ((q + 1) * 64 + 6) / 7;
        float acc = 0.f;
        for (int r = sh; r < eh; r++) acc += rp[r * 7 + q];
        g_kp[((size_t)b * 32 + ci) * 49 + tid] =
            acc / (float)((eh - sh) * (ew - sw));
    }
}

// ---------------------------------------------------------------------------
// Kernel K: 32x32 conv + BN on pooled tile; block 0 also folds wq/dy weights
// ---------------------------------------------------------------------------
__global__ void __launch_bounds__(256)
kconv_kernel(const float* __restrict__ wk_w,
             const float* __restrict__ wk_g,
             const float* __restrict__ wk_b,
             const float* __restrict__ wk_m,
             const float* __restrict__ wk_v,
             const float* __restrict__ wq_w,
             const float* __restrict__ wq_g,
             const float* __restrict__ wq_b,
             const float* __restrict__ wq_m,
             const float* __restrict__ wq_v,
             const float* __restrict__ dy_w,
             const float* __restrict__ dy_g,
             const float* __restrict__ dy_b,
             const float* __restrict__ dy_m,
             const float* __restrict__ dy_v)
{
    __shared__ float kps[32 * 49];
    const int b = blockIdx.x;
    const int tid = threadIdx.x;

    if (b == 0) {
        for (int idx = tid; idx < 1024; idx += 256) {
            const int o = idx >> 5, i = idx & 31;
            const float alpha = wq_g[o] * rsqrtf(wq_v[o] + EPSF) * 0.25f;
            g_wq[idx] = alpha * wq_w[idx];
            if (i == 0) g_qb[o] = 0.25f * wq_b[o] - wq_m[o] * alpha;
        }
        for (int idx = tid; idx < 4096; idx += 256) {
            const int o = idx >> 6;
            const float alpha = dy_g[o] * rsqrtf(dy_v[o] + EPSF);
            g_dyw[idx] = alpha * dy_w[idx];
            if ((idx & 63) == 0) g_dyb[o] = dy_b[o] - dy_m[o] * alpha;
        }
    }

    for (int idx = tid; idx < 1568; idx += 256)
        kps[idx] = g_kp[(size_t)b * 1568 + idx];
    __syncthreads();

    for (int idx = tid; idx < 1568; idx += 256) {
        const int o = idx / 49, pos = idx % 49;
        const float alpha = wk_g[o] * rsqrtf(wk_v[o] + EPSF);
        const float beta  = wk_b[o] - wk_m[o] * alpha;
        float acc = 0.f;
        #pragma unroll
        for (int i = 0; i < 32; i++)
            acc += wk_w[o * 32 + i] * kps[i * 49 + pos];
        const float val = alpha * acc + beta;
        const int g = o >> 3, c = o & 7;
        g_k[(((size_t)b * 4 + g) * 49 + pos) * 8 + c] = val;
    }
}

// ---------------------------------------------------------------------------
// Kernel A: logits + exp.  3 CTAs/SM.
// ---------------------------------------------------------------------------
constexpr int A_WQ = 0;       // 1024
constexpr int A_QB = 1024;    // 32
constexpr int A_KT = 1056;    // 1568
constexpr int A_PW = 2624;    // 74*52 = 3848 (zero padded)
constexpr int A_PB = 6472;    // 76
constexpr int A_R1 = 6548;    // 324
constexpr int A_R2 = 6872;    // 676
constexpr int A_TOT = 7548;   // 30192 bytes

__device__ __forceinline__ float dot49p(const float* __restrict__ wrow,
                                        const u64* __restrict__ sp)
{
    const ulonglong2* wp = (const ulonglong2*)wrow;
    u64 a0 = 0ull, a1 = 0ull, a2 = 0ull, a3 = 0ull;
    #pragma unroll
    for (int j = 0; j < 6; j++) {
        const ulonglong2 w0 = wp[2 * j];
        const ulonglong2 w1 = wp[2 * j + 1];
        a0 = ffma2(w0.x, sp[4 * j + 0], a0);
        a1 = ffma2(w0.y, sp[4 * j + 1], a1);
        a2 = ffma2(w1.x, sp[4 * j + 2], a2);
        a3 = ffma2(w1.y, sp[4 * j + 3], a3);
    }
    const u64 wt = *(const u64*)(wrow + 48);   // elems 48,49 (49 is zero)
    a0 = ffma2(wt, sp[24], a0);
    a0 = fadd2(a0, a1);
    a2 = fadd2(a2, a3);
    a0 = fadd2(a0, a2);
    const float2 f = unpack2(a0);
    return f.x + f.y;
}

__global__ void __launch_bounds__(256, 3)
a_kernel(const float* __restrict__ x,
         const float* __restrict__ proj_w, const float* __restrict__ proj_b,
         const float* __restrict__ rpb1, const float* __restrict__ rpb2)
{
    extern __shared__ float sm[];
    float* wqs = sm + A_WQ;
    float* qbs = sm + A_QB;
    float* kts = sm + A_KT;
    float* pws = sm + A_PW;
    float* pbs = sm + A_PB;
    float* r1s = sm + A_R1;
    float* r2s = sm + A_R2;

    const int tid = threadIdx.x;
    const int b  = blockIdx.z;
    const int h0 = blockIdx.y * 8;
    const int w0 = blockIdx.x * 8;
    const int flat = (b * 8 + blockIdx.y) * 8 + blockIdx.x;

    for (int idx = tid; idx < 1024; idx += 256) wqs[idx] = g_wq[idx];
    if (tid < 32) qbs[tid] = g_qb[tid];
    for (int idx = tid; idx < 1568; idx += 256) kts[idx] = g_k[b * 1568 + idx];
    for (int idx = tid; idx < 74 * 52; idx += 256) {
        const int o = idx / 52, l = idx % 52;
        pws[idx] = (l < 49) ? proj_w[o * 49 + l] : 0.f;
    }
    if (tid < 74) pbs[tid] = proj_b[tid];
    for (int idx = tid; idx < 324; idx += 256) r1s[idx] = rpb1[idx];
    for (int idx = tid; idx < 676; idx += 256) r2s[idx] = rpb2[idx];
    __syncthreads();

    const int p = tid & 63;
    const int g = tid >> 6;
    const int ph = p >> 3, pwd = p & 7;
    const int h = h0 + ph, w = w0 + pwd;

    // ---- q (8 channels of this head) ----
    float q[8];
    {
        const float* xpix = x + (size_t)b * 64 * 4096 + h * 64 + w;
        u64 xp[16];
        #pragma unroll
        for (int i = 0; i < 16; i++)
            xp[i] = pack2(xpix[(size_t)(2 * i) * 4096],
                          xpix[(size_t)(2 * i + 1) * 4096]);
        #pragma unroll
        for (int c = 0; c < 8; c++) {
            const ulonglong2* wp = (const ulonglong2*)(wqs + (g * 8 + c) * 32);
            u64 a0 = 0ull, a1 = 0ull;
            #pragma unroll
            for (int j = 0; j < 4; j++) {
                const ulonglong2 w0 = wp[2 * j];
                const ulonglong2 w1 = wp[2 * j + 1];
                a0 = ffma2(w0.x, xp[4 * j + 0], a0);
                a1 = ffma2(w0.y, xp[4 * j + 1], a1);
                a0 = ffma2(w1.x, xp[4 * j + 2], a0);
                a1 = ffma2(w1.y, xp[4 * j + 3], a1);
            }
            const float2 f = unpack2(fadd2(a0, a1));
            q[c] = qbs[g * 8 + c] + f.x + f.y;
        }
    }

    // ---- s[l] = q . k[l], packed into pairs ----
    u64 sp[25];
    {
        u64 qp[4];
        #pragma unroll
        for (int j = 0; j < 4; j++) qp[j] = pack2(q[2 * j], q[2 * j + 1]);
        float sprev = 0.f;
        #pragma unroll
        for (int l = 0; l < 49; l++) {
            const float* krow = kts + (g * 49 + l) * 8;
            const ulonglong2 k0 = *(const ulonglong2*)(krow);
            const ulonglong2 k1 = *(const ulonglong2*)(krow + 4);
            u64 a0 = ffma2(qp[0], k0.x, ffma2(qp[1], k0.y, 0ull));
            u64 a1 = ffma2(qp[2], k1.x, ffma2(qp[3], k1.y, 0ull));
            const float2 f = unpack2(fadd2(a0, a1));
            const float sl = f.x + f.y;
            if (l & 1) sp[l >> 1] = pack2(sprev, sl);
            else sprev = sl;
        }
        sp[24] = pack2(sprev, 0.f);
    }

    const int ihr = 63 - h, iwr = 63 - w;
    float* ep = g_e + (size_t)flat * 74 * 256 + tid;

    // ---- part 1: 25 logits ----
    {
        const int ih1 = min(ihr, 2) + max(0, ihr - 61);
        const int iw1 = min(iwr, 2) + max(0, iwr - 61);
        const float* r1g = r1s + g * 81 + ih1 * 9 + iw1;
        float sum = 0.f;
        #pragma unroll
        for (int ki = 0; ki < 5; ki++) {
            #pragma unroll
            for (int kj = 0; kj < 5; kj++) {
                const int o = ki * 5 + kj;
                const float v = dot49p(pws + o * 52, sp) + pbs[o]
                              + r1g[ki * 9 + kj];
                const float e = __expf(v);
                sum += e;
                ep[o * 256] = e;
            }
        }
        g_inv[(size_t)flat * 512 + tid] = 1.0f / sum;
    }

    // ---- part 2: 49 logits ----
    {
        const int ih2 = min(ihr, 3) + max(0, ihr - 60);
        const int iw2 = min(iwr, 3) + max(0, iwr - 60);
        const float* r2g = r2s + g * 169 + ih2 * 13 + iw2;
        float sum = 0.f;
        #pragma unroll
        for (int ki = 0; ki < 7; ki++) {
            #pragma unroll
            for (int kj = 0; kj < 7; kj++) {
                const int o = 25 + ki * 7 + kj;
                const float v = dot49p(pws + o * 52, sp) + pbs[o]
                              + r2g[ki * 13 + kj];
                const float e = __expf(v);
                sum += e;
                ep[o * 256] = e;
            }
        }
        g_inv[(size_t)flat * 512 + 256 + tid] = 1.0f / sum;
    }
}

// ---------------------------------------------------------------------------
// Kernel B: neighborhood aggregation + dy conv.  3 CTAs/SM.
// ---------------------------------------------------------------------------
constexpr int B_XT1 = 0;       // 12*12*36 = 5184 (ch 0..31, halo 2); ob aliases
constexpr int B_XT2 = 5184;    // 14*14*36 = 7056 (ch 32..63, halo 3)
constexpr int B_DYW = 12240;   // 64*68 = 4352
constexpr int B_DYB = 16592;   // 64
constexpr int B_TOT = 16656;   // 66624 bytes

__global__ void __launch_bounds__(256, 3)
b_kernel(const float* __restrict__ x, float* __restrict__ out)
{
    extern __shared__ float sm[];
    float* xt1 = sm + B_XT1;
    float* xt2 = sm + B_XT2;
    float* dyws = sm + B_DYW;
    float* dybs = sm + B_DYB;
    float* ob = sm + B_XT1;   // alias after barrier

    const int tid = threadIdx.x;
    const int b  = blockIdx.z;
    const int h0 = blockIdx.y * 8;
    const int w0 = blockIdx.x * 8;
    const int flat = (b * 8 + blockIdx.y) * 8 + blockIdx.x;
    const float* xb = x + (size_t)b * 64 * 4096;

    for (int idx = tid; idx < 32 * 144; idx += 256) {
        const int t = idx % 12, s0 = (idx / 12) % 12, ch = idx / 144;
        const int gr = min(max(h0 - 2 + s0, 0), 63);
        const int gc = min(max(w0 - 2 + t, 0), 63);
        xt1[(s0 * 12 + t) * 36 + ch] = xb[ch * 4096 + gr * 64 + gc];
    }
    for (int idx = tid; idx < 32 * 196; idx += 256) {
        const int t = idx % 14, s0 = (idx / 14) % 14, ch = idx / 196;
        const int gr = min(max(h0 - 3 + s0, 0), 63);
        const int gc = min(max(w0 - 3 + t, 0), 63);
        xt2[(s0 * 14 + t) * 36 + ch] = xb[(32 + ch) * 4096 + gr * 64 + gc];
    }
    for (int idx = tid; idx < 4096; idx += 256)
        dyws[(idx >> 6) * 68 + (idx & 63)] = g_dyw[idx];
    if (tid < 64) dybs[tid] = g_dyb[tid];
    __syncthreads();

    const int p = tid & 63;
    const int g = tid >> 6;
    const int ph = p >> 3, pwd = p & 7;
    const int h = h0 + ph, w = w0 + pwd;
    const float* ep = g_e + (size_t)flat * 74 * 256 + tid;

    float o1[8], o2[8];

    // ---- part 1: 5x5 ----
    {
        const int si = min(max(h - 2, 0), 59) - (h0 - 2);
        const int sj = min(max(w - 2, 0), 59) - (w0 - 2);
        u64 c0 = 0ull, c1 = 0ull, c2 = 0ull, c3 = 0ull;
        #pragma unroll
        for (int ki = 0; ki < 5; ki++) {
            const float* row = xt1 + ((si + ki) * 12 + sj) * 36 + g * 8;
            #pragma unroll
            for (int kj = 0; kj < 5; kj++) {
                const float e = ep[(ki * 5 + kj) * 256];
                const u64 ee = pack2(e, e);
                const ulonglong2 v0 = *(const ulonglong2*)(row + kj * 36);
                const ulonglong2 v1 = *(const ulonglong2*)(row + kj * 36 + 4);
                c0 = ffma2(ee, v0.x, c0);
                c1 = ffma2(ee, v0.y, c1);
                c2 = ffma2(ee, v1.x, c2);
                c3 = ffma2(ee, v1.y, c3);
            }
        }
        const float inv = g_inv[(size_t)flat * 512 + tid];
        float2 f;
        f = unpack2(c0); o1[0] = f.x * inv; o1[1] = f.y * inv;
        f = unpack2(c1); o1[2] = f.x * inv; o1[3] = f.y * inv;
        f = unpack2(c2); o1[4] = f.x * inv; o1[5] = f.y * inv;
        f = unpack2(c3); o1[6] = f.x * inv; o1[7] = f.y * inv;
    }

    // ---- part 2: 7x7 ----
    {
        const int si = min(max(h - 3, 0), 57) - (h0 - 3);
        const int sj = min(max(w - 3, 0), 57) - (w0 - 3);
        u64 c0 = 0ull, c1 = 0ull, c2 = 0ull, c3 = 0ull;
        #pragma unroll
        for (int ki = 0; ki < 7; ki++) {
            const float* row = xt2 + ((si + ki) * 14 + sj) * 36 + g * 8;
            #pragma unroll
            for (int kj = 0; kj < 7; kj++) {
                const float e = ep[(25 + ki * 7 + kj) * 256];
                const u64 ee = pack2(e, e);
                const ulonglong2 v0 = *(const ulonglong2*)(row + kj * 36);
                const ulonglong2 v1 = *(const ulonglong2*)(row + kj * 36 + 4);
                c0 = ffma2(ee, v0.x, c0);
                c1 = ffma2(ee, v0.y, c1);
                c2 = ffma2(ee, v1.x, c2);
                c3 = ffma2(ee, v1.y, c3);
            }
        }
        const float inv = g_inv[(size_t)flat * 512 + 256 + tid];
        float2 f;
        f = unpack2(c0); o2[0] = f.x * inv; o2[1] = f.y * inv;
        f = unpack2(c1); o2[2] = f.x * inv; o2[3] = f.y * inv;
        f = unpack2(c2); o2[4] = f.x * inv; o2[5] = f.y * inv;
        f = unpack2(c3); o2[6] = f.x * inv; o2[7] = f.y * inv;
    }

    __syncthreads();   // xt reads done -> reuse as ob
    {
        float* obp = ob + p * 68 + g * 8;
        *(float4*)(obp)          = make_float4(o1[0], o1[1], o1[2], o1[3]);
        *(float4*)(obp + 4)      = make_float4(o1[4], o1[5], o1[6], o1[7]);
        *(float4*)(obp + 32)     = make_float4(o2[0], o2[1], o2[2], o2[3]);
        *(float4*)(obp + 32 + 4) = make_float4(o2[4], o2[5], o2[6], o2[7]);
    }
    __syncthreads();

    // ---- dy conv ----
    {
        const int r = g;
        u64 acc[16];
        #pragma unroll
        for (int j = 0; j < 16; j++) acc[j] = 0ull;
        const float* obr = ob + p * 68;
        #pragma unroll
        for (int c4 = 0; c4 < 16; c4++) {
            const ulonglong2 xv = *(const ulonglong2*)(obr + c4 * 4);
            #pragma unroll
            for (int j = 0; j < 16; j++) {
                const ulonglong2 wv =
                    *(const ulonglong2*)(dyws + (r + 4 * j) * 68 + c4 * 4);
                acc[j] = ffma2(xv.x, wv.x, acc[j]);
                acc[j] = ffma2(xv.y, wv.y, acc[j]);
            }
        }
        float* outp = out + (size_t)b * 64 * 4096 + h * 64 + w;
        #pragma unroll
        for (int j = 0; j < 16; j++) {
            const float2 f = unpack2(acc[j]);
            outp[(size_t)(r + 4 * j) * 4096] = f.x + f.y + dybs[r + 4 * j];
        }
    }
}

// ---------------------------------------------------------------------------
extern "C" void kernel_launch(void* const* d_in, const int* in_sizes, int n_in,
                              void* d_out, int out_size)
{
    const float* x      = (const float*)d_in[0];
    const float* wq_w   = (const float*)d_in[1];
    const float* wq_g   = (const float*)d_in[2];
    const float* wq_b   = (const float*)d_in[3];
    const float* wq_m   = (const float*)d_in[4];
    const float* wq_v   = (const float*)d_in[5];
    const float* wk_w   = (const float*)d_in[6];
    const float* wk_g   = (const float*)d_in[7];
    const float* wk_b   = (const float*)d_in[8];
    const float* wk_m   = (const float*)d_in[9];
    const float* wk_v   = (const float*)d_in[10];
    const float* proj_w = (const float*)d_in[11];
    const float* proj_b = (const float*)d_in[12];
    const float* rpb1   = (const float*)d_in[13];
    const float* rpb2   = (const float*)d_in[14];
    const float* dy_w   = (const float*)d_in[15];
    const float* dy_g   = (const float*)d_in[16];
    const float* dy_b   = (const float*)d_in[17];
    const float* dy_m   = (const float*)d_in[18];
    const float* dy_v   = (const float*)d_in[19];
    float* out = (float*)d_out;

    cudaFuncSetAttribute(a_kernel, cudaFuncAttributeMaxDynamicSharedMemorySize,
                         A_TOT * (int)sizeof(float));
    cudaFuncSetAttribute(b_kernel, cudaFuncAttributeMaxDynamicSharedMemorySize,
                         B_TOT * (int)sizeof(float));

    pool_kernel<<<256, 256>>>(x);
    kconv_kernel<<<8, 256>>>(wk_w, wk_g, wk_b, wk_m, wk_v,
                             wq_w, wq_g, wq_b, wq_m, wq_v,
                             dy_w, dy_g, dy_b, dy_m, dy_v);

    dim3 gm(8, 8, 8);
    a_kernel<<<gm, 256, A_TOT * (int)sizeof(float)>>>(
        x, proj_w, proj_b, rpb1, rpb2);
    b_kernel<<<gm, 256, B_TOT * (int)sizeof(float)>>>(x, out);
}

// round 5
// speedup vs baseline: 2.0363x; 1.2690x over previous
#include <cuda_runtime.h>

#define EPSF 1e-5f

typedef unsigned long long u64;

__device__ __forceinline__ u64 ffma2(u64 a, u64 b, u64 c) {
    u64 d;
    asm("fma.rn.f32x2 %0, %1, %2, %3;" : "=l"(d) : "l"(a), "l"(b), "l"(c));
    return d;
}
__device__ __forceinline__ u64 fadd2(u64 a, u64 b) {
    u64 d;
    asm("add.rn.f32x2 %0, %1, %2;" : "=l"(d) : "l"(a), "l"(b));
    return d;
}
__device__ __forceinline__ u64 pack2(float lo, float hi) {
    u64 d;
    asm("mov.b64 %0, {%1, %2};" : "=l"(d) : "f"(lo), "f"(hi));
    return d;
}
__device__ __forceinline__ float2 unpack2(u64 a) {
    float2 r;
    asm("mov.b64 {%0, %1}, %2;" : "=f"(r.x), "=f"(r.y) : "l"(a));
    return r;
}

// ---------------------------------------------------------------------------
// device scratch (static allocation only)
// ---------------------------------------------------------------------------
__device__ float g_kp[8 * 32 * 49];         // pooled context [b][ci][pos]
__device__ float g_k[8 * 4 * 49 * 8];       // pooled keys [b][g][l][c]
__device__ float g_kproj[8 * 4 * 74 * 8];   // proj-folded keys [b][g][o][c]
__device__ float g_wq[32 * 32];             // BN+SCALE folded q weights
__device__ float g_qb[32];
__device__ float g_dyw[64 * 64];            // BN folded dy weights
__device__ float g_dyb[64];
// e rows: [blk][row 0..11][slot 0..7][tid], row = window row (5 for p1, 7 p2)
__device__ float g_e[512 * 12 * 2048];
__device__ float g_inv[512 * 2 * 256];      // 1/sum, [blk][part][tid]
__device__ float g_ob[8 * 4096 * 64];       // aggregated values [b][hw][ch]

// ---------------------------------------------------------------------------
// Kernel P: adaptive pool 64x64 -> 7x7, one block per (batch, channel)
// ---------------------------------------------------------------------------
__global__ void __launch_bounds__(256)
pool_kernel(const float* __restrict__ x)
{
    __shared__ float ch[4096];
    __shared__ float rp[64 * 7];

    const int b  = blockIdx.x >> 5;
    const int ci = blockIdx.x & 31;
    const int tid = threadIdx.x;

    const float4* src = (const float4*)(x + ((size_t)b * 64 + 32 + ci) * 4096);
    float4* dst = (float4*)ch;
    #pragma unroll
    for (int j = 0; j < 4; j++)
        dst[tid + 256 * j] = src[tid + 256 * j];
    __syncthreads();

    for (int idx = tid; idx < 64 * 7; idx += 256) {
        const int r = idx / 7, q = idx % 7;
        const int sw = (q * 64) / 7;
        const int ew = ((q + 1) * 64 + 6) / 7;
        float acc = 0.f;
        for (int v = sw; v < ew; v++) acc += ch[r * 64 + v];
        rp[idx] = acc;
    }
    __syncthreads();

    if (tid < 49) {
        const int p = tid / 7, q = tid % 7;
        const int sh = (p * 64) / 7;
        const int eh = ((p + 1) * 64 + 6) / 7;
        const int sw = (q * 64) / 7;
        const int ew = ((q + 1) * 64 + 6) / 7;
        float acc = 0.f;
        for (int r = sh; r < eh; r++) acc += rp[r * 7 + q];
        g_kp[((size_t)b * 32 + ci) * 49 + tid] =
            acc / (float)((eh - sh) * (ew - sw));
    }
}

// ---------------------------------------------------------------------------
// Kernel K: 32x32 conv + BN on pooled tile; block 0 also folds wq/dy weights
// ---------------------------------------------------------------------------
__global__ void __launch_bounds__(256)
kconv_kernel(const float* __restrict__ wk_w,
             const float* __restrict__ wk_g,
             const float* __restrict__ wk_b,
             const float* __restrict__ wk_m,
             const float* __restrict__ wk_v,
             const float* __restrict__ wq_w,
             const float* __restrict__ wq_g,
             const float* __restrict__ wq_b,
             const float* __restrict__ wq_m,
             const float* __restrict__ wq_v,
             const float* __restrict__ dy_w,
             const float* __restrict__ dy_g,
             const float* __restrict__ dy_b,
             const float* __restrict__ dy_m,
             const float* __restrict__ dy_v)
{
    __shared__ float kps[32 * 49];
    const int b = blockIdx.x;
    const int tid = threadIdx.x;

    if (b == 0) {
        for (int idx = tid; idx < 1024; idx += 256) {
            const int o = idx >> 5, i = idx & 31;
            const float alpha = wq_g[o] * rsqrtf(wq_v[o] + EPSF) * 0.25f;
            g_wq[idx] = alpha * wq_w[idx];
            if (i == 0) g_qb[o] = 0.25f * wq_b[o] - wq_m[o] * alpha;
        }
        for (int idx = tid; idx < 4096; idx += 256) {
            const int o = idx >> 6;
            const float alpha = dy_g[o] * rsqrtf(dy_v[o] + EPSF);
            g_dyw[idx] = alpha * dy_w[idx];
            if ((idx & 63) == 0) g_dyb[o] = dy_b[o] - dy_m[o] * alpha;
        }
    }

    for (int idx = tid; idx < 1568; idx += 256)
        kps[idx] = g_kp[(size_t)b * 1568 + idx];
    __syncthreads();

    for (int idx = tid; idx < 1568; idx += 256) {
        const int o = idx / 49, pos = idx % 49;
        const float alpha = wk_g[o] * rsqrtf(wk_v[o] + EPSF);
        const float beta  = wk_b[o] - wk_m[o] * alpha;
        float acc = 0.f;
        #pragma unroll
        for (int i = 0; i < 32; i++)
            acc += wk_w[o * 32 + i] * kps[i * 49 + pos];
        const float val = alpha * acc + beta;
        const int g = o >> 3, c = o & 7;
        g_k[(((size_t)b * 4 + g) * 49 + pos) * 8 + c] = val;
    }
}

// ---------------------------------------------------------------------------
// Kernel KP: kproj[b,g,o,c] = sum_l proj_w[o,l] * k[b,g,l,c]
// grid (4 g, 8 b)
// ---------------------------------------------------------------------------
__global__ void __launch_bounds__(256)
kproj_kernel(const float* __restrict__ proj_w)
{
    __shared__ float pws[74 * 49];
    __shared__ float ktg[49 * 8];
    const int g = blockIdx.x;
    const int b = blockIdx.y;
    const int tid = threadIdx.x;

    for (int idx = tid; idx < 74 * 49; idx += 256) pws[idx] = proj_w[idx];
    for (int idx = tid; idx < 392; idx += 256)
        ktg[idx] = g_k[((size_t)(b * 4 + g) * 49) * 8 + idx];
    __syncthreads();

    for (int idx = tid; idx < 74 * 8; idx += 256) {
        const int o = idx >> 3, c = idx & 7;
        float acc = 0.f;
        #pragma unroll
        for (int l = 0; l < 49; l++)
            acc += pws[o * 49 + l] * ktg[l * 8 + c];
        g_kproj[((size_t)(b * 4 + g) * 74 + o) * 8 + c] = acc;
    }
}

// ---------------------------------------------------------------------------
// Kernel A: logits via q . kproj, exp, store grouped e.  4 CTAs/SM.
// ---------------------------------------------------------------------------
__global__ void __launch_bounds__(256, 4)
a_kernel(const float* __restrict__ x,
         const float* __restrict__ proj_b,
         const float* __restrict__ rpb1, const float* __restrict__ rpb2)
{
    __shared__ float wqs[1024];
    __shared__ float qbs[32];
    __shared__ float kps[4 * 74 * 8];
    __shared__ float pbs[76];
    __shared__ float r1s[324];
    __shared__ float r2s[676];

    const int tid = threadIdx.x;
    const int b  = blockIdx.z;
    const int h0 = blockIdx.y * 8;
    const int w0 = blockIdx.x * 8;
    const int flat = (b * 8 + blockIdx.y) * 8 + blockIdx.x;

    for (int idx = tid; idx < 1024; idx += 256) wqs[idx] = g_wq[idx];
    if (tid < 32) qbs[tid] = g_qb[tid];
    for (int idx = tid; idx < 2368; idx += 256)
        kps[idx] = g_kproj[(size_t)b * 2368 + idx];
    if (tid < 74) pbs[tid] = proj_b[tid];
    for (int idx = tid; idx < 324; idx += 256) r1s[idx] = rpb1[idx];
    for (int idx = tid; idx < 676; idx += 256) r2s[idx] = rpb2[idx];
    __syncthreads();

    const int p = tid & 63;
    const int g = tid >> 6;
    const int ph = p >> 3, pwd = p & 7;
    const int h = h0 + ph, w = w0 + pwd;

    // ---- q (8 channels of this head) ----
    u64 qp[4];
    {
        const float* xpix = x + (size_t)b * 64 * 4096 + h * 64 + w;
        u64 xp[16];
        #pragma unroll
        for (int i = 0; i < 16; i++)
            xp[i] = pack2(xpix[(size_t)(2 * i) * 4096],
                          xpix[(size_t)(2 * i + 1) * 4096]);
        float q[8];
        #pragma unroll
        for (int c = 0; c < 8; c++) {
            const ulonglong2* wp = (const ulonglong2*)(wqs + (g * 8 + c) * 32);
            u64 a0 = 0ull, a1 = 0ull;
            #pragma unroll
            for (int j = 0; j < 4; j++) {
                const ulonglong2 w0 = wp[2 * j];
                const ulonglong2 w1 = wp[2 * j + 1];
                a0 = ffma2(w0.x, xp[4 * j + 0], a0);
                a1 = ffma2(w0.y, xp[4 * j + 1], a1);
                a0 = ffma2(w1.x, xp[4 * j + 2], a0);
                a1 = ffma2(w1.y, xp[4 * j + 3], a1);
            }
            const float2 f = unpack2(fadd2(a0, a1));
            q[c] = qbs[g * 8 + c] + f.x + f.y;
        }
        #pragma unroll
        for (int j = 0; j < 4; j++) qp[j] = pack2(q[2 * j], q[2 * j + 1]);
    }

    const int ihr = 63 - h, iwr = 63 - w;
    const float* kbase = kps + g * 74 * 8;

    // ---- part 1: 5x5, store per window row ----
    {
        const int ih1 = min(ihr, 2) + max(0, ihr - 61);
        const int iw1 = min(iwr, 2) + max(0, iwr - 61);
        const float* r1g = r1s + g * 81 + ih1 * 9 + iw1;
        float sum = 0.f;
        #pragma unroll
        for (int ki = 0; ki < 5; ki++) {
            float4 eb0;
            float eb4 = 0.f;
            #pragma unroll
            for (int kj = 0; kj < 5; kj++) {
                const int o = ki * 5 + kj;
                const float* kr = kbase + o * 8;
                const ulonglong2 k0 = *(const ulonglong2*)kr;
                const ulonglong2 k1 = *(const ulonglong2*)(kr + 4);
                const u64 a0 = ffma2(qp[0], k0.x, ffma2(qp[1], k0.y, 0ull));
                const u64 a1 = ffma2(qp[2], k1.x, ffma2(qp[3], k1.y, 0ull));
                const float2 f = unpack2(fadd2(a0, a1));
                const float v = f.x + f.y + pbs[o] + r1g[ki * 9 + kj];
                const float e = __expf(v);
                sum += e;
                if (kj == 0) eb0.x = e;
                else if (kj == 1) eb0.y = e;
                else if (kj == 2) eb0.z = e;
                else if (kj == 3) eb0.w = e;
                else eb4 = e;
            }
            float4* rowp = (float4*)(g_e + ((size_t)flat * 12 + ki) * 2048) + tid;
            rowp[0]   = eb0;
            rowp[256] = make_float4(eb4, 0.f, 0.f, 0.f);
        }
        g_inv[(size_t)flat * 512 + tid] = 1.0f / sum;
    }

    // ---- part 2: 7x7 ----
    {
        const int ih2 = min(ihr, 3) + max(0, ihr - 60);
        const int iw2 = min(iwr, 3) + max(0, iwr - 60);
        const float* r2g = r2s + g * 169 + ih2 * 13 + iw2;
        float sum = 0.f;
        #pragma unroll
        for (int ki = 0; ki < 7; ki++) {
            float4 eb0, eb1;
            eb1.w = 0.f;
            #pragma unroll
            for (int kj = 0; kj < 7; kj++) {
                const int o = 25 + ki * 7 + kj;
                const float* kr = kbase + o * 8;
                const ulonglong2 k0 = *(const ulonglong2*)kr;
                const ulonglong2 k1 = *(const ulonglong2*)(kr + 4);
                const u64 a0 = ffma2(qp[0], k0.x, ffma2(qp[1], k0.y, 0ull));
                const u64 a1 = ffma2(qp[2], k1.x, ffma2(qp[3], k1.y, 0ull));
                const float2 f = unpack2(fadd2(a0, a1));
                const float v = f.x + f.y + pbs[o] + r2g[ki * 13 + kj];
                const float e = __expf(v);
                sum += e;
                if (kj == 0) eb0.x = e;
                else if (kj == 1) eb0.y = e;
                else if (kj == 2) eb0.z = e;
                else if (kj == 3) eb0.w = e;
                else if (kj == 4) eb1.x = e;
                else if (kj == 5) eb1.y = e;
                else eb1.z = e;
            }
            float4* rowp =
                (float4*)(g_e + ((size_t)flat * 12 + 5 + ki) * 2048) + tid;
            rowp[0]   = eb0;
            rowp[256] = eb1;
        }
        g_inv[(size_t)flat * 512 + 256 + tid] = 1.0f / sum;
    }
}

// ---------------------------------------------------------------------------
// Kernel B: neighborhood aggregation only.  4 CTAs/SM (smem 49KB).
// ---------------------------------------------------------------------------
constexpr int B_XT1 = 0;       // 12*12*36 = 5184 (ch 0..31, halo 2)
constexpr int B_XT2 = 5184;    // 14*14*36 = 7056 (ch 32..63, halo 3)
constexpr int B_TOT = 12240;   // 48960 bytes

__global__ void __launch_bounds__(256, 4)
b_kernel(const float* __restrict__ x)
{
    extern __shared__ float sm[];
    float* xt1 = sm + B_XT1;
    float* xt2 = sm + B_XT2;

    const int tid = threadIdx.x;
    const int b  = blockIdx.z;
    const int h0 = blockIdx.y * 8;
    const int w0 = blockIdx.x * 8;
    const int flat = (b * 8 + blockIdx.y) * 8 + blockIdx.x;
    const float* xb = x + (size_t)b * 64 * 4096;

    for (int idx = tid; idx < 32 * 144; idx += 256) {
        const int t = idx % 12, s0 = (idx / 12) % 12, ch = idx / 144;
        const int gr = min(max(h0 - 2 + s0, 0), 63);
        const int gc = min(max(w0 - 2 + t, 0), 63);
        xt1[(s0 * 12 + t) * 36 + ch] = xb[ch * 4096 + gr * 64 + gc];
    }
    for (int idx = tid; idx < 32 * 196; idx += 256) {
        const int t = idx % 14, s0 = (idx / 14) % 14, ch = idx / 196;
        const int gr = min(max(h0 - 3 + s0, 0), 63);
        const int gc = min(max(w0 - 3 + t, 0), 63);
        xt2[(s0 * 14 + t) * 36 + ch] = xb[(32 + ch) * 4096 + gr * 64 + gc];
    }
    __syncthreads();

    const int p = tid & 63;
    const int g = tid >> 6;
    const int ph = p >> 3, pwd = p & 7;
    const int h = h0 + ph, w = w0 + pwd;
    float* obp = g_ob + ((size_t)b * 4096 + h * 64 + w) * 64 + g * 8;

    // ---- part 1: 5x5 ----
    {
        const int si = min(max(h - 2, 0), 59) - (h0 - 2);
        const int sj = min(max(w - 2, 0), 59) - (w0 - 2);
        u64 c0 = 0ull, c1 = 0ull, c2 = 0ull, c3 = 0ull;
        #pragma unroll
        for (int ki = 0; ki < 5; ki++) {
            const float4* rp =
                (const float4*)(g_e + ((size_t)flat * 12 + ki) * 2048) + tid;
            const float4 va = rp[0];
            const float e4 = rp[256].x;
            const float ev[5] = {va.x, va.y, va.z, va.w, e4};
            const float* row = xt1 + ((si + ki) * 12 + sj) * 36 + g * 8;
            #pragma unroll
            for (int kj = 0; kj < 5; kj++) {
                const u64 ee = pack2(ev[kj], ev[kj]);
                const ulonglong2 v0 = *(const ulonglong2*)(row + kj * 36);
                const ulonglong2 v1 = *(const ulonglong2*)(row + kj * 36 + 4);
                c0 = ffma2(ee, v0.x, c0);
                c1 = ffma2(ee, v0.y, c1);
                c2 = ffma2(ee, v1.x, c2);
                c3 = ffma2(ee, v1.y, c3);
            }
        }
        const float inv = g_inv[(size_t)flat * 512 + tid];
        float2 f;
        float4 oA, oB;
        f = unpack2(c0); oA.x = f.x * inv; oA.y = f.y * inv;
        f = unpack2(c1); oA.z = f.x * inv; oA.w = f.y * inv;
        f = unpack2(c2); oB.x = f.x * inv; oB.y = f.y * inv;
        f = unpack2(c3); oB.z = f.x * inv; oB.w = f.y * inv;
        *(float4*)(obp)     = oA;
        *(float4*)(obp + 4) = oB;
    }

    // ---- part 2: 7x7 ----
    {
        const int si = min(max(h - 3, 0), 57) - (h0 - 3);
        const int sj = min(max(w - 3, 0), 57) - (w0 - 3);
        u64 c0 = 0ull, c1 = 0ull, c2 = 0ull, c3 = 0ull;
        #pragma unroll
        for (int ki = 0; ki < 7; ki++) {
            const float4* rp =
                (const float4*)(g_e + ((size_t)flat * 12 + 5 + ki) * 2048) + tid;
            const float4 va = rp[0];
            const float4 vb = rp[256];
            const float ev[7] = {va.x, va.y, va.z, va.w, vb.x, vb.y, vb.z};
            const float* row = xt2 + ((si + ki) * 14 + sj) * 36 + g * 8;
            #pragma unroll
            for (int kj = 0; kj < 7; kj++) {
                const u64 ee = pack2(ev[kj], ev[kj]);
                const ulonglong2 v0 = *(const ulonglong2*)(row + kj * 36);
                const ulonglong2 v1 = *(const ulonglong2*)(row + kj * 36 + 4);
                c0 = ffma2(ee, v0.x, c0);
                c1 = ffma2(ee, v0.y, c1);
                c2 = ffma2(ee, v1.x, c2);
                c3 = ffma2(ee, v1.y, c3);
            }
        }
        const float inv = g_inv[(size_t)flat * 512 + 256 + tid];
        float2 f;
        float4 oA, oB;
        f = unpack2(c0); oA.x = f.x * inv; oA.y = f.y * inv;
        f = unpack2(c1); oA.z = f.x * inv; oA.w = f.y * inv;
        f = unpack2(c2); oB.x = f.x * inv; oB.y = f.y * inv;
        f = unpack2(c3); oB.z = f.x * inv; oB.w = f.y * inv;
        *(float4*)(obp + 32)     = oA;
        *(float4*)(obp + 32 + 4) = oB;
    }
}

// ---------------------------------------------------------------------------
// Kernel C: dy 1x1 conv + BN.  Block = 64 pixels (one image row).
// obs uses group-rotation swizzle to avoid bank conflicts.
// ---------------------------------------------------------------------------
__global__ void __launch_bounds__(256, 4)
c_kernel(float* __restrict__ out)
{
    __shared__ float dyws[64 * 68];
    __shared__ float dybs[64];
    __shared__ float obs[64 * 64];

    const int tid = threadIdx.x;
    const int b = blockIdx.x >> 6;
    const int chunk = blockIdx.x & 63;
    const int px0 = chunk * 64;

    for (int idx = tid; idx < 4096; idx += 256)
        dyws[(idx >> 6) * 68 + (idx & 63)] = g_dyw[idx];
    if (tid < 64) dybs[tid] = g_dyb[tid];

    const float4* src = (const float4*)(g_ob + ((size_t)b * 4096 + px0) * 64);
    #pragma unroll
    for (int it = 0; it < 4; it++) {
        const int idx = tid + it * 256;
        const int px = idx >> 4, c4 = idx & 15;
        const float4 v = src[idx];
        *(float4*)(obs + px * 64 + ((c4 + px) & 15) * 4) = v;
    }
    __syncthreads();

    const int p = tid & 63;
    const int r = tid >> 6;
    u64 acc[16];
    #pragma unroll
    for (int j = 0; j < 16; j++) acc[j] = 0ull;

    #pragma unroll
    for (int c4 = 0; c4 < 16; c4++) {
        const ulonglong2 xv =
            *(const ulonglong2*)(obs + p * 64 + ((c4 + p) & 15) * 4);
        #pragma unroll
        for (int j = 0; j < 16; j++) {
            const ulonglong2 wv =
                *(const ulonglong2*)(dyws + (r + 4 * j) * 68 + c4 * 4);
            acc[j] = ffma2(xv.x, wv.x, acc[j]);
            acc[j] = ffma2(xv.y, wv.y, acc[j]);
        }
    }

    float* outp = out + (size_t)b * 262144 + px0 + p;
    #pragma unroll
    for (int j = 0; j < 16; j++) {
        const float2 f = unpack2(acc[j]);
        outp[(size_t)(r + 4 * j) * 4096] = f.x + f.y + dybs[r + 4 * j];
    }
}

// ---------------------------------------------------------------------------
extern "C" void kernel_launch(void* const* d_in, const int* in_sizes, int n_in,
                              void* d_out, int out_size)
{
    const float* x      = (const float*)d_in[0];
    const float* wq_w   = (const float*)d_in[1];
    const float* wq_g   = (const float*)d_in[2];
    const float* wq_b   = (const float*)d_in[3];
    const float* wq_m   = (const float*)d_in[4];
    const float* wq_v   = (const float*)d_in[5];
    const float* wk_w   = (const float*)d_in[6];
    const float* wk_g   = (const float*)d_in[7];
    const float* wk_b   = (const float*)d_in[8];
    const float* wk_m   = (const float*)d_in[9];
    const float* wk_v   = (const float*)d_in[10];
    const float* proj_w = (const float*)d_in[11];
    const float* proj_b = (const float*)d_in[12];
    const float* rpb1   = (const float*)d_in[13];
    const float* rpb2   = (const float*)d_in[14];
    const float* dy_w   = (const float*)d_in[15];
    const float* dy_g   = (const float*)d_in[16];
    const float* dy_b   = (const float*)d_in[17];
    const float* dy_m   = (const float*)d_in[18];
    const float* dy_v   = (const float*)d_in[19];
    float* out = (float*)d_out;

    cudaFuncSetAttribute(b_kernel, cudaFuncAttributeMaxDynamicSharedMemorySize,
                         B_TOT * (int)sizeof(float));

    pool_kernel<<<256, 256>>>(x);
    kconv_kernel<<<8, 256>>>(wk_w, wk_g, wk_b, wk_m, wk_v,
                             wq_w, wq_g, wq_b, wq_m, wq_v,
                             dy_w, dy_g, dy_b, dy_m, dy_v);
    kproj_kernel<<<dim3(4, 8), 256>>>(proj_w);

    dim3 gm(8, 8, 8);
    a_kernel<<<gm, 256>>>(x, proj_b, rpb1, rpb2);
    b_kernel<<<gm, 256, B_TOT * (int)sizeof(float)>>>(x);
    c_kernel<<<512, 256>>>(out);
}

// round 6
// speedup vs baseline: 2.4722x; 1.2140x over previous
#include <cuda_runtime.h>

#define EPSF 1e-5f

typedef unsigned long long u64;

__device__ __forceinline__ u64 ffma2(u64 a, u64 b, u64 c) {
    u64 d;
    asm("fma.rn.f32x2 %0, %1, %2, %3;" : "=l"(d) : "l"(a), "l"(b), "l"(c));
    return d;
}
__device__ __forceinline__ u64 fadd2(u64 a, u64 b) {
    u64 d;
    asm("add.rn.f32x2 %0, %1, %2;" : "=l"(d) : "l"(a), "l"(b));
    return d;
}
__device__ __forceinline__ u64 pack2(float lo, float hi) {
    u64 d;
    asm("mov.b64 %0, {%1, %2};" : "=l"(d) : "f"(lo), "f"(hi));
    return d;
}
__device__ __forceinline__ float2 unpack2(u64 a) {
    float2 r;
    asm("mov.b64 {%0, %1}, %2;" : "=f"(r.x), "=f"(r.y) : "l"(a));
    return r;
}

// ---------------------------------------------------------------------------
// device scratch (static allocation only)
// ---------------------------------------------------------------------------
__device__ float g_kp[8 * 32 * 49];         // pooled context [b][ci][pos]
__device__ float g_k[8 * 4 * 49 * 8];       // pooled keys [b][g][l][c]
__device__ float g_kproj[8 * 4 * 74 * 8];   // proj-folded keys [b][g][o][c]
__device__ float g_wq[32 * 32];             // BN+SCALE folded q weights
__device__ float g_qb[32];
__device__ float g_dyw[64 * 64];            // BN folded dy weights
__device__ float g_dyb[64];
__device__ float g_ob[8 * 4096 * 64];       // aggregated values [b][hw][ch]

// ---------------------------------------------------------------------------
// Kernel P: adaptive pool 64x64 -> 7x7, one block per (batch, channel)
// ---------------------------------------------------------------------------
__global__ void __launch_bounds__(256)
pool_kernel(const float* __restrict__ x)
{
    __shared__ float ch[4096];
    __shared__ float rp[64 * 7];

    const int b  = blockIdx.x >> 5;
    const int ci = blockIdx.x & 31;
    const int tid = threadIdx.x;

    const float4* src = (const float4*)(x + ((size_t)b * 64 + 32 + ci) * 4096);
    float4* dst = (float4*)ch;
    #pragma unroll
    for (int j = 0; j < 4; j++)
        dst[tid + 256 * j] = src[tid + 256 * j];
    __syncthreads();

    for (int idx = tid; idx < 64 * 7; idx += 256) {
        const int r = idx / 7, q = idx % 7;
        const int sw = (q * 64) / 7;
        const int ew = ((q + 1) * 64 + 6) / 7;
        float acc = 0.f;
        for (int v = sw; v < ew; v++) acc += ch[r * 64 + v];
        rp[idx] = acc;
    }
    __syncthreads();

    if (tid < 49) {
        const int p = tid / 7, q = tid % 7;
        const int sh = (p * 64) / 7;
        const int eh = ((p + 1) * 64 + 6) / 7;
        const int sw = (q * 64) / 7;
        const int ew = ((q + 1) * 64 + 6) / 7;
        float acc = 0.f;
        for (int r = sh; r < eh; r++) acc += rp[r * 7 + q];
        g_kp[((size_t)b * 32 + ci) * 49 + tid] =
            acc / (float)((eh - sh) * (ew - sw));
    }
}

// ---------------------------------------------------------------------------
// Kernel K: 32x32 conv + BN on pooled tile; block 0 also folds wq/dy weights
// ---------------------------------------------------------------------------
__global__ void __launch_bounds__(256)
kconv_kernel(const float* __restrict__ wk_w,
             const float* __restrict__ wk_g,
             const float* __restrict__ wk_b,
             const float* __restrict__ wk_m,
             const float* __restrict__ wk_v,
             const float* __restrict__ wq_w,
             const float* __restrict__ wq_g,
             const float* __restrict__ wq_b,
             const float* __restrict__ wq_m,
             const float* __restrict__ wq_v,
             const float* __restrict__ dy_w,
             const float* __restrict__ dy_g,
             const float* __restrict__ dy_b,
             const float* __restrict__ dy_m,
             const float* __restrict__ dy_v)
{
    __shared__ float kps[32 * 49];
    const int b = blockIdx.x;
    const int tid = threadIdx.x;

    if (b == 0) {
        for (int idx = tid; idx < 1024; idx += 256) {
            const int o = idx >> 5, i = idx & 31;
            const float alpha = wq_g[o] * rsqrtf(wq_v[o] + EPSF) * 0.25f;
            g_wq[idx] = alpha * wq_w[idx];
            if (i == 0) g_qb[o] = 0.25f * wq_b[o] - wq_m[o] * alpha;
        }
        for (int idx = tid; idx < 4096; idx += 256) {
            const int o = idx >> 6;
            const float alpha = dy_g[o] * rsqrtf(dy_v[o] + EPSF);
            g_dyw[idx] = alpha * dy_w[idx];
            if ((idx & 63) == 0) g_dyb[o] = dy_b[o] - dy_m[o] * alpha;
        }
    }

    for (int idx = tid; idx < 1568; idx += 256)
        kps[idx] = g_kp[(size_t)b * 1568 + idx];
    __syncthreads();

    for (int idx = tid; idx < 1568; idx += 256) {
        const int o = idx / 49, pos = idx % 49;
        const float alpha = wk_g[o] * rsqrtf(wk_v[o] + EPSF);
        const float beta  = wk_b[o] - wk_m[o] * alpha;
        float acc = 0.f;
        #pragma unroll
        for (int i = 0; i < 32; i++)
            acc += wk_w[o * 32 + i] * kps[i * 49 + pos];
        const float val = alpha * acc + beta;
        const int g = o >> 3, c = o & 7;
        g_k[(((size_t)b * 4 + g) * 49 + pos) * 8 + c] = val;
    }
}

// ---------------------------------------------------------------------------
// Kernel KP: kproj[b,g,o,c] = sum_l proj_w[o,l] * k[b,g,l,c]
// ---------------------------------------------------------------------------
__global__ void __launch_bounds__(256)
kproj_kernel(const float* __restrict__ proj_w)
{
    __shared__ float pws[74 * 49];
    __shared__ float ktg[49 * 8];
    const int g = blockIdx.x;
    const int b = blockIdx.y;
    const int tid = threadIdx.x;

    for (int idx = tid; idx < 74 * 49; idx += 256) pws[idx] = proj_w[idx];
    for (int idx = tid; idx < 392; idx += 256)
        ktg[idx] = g_k[((size_t)(b * 4 + g) * 49) * 8 + idx];
    __syncthreads();

    for (int idx = tid; idx < 74 * 8; idx += 256) {
        const int o = idx >> 3, c = idx & 7;
        float acc = 0.f;
        #pragma unroll
        for (int l = 0; l < 49; l++)
            acc += pws[o * 49 + l] * ktg[l * 8 + c];
        g_kproj[((size_t)(b * 4 + g) * 74 + o) * 8 + c] = acc;
    }
}

// ---------------------------------------------------------------------------
// Kernel M: merged logits+exp+aggregation.  512 threads, 16x8 tile, 2 CTAs/SM.
// ---------------------------------------------------------------------------
constexpr int M_XT1 = 0;        // 20*12*36 = 8640  (ch 0..31, halo 2)
constexpr int M_XT2 = 8640;     // 22*14*36 = 11088 (ch 32..63, halo 3)
constexpr int M_WQ  = 19728;    // 1024
constexpr int M_QB  = 20752;    // 32
constexpr int M_KP  = 20784;    // 2368
constexpr int M_PB  = 23152;    // 76
constexpr int M_R1  = 23228;    // 324
constexpr int M_R2  = 23552;    // 676
constexpr int M_TOT = 24228;    // floats -> 96912 bytes

__global__ void __launch_bounds__(512, 2)
m_kernel(const float* __restrict__ x,
         const float* __restrict__ proj_b,
         const float* __restrict__ rpb1, const float* __restrict__ rpb2)
{
    extern __shared__ float sm[];
    float* xt1 = sm + M_XT1;
    float* xt2 = sm + M_XT2;
    float* wqs = sm + M_WQ;
    float* qbs = sm + M_QB;
    float* kps = sm + M_KP;
    float* pbs = sm + M_PB;
    float* r1s = sm + M_R1;
    float* r2s = sm + M_R2;

    const int tid = threadIdx.x;
    const int b  = blockIdx.z;
    const int h0 = blockIdx.y * 16;
    const int w0 = blockIdx.x * 8;
    const float* xb = x + (size_t)b * 64 * 4096;

    // ---- cooperative staging ----
    for (int idx = tid; idx < 32 * 240; idx += 512) {
        const int t = idx % 12, s0 = (idx / 12) % 20, ch = idx / 240;
        const int gr = min(max(h0 - 2 + s0, 0), 63);
        const int gc = min(max(w0 - 2 + t, 0), 63);
        xt1[(s0 * 12 + t) * 36 + ch] = xb[ch * 4096 + gr * 64 + gc];
    }
    for (int idx = tid; idx < 32 * 308; idx += 512) {
        const int t = idx % 14, s0 = (idx / 14) % 22, ch = idx / 308;
        const int gr = min(max(h0 - 3 + s0, 0), 63);
        const int gc = min(max(w0 - 3 + t, 0), 63);
        xt2[(s0 * 14 + t) * 36 + ch] = xb[(32 + ch) * 4096 + gr * 64 + gc];
    }
    for (int idx = tid; idx < 1024; idx += 512) wqs[idx] = g_wq[idx];
    if (tid < 32) qbs[tid] = g_qb[tid];
    for (int idx = tid; idx < 2368; idx += 512)
        kps[idx] = g_kproj[(size_t)b * 2368 + idx];
    if (tid < 74) pbs[tid] = proj_b[tid];
    if (tid >= 128 && tid < 452) r1s[tid - 128] = rpb1[tid - 128];
    for (int idx = tid; idx < 676; idx += 512) r2s[idx] = rpb2[idx];
    __syncthreads();

    const int p = tid & 127;
    const int g = tid >> 7;
    const int ph = p >> 3, pwd = p & 7;
    const int h = h0 + ph, w = w0 + pwd;

    // ---- q (8 channels of this head) from xt1 ----
    u64 qp[4];
    {
        const float* xpix = xt1 + ((ph + 2) * 12 + (pwd + 2)) * 36;
        const float* wrow = wqs + g * 8 * 32;
        u64 acc[8];
        #pragma unroll
        for (int c = 0; c < 8; c++) acc[c] = 0ull;
        #pragma unroll
        for (int i4 = 0; i4 < 8; i4++) {
            const ulonglong2 xv = *(const ulonglong2*)(xpix + i4 * 4);
            #pragma unroll
            for (int c = 0; c < 8; c++) {
                const ulonglong2 wv =
                    *(const ulonglong2*)(wrow + c * 32 + i4 * 4);
                acc[c] = ffma2(xv.x, wv.x, acc[c]);
                acc[c] = ffma2(xv.y, wv.y, acc[c]);
            }
        }
        float q[8];
        #pragma unroll
        for (int c = 0; c < 8; c++) {
            const float2 f = unpack2(acc[c]);
            q[c] = qbs[g * 8 + c] + f.x + f.y;
        }
        #pragma unroll
        for (int j = 0; j < 4; j++) qp[j] = pack2(q[2 * j], q[2 * j + 1]);
    }

    const int ihr = 63 - h, iwr = 63 - w;
    const float* kbase = kps + g * 74 * 8;
    float* obp = g_ob + ((size_t)b * 4096 + h * 64 + w) * 64 + g * 8;

    // ===== part 1: 5x5 fused =====
    {
        const int ih1 = min(ihr, 2) + max(0, ihr - 61);
        const int iw1 = min(iwr, 2) + max(0, iwr - 61);
        const float* r1g = r1s + g * 81 + ih1 * 9 + iw1;
        const int si = min(max(h - 2, 0), 59) - (h0 - 2);
        const int sj = min(max(w - 2, 0), 59) - (w0 - 2);

        u64 c0 = 0ull, c1 = 0ull, c2 = 0ull, c3 = 0ull;
        float sum = 0.f;
        #pragma unroll
        for (int ki = 0; ki < 5; ki++) {
            const float* row = xt1 + ((si + ki) * 12 + sj) * 36 + g * 8;
            #pragma unroll
            for (int kj = 0; kj < 5; kj++) {
                const int o = ki * 5 + kj;
                const float* kr = kbase + o * 8;
                const ulonglong2 k0 = *(const ulonglong2*)kr;
                const ulonglong2 k1 = *(const ulonglong2*)(kr + 4);
                const u64 a0 = ffma2(qp[0], k0.x, ffma2(qp[1], k0.y, 0ull));
                const u64 a1 = ffma2(qp[2], k1.x, ffma2(qp[3], k1.y, 0ull));
                const float2 f = unpack2(fadd2(a0, a1));
                const float v = f.x + f.y + pbs[o] + r1g[ki * 9 + kj];
                const float e = __expf(v);
                sum += e;
                const u64 ee = pack2(e, e);
                const ulonglong2 v0 = *(const ulonglong2*)(row + kj * 36);
                const ulonglong2 v1 = *(const ulonglong2*)(row + kj * 36 + 4);
                c0 = ffma2(ee, v0.x, c0);
                c1 = ffma2(ee, v0.y, c1);
                c2 = ffma2(ee, v1.x, c2);
                c3 = ffma2(ee, v1.y, c3);
            }
        }
        const float inv = 1.0f / sum;
        float2 f;
        float4 oA, oB;
        f = unpack2(c0); oA.x = f.x * inv; oA.y = f.y * inv;
        f = unpack2(c1); oA.z = f.x * inv; oA.w = f.y * inv;
        f = unpack2(c2); oB.x = f.x * inv; oB.y = f.y * inv;
        f = unpack2(c3); oB.z = f.x * inv; oB.w = f.y * inv;
        *(float4*)(obp)     = oA;
        *(float4*)(obp + 4) = oB;
    }

    // ===== part 2: 7x7 fused =====
    {
        const int ih2 = min(ihr, 3) + max(0, ihr - 60);
        const int iw2 = min(iwr, 3) + max(0, iwr - 60);
        const float* r2g = r2s + g * 169 + ih2 * 13 + iw2;
        const int si = min(max(h - 3, 0), 57) - (h0 - 3);
        const int sj = min(max(w - 3, 0), 57) - (w0 - 3);

        u64 c0 = 0ull, c1 = 0ull, c2 = 0ull, c3 = 0ull;
        float sum = 0.f;
        #pragma unroll
        for (int ki = 0; ki < 7; ki++) {
            const float* row = xt2 + ((si + ki) * 14 + sj) * 36 + g * 8;
            #pragma unroll
            for (int kj = 0; kj < 7; kj++) {
                const int o = 25 + ki * 7 + kj;
                const float* kr = kbase + o * 8;
                const ulonglong2 k0 = *(const ulonglong2*)kr;
                const ulonglong2 k1 = *(const ulonglong2*)(kr + 4);
                const u64 a0 = ffma2(qp[0], k0.x, ffma2(qp[1], k0.y, 0ull));
                const u64 a1 = ffma2(qp[2], k1.x, ffma2(qp[3], k1.y, 0ull));
                const float2 f = unpack2(fadd2(a0, a1));
                const float v = f.x + f.y + pbs[o] + r2g[ki * 13 + kj];
                const float e = __expf(v);
                sum += e;
                const u64 ee = pack2(e, e);
                const ulonglong2 v0 = *(const ulonglong2*)(row + kj * 36);
                const ulonglong2 v1 = *(const ulonglong2*)(row + kj * 36 + 4);
                c0 = ffma2(ee, v0.x, c0);
                c1 = ffma2(ee, v0.y, c1);
                c2 = ffma2(ee, v1.x, c2);
                c3 = ffma2(ee, v1.y, c3);
            }
        }
        const float inv = 1.0f / sum;
        float2 f;
        float4 oA, oB;
        f = unpack2(c0); oA.x = f.x * inv; oA.y = f.y * inv;
        f = unpack2(c1); oA.z = f.x * inv; oA.w = f.y * inv;
        f = unpack2(c2); oB.x = f.x * inv; oB.y = f.y * inv;
        f = unpack2(c3); oB.z = f.x * inv; oB.w = f.y * inv;
        *(float4*)(obp + 32)     = oA;
        *(float4*)(obp + 32 + 4) = oB;
    }
}

// ---------------------------------------------------------------------------
// Kernel C: dy 1x1 conv + BN.  Block = 64 pixels.
// ---------------------------------------------------------------------------
__global__ void __launch_bounds__(256, 4)
c_kernel(float* __restrict__ out)
{
    __shared__ float dyws[64 * 68];
    __shared__ float dybs[64];
    __shared__ float obs[64 * 64];

    const int tid = threadIdx.x;
    const int b = blockIdx.x >> 6;
    const int chunk = blockIdx.x & 63;
    const int px0 = chunk * 64;

    for (int idx = tid; idx < 4096; idx += 256)
        dyws[(idx >> 6) * 68 + (idx & 63)] = g_dyw[idx];
    if (tid < 64) dybs[tid] = g_dyb[tid];

    const float4* src = (const float4*)(g_ob + ((size_t)b * 4096 + px0) * 64);
    #pragma unroll
    for (int it = 0; it < 4; it++) {
        const int idx = tid + it * 256;
        const int px = idx >> 4, c4 = idx & 15;
        const float4 v = src[idx];
        *(float4*)(obs + px * 64 + ((c4 + px) & 15) * 4) = v;
    }
    __syncthreads();

    const int p = tid & 63;
    const int r = tid >> 6;
    u64 acc[16];
    #pragma unroll
    for (int j = 0; j < 16; j++) acc[j] = 0ull;

    #pragma unroll
    for (int c4 = 0; c4 < 16; c4++) {
        const ulonglong2 xv =
            *(const ulonglong2*)(obs + p * 64 + ((c4 + p) & 15) * 4);
        #pragma unroll
        for (int j = 0; j < 16; j++) {
            const ulonglong2 wv =
                *(const ulonglong2*)(dyws + (r + 4 * j) * 68 + c4 * 4);
            acc[j] = ffma2(xv.x, wv.x, acc[j]);
            acc[j] = ffma2(xv.y, wv.y, acc[j]);
        }
    }

    float* outp = out + (size_t)b * 262144 + px0 + p;
    #pragma unroll
    for (int j = 0; j < 16; j++) {
        const float2 f = unpack2(acc[j]);
        outp[(size_t)(r + 4 * j) * 4096] = f.x + f.y + dybs[r + 4 * j];
    }
}

// ---------------------------------------------------------------------------
extern "C" void kernel_launch(void* const* d_in, const int* in_sizes, int n_in,
                              void* d_out, int out_size)
{
    const float* x      = (const float*)d_in[0];
    const float* wq_w   = (const float*)d_in[1];
    const float* wq_g   = (const float*)d_in[2];
    const float* wq_b   = (const float*)d_in[3];
    const float* wq_m   = (const float*)d_in[4];
    const float* wq_v   = (const float*)d_in[5];
    const float* wk_w   = (const float*)d_in[6];
    const float* wk_g   = (const float*)d_in[7];
    const float* wk_b   = (const float*)d_in[8];
    const float* wk_m   = (const float*)d_in[9];
    const float* wk_v   = (const float*)d_in[10];
    const float* proj_w = (const float*)d_in[11];
    const float* proj_b = (const float*)d_in[12];
    const float* rpb1   = (const float*)d_in[13];
    const float* rpb2   = (const float*)d_in[14];
    const float* dy_w   = (const float*)d_in[15];
    const float* dy_g   = (const float*)d_in[16];
    const float* dy_b   = (const float*)d_in[17];
    const float* dy_m   = (const float*)d_in[18];
    const float* dy_v   = (const float*)d_in[19];
    float* out = (float*)d_out;

    cudaFuncSetAttribute(m_kernel, cudaFuncAttributeMaxDynamicSharedMemorySize,
                         M_TOT * (int)sizeof(float));

    pool_kernel<<<256, 256>>>(x);
    kconv_kernel<<<8, 256>>>(wk_w, wk_g, wk_b, wk_m, wk_v,
                             wq_w, wq_g, wq_b, wq_m, wq_v,
                             dy_w, dy_g, dy_b, dy_m, dy_v);
    kproj_kernel<<<dim3(4, 8), 256>>>(proj_w);

    dim3 gm(8, 4, 8);
    m_kernel<<<gm, 512, M_TOT * (int)sizeof(float)>>>(x, proj_b, rpb1, rpb2);
    c_kernel<<<512, 256>>>(out);
}

// round 7
// speedup vs baseline: 2.7305x; 1.1045x over previous
#include <cuda_runtime.h>

#define EPSF 1e-5f

typedef unsigned long long u64;

__device__ __forceinline__ u64 ffma2(u64 a, u64 b, u64 c) {
    u64 d;
    asm("fma.rn.f32x2 %0, %1, %2, %3;" : "=l"(d) : "l"(a), "l"(b), "l"(c));
    return d;
}
__device__ __forceinline__ u64 fadd2(u64 a, u64 b) {
    u64 d;
    asm("add.rn.f32x2 %0, %1, %2;" : "=l"(d) : "l"(a), "l"(b));
    return d;
}
__device__ __forceinline__ u64 pack2(float lo, float hi) {
    u64 d;
    asm("mov.b64 %0, {%1, %2};" : "=l"(d) : "f"(lo), "f"(hi));
    return d;
}
__device__ __forceinline__ float2 unpack2(u64 a) {
    float2 r;
    asm("mov.b64 {%0, %1}, %2;" : "=f"(r.x), "=f"(r.y) : "l"(a));
    return r;
}

// ---------------------------------------------------------------------------
// device scratch (static allocation only)
// ---------------------------------------------------------------------------
__device__ float g_kp[8 * 32 * 49];         // pooled context [b][ci][pos]
__device__ float g_kproj[8 * 4 * 74 * 8];   // proj-folded keys [b][g][o][c]
__device__ float g_wq[32 * 32];             // BN+SCALE folded q weights
__device__ float g_qb[32];
__device__ float g_dyw[64 * 64];            // BN folded dy weights
__device__ float g_dyb[64];

// ---------------------------------------------------------------------------
// Kernel P: adaptive pool 64x64 -> 7x7, one block per (batch, channel)
// ---------------------------------------------------------------------------
__global__ void __launch_bounds__(256)
pool_kernel(const float* __restrict__ x)
{
    __shared__ float ch[4096];
    __shared__ float rp[64 * 7];

    const int b  = blockIdx.x >> 5;
    const int ci = blockIdx.x & 31;
    const int tid = threadIdx.x;

    const float4* src = (const float4*)(x + ((size_t)b * 64 + 32 + ci) * 4096);
    float4* dst = (float4*)ch;
    #pragma unroll
    for (int j = 0; j < 4; j++)
        dst[tid + 256 * j] = src[tid + 256 * j];
    __syncthreads();

    for (int idx = tid; idx < 64 * 7; idx += 256) {
        const int r = idx / 7, q = idx % 7;
        const int sw = (q * 64) / 7;
        const int ew = ((q + 1) * 64 + 6) / 7;
        float acc = 0.f;
        for (int v = sw; v < ew; v++) acc += ch[r * 64 + v];
        rp[idx] = acc;
    }
    __syncthreads();

    if (tid < 49) {
        const int p = tid / 7, q = tid % 7;
        const int sh = (p * 64) / 7;
        const int eh = ((p + 1) * 64 + 6) / 7;
        const int sw = (q * 64) / 7;
        const int ew = ((q + 1) * 64 + 6) / 7;
        float acc = 0.f;
        for (int r = sh; r < eh; r++) acc += rp[r * 7 + q];
        g_kp[((size_t)b * 32 + ci) * 49 + tid] =
            acc / (float)((eh - sh) * (ew - sw));
    }
}

// ---------------------------------------------------------------------------
// Kernel KC: fused (k conv+BN) -> kproj, one block per batch.
// Block 0 also folds wq / dy weights.
// ---------------------------------------------------------------------------
__global__ void __launch_bounds__(256)
kc_kernel(const float* __restrict__ wk_w,
          const float* __restrict__ wk_g,
          const float* __restrict__ wk_b,
          const float* __restrict__ wk_m,
          const float* __restrict__ wk_v,
          const float* __restrict__ proj_w,
          const float* __restrict__ wq_w,
          const float* __restrict__ wq_g,
          const float* __restrict__ wq_b,
          const float* __restrict__ wq_m,
          const float* __restrict__ wq_v,
          const float* __restrict__ dy_w,
          const float* __restrict__ dy_g,
          const float* __restrict__ dy_b,
          const float* __restrict__ dy_m,
          const float* __restrict__ dy_v)
{
    __shared__ float kpin[1568];     // pooled context [ci][pos]
    __shared__ float kt[1568];       // keys [g][l][c]
    __shared__ float pws[74 * 49];

    const int b = blockIdx.x;
    const int tid = threadIdx.x;

    if (b == 0) {
        for (int idx = tid; idx < 1024; idx += 256) {
            const int o = idx >> 5, i = idx & 31;
            const float alpha = wq_g[o] * rsqrtf(wq_v[o] + EPSF) * 0.25f;
            g_wq[idx] = alpha * wq_w[idx];
            if (i == 0) g_qb[o] = 0.25f * wq_b[o] - wq_m[o] * alpha;
        }
        for (int idx = tid; idx < 4096; idx += 256) {
            const int o = idx >> 6;
            const float alpha = dy_g[o] * rsqrtf(dy_v[o] + EPSF);
            g_dyw[idx] = alpha * dy_w[idx];
            if ((idx & 63) == 0) g_dyb[o] = dy_b[o] - dy_m[o] * alpha;
        }
    }

    for (int idx = tid; idx < 1568; idx += 256)
        kpin[idx] = g_kp[(size_t)b * 1568 + idx];
    for (int idx = tid; idx < 74 * 49; idx += 256) pws[idx] = proj_w[idx];
    __syncthreads();

    // k = BN(conv1x1(pooled))
    for (int idx = tid; idx < 1568; idx += 256) {
        const int o = idx / 49, pos = idx % 49;
        const float alpha = wk_g[o] * rsqrtf(wk_v[o] + EPSF);
        const float beta  = wk_b[o] - wk_m[o] * alpha;
        float acc = 0.f;
        #pragma unroll
        for (int i = 0; i < 32; i++)
            acc += wk_w[o * 32 + i] * kpin[i * 49 + pos];
        kt[(((o >> 3) * 49) + pos) * 8 + (o & 7)] = alpha * acc + beta;
    }
    __syncthreads();

    // kproj[g][o][c] = sum_l pw[o][l] * k[g][l][c]
    for (int idx = tid; idx < 2368; idx += 256) {
        const int g = idx / 592;
        const int rem = idx % 592;
        const int o = rem >> 3, c = rem & 7;
        float acc = 0.f;
        #pragma unroll
        for (int l = 0; l < 49; l++)
            acc += pws[o * 49 + l] * kt[(g * 49 + l) * 8 + c];
        g_kproj[(size_t)b * 2368 + idx] = acc;
    }
}

// ---------------------------------------------------------------------------
// Kernel M: fully fused main kernel.  512 threads, 16x8 tile, 2 CTAs/SM.
// q conv -> logits(q.kproj) -> exp -> aggregation -> dy conv + BN
// ---------------------------------------------------------------------------
constexpr int M_XT1 = 0;        // 20*12*36 = 8640  (ch 0..31, halo 2); obs alias
constexpr int M_XT2 = 8640;     // 22*14*36 = 11088 (ch 32..63, halo 3)
constexpr int M_BUF = 19728;    // 2368: wq (first 1024) then kproj
constexpr int M_QB  = 22096;    // 32
constexpr int M_PB  = 22128;    // 76
constexpr int M_R1  = 22204;    // 324
constexpr int M_R2  = 22528;    // 676
constexpr int M_DYW = 23204;    // 4096
constexpr int M_DYB = 27300;    // 64
constexpr int M_TOT = 27364;    // floats -> 109456 bytes (x2 = 218912 <= 227KB)

__global__ void __launch_bounds__(512, 2)
m_kernel(const float* __restrict__ x,
         const float* __restrict__ proj_b,
         const float* __restrict__ rpb1, const float* __restrict__ rpb2,
         float* __restrict__ out)
{
    extern __shared__ float sm[];
    float* xt1 = sm + M_XT1;
    float* xt2 = sm + M_XT2;
    float* buf = sm + M_BUF;
    float* qbs = sm + M_QB;
    float* pbs = sm + M_PB;
    float* r1s = sm + M_R1;
    float* r2s = sm + M_R2;
    float* dyws = sm + M_DYW;
    float* dybs = sm + M_DYB;
    float* obs = sm + M_XT1;    // alias: valid after part-1 barrier

    const int tid = threadIdx.x;
    const int b  = blockIdx.z;
    const int h0 = blockIdx.y * 16;
    const int w0 = blockIdx.x * 8;
    const float* xb = x + (size_t)b * 64 * 4096;

    // ---- stage phase 1 ----
    for (int idx = tid; idx < 32 * 240; idx += 512) {
        const int t = idx % 12, s0 = (idx / 12) % 20, ch = idx / 240;
        const int gr = min(max(h0 - 2 + s0, 0), 63);
        const int gc = min(max(w0 - 2 + t, 0), 63);
        xt1[(s0 * 12 + t) * 36 + ch] = xb[ch * 4096 + gr * 64 + gc];
    }
    for (int idx = tid; idx < 32 * 308; idx += 512) {
        const int t = idx % 14, s0 = (idx / 14) % 22, ch = idx / 308;
        const int gr = min(max(h0 - 3 + s0, 0), 63);
        const int gc = min(max(w0 - 3 + t, 0), 63);
        xt2[(s0 * 14 + t) * 36 + ch] = xb[(32 + ch) * 4096 + gr * 64 + gc];
    }
    for (int idx = tid; idx < 1024; idx += 512) buf[idx] = g_wq[idx];
    if (tid < 32) qbs[tid] = g_qb[tid];
    if (tid < 74) pbs[tid] = proj_b[tid];
    for (int idx = tid; idx < 324; idx += 512) r1s[idx] = rpb1[idx];
    for (int idx = tid; idx < 676; idx += 512) r2s[idx] = rpb2[idx];
    for (int idx = tid; idx < 4096; idx += 512) dyws[idx] = g_dyw[idx];
    if (tid < 64) dybs[tid] = g_dyb[tid];
    __syncthreads();

    const int p = tid & 127;
    const int g = tid >> 7;
    const int ph = p >> 3, pwd = p & 7;
    const int h = h0 + ph, w = w0 + pwd;

    // ---- q (8 channels of this head) from xt1 ----
    u64 qp[4];
    {
        const float* xpix = xt1 + ((ph + 2) * 12 + (pwd + 2)) * 36;
        const float* wrow = buf + g * 8 * 32;
        u64 acc[8];
        #pragma unroll
        for (int c = 0; c < 8; c++) acc[c] = 0ull;
        #pragma unroll
        for (int i4 = 0; i4 < 8; i4++) {
            const ulonglong2 xv = *(const ulonglong2*)(xpix + i4 * 4);
            #pragma unroll
            for (int c = 0; c < 8; c++) {
                const ulonglong2 wv =
                    *(const ulonglong2*)(wrow + c * 32 + i4 * 4);
                acc[c] = ffma2(xv.x, wv.x, acc[c]);
                acc[c] = ffma2(xv.y, wv.y, acc[c]);
            }
        }
        float q[8];
        #pragma unroll
        for (int c = 0; c < 8; c++) {
            const float2 f = unpack2(acc[c]);
            q[c] = qbs[g * 8 + c] + f.x + f.y;
        }
        #pragma unroll
        for (int j = 0; j < 4; j++) qp[j] = pack2(q[2 * j], q[2 * j + 1]);
    }
    __syncthreads();   // q done -> buf can be overwritten

    // ---- stage kproj into buf ----
    for (int idx = tid; idx < 2368; idx += 512)
        buf[idx] = g_kproj[(size_t)b * 2368 + idx];
    __syncthreads();

    const int ihr = 63 - h, iwr = 63 - w;
    const float* kbase = buf + g * 74 * 8;

    // ===== part 1: 5x5 fused =====
    float o1[8];
    {
        const int ih1 = min(ihr, 2) + max(0, ihr - 61);
        const int iw1 = min(iwr, 2) + max(0, iwr - 61);
        const float* r1g = r1s + g * 81 + ih1 * 9 + iw1;
        const int si = min(max(h - 2, 0), 59) - (h0 - 2);
        const int sj = min(max(w - 2, 0), 59) - (w0 - 2);

        u64 c0 = 0ull, c1 = 0ull, c2 = 0ull, c3 = 0ull;
        float sum = 0.f;
        #pragma unroll
        for (int ki = 0; ki < 5; ki++) {
            const float* row = xt1 + ((si + ki) * 12 + sj) * 36 + g * 8;
            #pragma unroll
            for (int kj = 0; kj < 5; kj++) {
                const int o = ki * 5 + kj;
                const float* kr = kbase + o * 8;
                const ulonglong2 k0 = *(const ulonglong2*)kr;
                const ulonglong2 k1 = *(const ulonglong2*)(kr + 4);
                const u64 a0 = ffma2(qp[0], k0.x, ffma2(qp[1], k0.y, 0ull));
                const u64 a1 = ffma2(qp[2], k1.x, ffma2(qp[3], k1.y, 0ull));
                const float2 f = unpack2(fadd2(a0, a1));
                const float v = f.x + f.y + pbs[o] + r1g[ki * 9 + kj];
                const float e = __expf(v);
                sum += e;
                const u64 ee = pack2(e, e);
                const ulonglong2 v0 = *(const ulonglong2*)(row + kj * 36);
                const ulonglong2 v1 = *(const ulonglong2*)(row + kj * 36 + 4);
                c0 = ffma2(ee, v0.x, c0);
                c1 = ffma2(ee, v0.y, c1);
                c2 = ffma2(ee, v1.x, c2);
                c3 = ffma2(ee, v1.y, c3);
            }
        }
        const float inv = 1.0f / sum;
        float2 f;
        f = unpack2(c0); o1[0] = f.x * inv; o1[1] = f.y * inv;
        f = unpack2(c1); o1[2] = f.x * inv; o1[3] = f.y * inv;
        f = unpack2(c2); o1[4] = f.x * inv; o1[5] = f.y * inv;
        f = unpack2(c3); o1[6] = f.x * inv; o1[7] = f.y * inv;
    }

    __syncthreads();   // all xt1 reads done -> obs alias valid

    // store o1 into obs with group-rotation swizzle (rows of 64, groups of 4)
    {
        const int c4a = 2 * g, c4b = 2 * g + 1;
        *(float4*)(obs + p * 64 + ((c4a + p) & 15) * 4) =
            make_float4(o1[0], o1[1], o1[2], o1[3]);
        *(float4*)(obs + p * 64 + ((c4b + p) & 15) * 4) =
            make_float4(o1[4], o1[5], o1[6], o1[7]);
    }

    // ===== part 2: 7x7 fused =====
    {
        const int ih2 = min(ihr, 3) + max(0, ihr - 60);
        const int iw2 = min(iwr, 3) + max(0, iwr - 60);
        const float* r2g = r2s + g * 169 + ih2 * 13 + iw2;
        const int si = min(max(h - 3, 0), 57) - (h0 - 3);
        const int sj = min(max(w - 3, 0), 57) - (w0 - 3);

        u64 c0 = 0ull, c1 = 0ull, c2 = 0ull, c3 = 0ull;
        float sum = 0.f;
        #pragma unroll
        for (int ki = 0; ki < 7; ki++) {
            const float* row = xt2 + ((si + ki) * 14 + sj) * 36 + g * 8;
            #pragma unroll
            for (int kj = 0; kj < 7; kj++) {
                const int o = 25 + ki * 7 + kj;
                const float* kr = kbase + o * 8;
                const ulonglong2 k0 = *(const ulonglong2*)kr;
                const ulonglong2 k1 = *(const ulonglong2*)(kr + 4);
                const u64 a0 = ffma2(qp[0], k0.x, ffma2(qp[1], k0.y, 0ull));
                const u64 a1 = ffma2(qp[2], k1.x, ffma2(qp[3], k1.y, 0ull));
                const float2 f = unpack2(fadd2(a0, a1));
                const float v = f.x + f.y + pbs[o] + r2g[ki * 13 + kj];
                const float e = __expf(v);
                sum += e;
                const u64 ee = pack2(e, e);
                const ulonglong2 v0 = *(const ulonglong2*)(row + kj * 36);
                const ulonglong2 v1 = *(const ulonglong2*)(row + kj * 36 + 4);
                c0 = ffma2(ee, v0.x, c0);
                c1 = ffma2(ee, v0.y, c1);
                c2 = ffma2(ee, v1.x, c2);
                c3 = ffma2(ee, v1.y, c3);
            }
        }
        const float inv = 1.0f / sum;
        const int c4a = 8 + 2 * g, c4b = 9 + 2 * g;
        float2 f0 = unpack2(c0), f1 = unpack2(c1);
        float2 f2 = unpack2(c2), f3 = unpack2(c3);
        *(float4*)(obs + p * 64 + ((c4a + p) & 15) * 4) =
            make_float4(f0.x * inv, f0.y * inv, f1.x * inv, f1.y * inv);
        *(float4*)(obs + p * 64 + ((c4b + p) & 15) * 4) =
            make_float4(f2.x * inv, f2.y * inv, f3.x * inv, f3.y * inv);
    }
    __syncthreads();

    // ===== dy conv + BN: thread (p, r) -> channels r, r+4, ..., r+60 =====
    {
        const int r = g;
        u64 acc[16];
        #pragma unroll
        for (int j = 0; j < 16; j++) acc[j] = 0ull;
        #pragma unroll
        for (int c4 = 0; c4 < 16; c4++) {
            const ulonglong2 xv =
                *(const ulonglong2*)(obs + p * 64 + ((c4 + p) & 15) * 4);
            #pragma unroll
            for (int j = 0; j < 16; j++) {
                const ulonglong2 wv =
                    *(const ulonglong2*)(dyws + (r + 4 * j) * 64 + c4 * 4);
                acc[j] = ffma2(xv.x, wv.x, acc[j]);
                acc[j] = ffma2(xv.y, wv.y, acc[j]);
            }
        }
        float* outp = out + (size_t)b * 262144 + h * 64 + w;
        #pragma unroll
        for (int j = 0; j < 16; j++) {
            const float2 f = unpack2(acc[j]);
            outp[(size_t)(r + 4 * j) * 4096] = f.x + f.y + dybs[r + 4 * j];
        }
    }
}

// ---------------------------------------------------------------------------
extern "C" void kernel_launch(void* const* d_in, const int* in_sizes, int n_in,
                              void* d_out, int out_size)
{
    const float* x      = (const float*)d_in[0];
    const float* wq_w   = (const float*)d_in[1];
    const float* wq_g   = (const float*)d_in[2];
    const float* wq_b   = (const float*)d_in[3];
    const float* wq_m   = (const float*)d_in[4];
    const float* wq_v   = (const float*)d_in[5];
    const float* wk_w   = (const float*)d_in[6];
    const float* wk_g   = (const float*)d_in[7];
    const float* wk_b   = (const float*)d_in[8];
    const float* wk_m   = (const float*)d_in[9];
    const float* wk_v   = (const float*)d_in[10];
    const float* proj_w = (const float*)d_in[11];
    const float* proj_b = (const float*)d_in[12];
    const float* rpb1   = (const float*)d_in[13];
    const float* rpb2   = (const float*)d_in[14];
    const float* dy_w   = (const float*)d_in[15];
    const float* dy_g   = (const float*)d_in[16];
    const float* dy_b   = (const float*)d_in[17];
    const float* dy_m   = (const float*)d_in[18];
    const float* dy_v   = (const float*)d_in[19];
    float* out = (float*)d_out;

    cudaFuncSetAttribute(m_kernel, cudaFuncAttributeMaxDynamicSharedMemorySize,
                         M_TOT * (int)sizeof(float));

    pool_kernel<<<256, 256>>>(x);
    kc_kernel<<<8, 256>>>(wk_w, wk_g, wk_b, wk_m, wk_v, proj_w,
                          wq_w, wq_g, wq_b, wq_m, wq_v,
                          dy_w, dy_g, dy_b, dy_m, dy_v);

    dim3 gm(8, 4, 8);
    m_kernel<<<gm, 512, M_TOT * (int)sizeof(float)>>>(
        x, proj_b, rpb1, rpb2, out);
}

// round 8
// speedup vs baseline: 2.7980x; 1.0247x over previous
#include <cuda_runtime.h>

#define EPSF 1e-5f

typedef unsigned long long u64;

__device__ __forceinline__ u64 ffma2(u64 a, u64 b, u64 c) {
    u64 d;
    asm("fma.rn.f32x2 %0, %1, %2, %3;" : "=l"(d) : "l"(a), "l"(b), "l"(c));
    return d;
}
__device__ __forceinline__ u64 fadd2(u64 a, u64 b) {
    u64 d;
    asm("add.rn.f32x2 %0, %1, %2;" : "=l"(d) : "l"(a), "l"(b));
    return d;
}
__device__ __forceinline__ u64 pack2(float lo, float hi) {
    u64 d;
    asm("mov.b64 %0, {%1, %2};" : "=l"(d) : "f"(lo), "f"(hi));
    return d;
}
__device__ __forceinline__ float2 unpack2(u64 a) {
    float2 r;
    asm("mov.b64 {%0, %1}, %2;" : "=f"(r.x), "=f"(r.y) : "l"(a));
    return r;
}

// pair-row -> o mapping (38 rows per head; -1 = pad lane)
// rows 0..9:  part1 in-row pairs  (ki=row/2, kj=2*(row%2)+par)
// rows 10..12: part1 kj=4 singles paired across ki (pad at row12,par1)
// rows 13..33: part2 in-row pairs (ki=(row-13)/3, kj=2*((row-13)%3)+par)
// rows 34..37: part2 kj=6 singles paired across ki (pad at row37,par1)
__host__ __device__ __forceinline__ int omap(int row, int par) {
    if (row < 10) { int ki = row >> 1, j = row & 1; return ki * 5 + 2 * j + par; }
    if (row < 13) { int sp = row - 10; int ki = 2 * sp + par;
                    return (sp == 2 && par == 1) ? -1 : (ki * 5 + 4); }
    if (row < 34) { int r2 = row - 13; int ki = r2 / 3, j = r2 % 3;
                    return 25 + ki * 7 + 2 * j + par; }
    int sp = row - 34; int ki = 2 * sp + par;
    return (sp == 3 && par == 1) ? -1 : (25 + ki * 7 + 6);
}

// ---------------------------------------------------------------------------
// device scratch (static allocation only)
// ---------------------------------------------------------------------------
__device__ float g_kp[8 * 32 * 49];         // pooled context [b][ci][pos]
__device__ float g_kpp[8 * 4 * 38 * 16];    // pair-interleaved proj-keys
__device__ float g_wq[32 * 32];             // BN+SCALE folded q weights
__device__ float g_qb[32];
__device__ float g_dyw[64 * 64];            // BN folded dy weights
__device__ float g_dyb[64];

// ---------------------------------------------------------------------------
// Kernel P: adaptive pool 64x64 -> 7x7, one block per (batch, channel)
// ---------------------------------------------------------------------------
__global__ void __launch_bounds__(512)
pool_kernel(const float* __restrict__ x)
{
    __shared__ float ch[4096];
    __shared__ float rp[64 * 7];

    const int b  = blockIdx.x >> 5;
    const int ci = blockIdx.x & 31;
    const int tid = threadIdx.x;

    const float4* src = (const float4*)(x + ((size_t)b * 64 + 32 + ci) * 4096);
    float4* dst = (float4*)ch;
    #pragma unroll
    for (int j = 0; j < 2; j++)
        dst[tid + 512 * j] = src[tid + 512 * j];
    __syncthreads();

    if (tid < 448) {
        const int r = tid / 7, q = tid % 7;
        const int sw = (q * 64) / 7;
        const int ew = ((q + 1) * 64 + 6) / 7;
        float acc = 0.f;
        for (int v = sw; v < ew; v++) acc += ch[r * 64 + v];
        rp[tid] = acc;
    }
    __syncthreads();

    if (tid < 49) {
        const int p = tid / 7, q = tid % 7;
        const int sh = (p * 64) / 7;
        const int eh = ((p + 1) * 64 + 6) / 7;
        const int sw = (q * 64) / 7;
        const int ew = ((q + 1) * 64 + 6) / 7;
        float acc = 0.f;
        for (int r = sh; r < eh; r++) acc += rp[r * 7 + q];
        g_kp[((size_t)b * 32 + ci) * 49 + tid] =
            acc / (float)((eh - sh) * (ew - sw));
    }
}

// ---------------------------------------------------------------------------
// Kernel KC: fused (k conv+BN) -> paired kproj, one block per batch.
// Block 0 also folds wq / dy weights.
// ---------------------------------------------------------------------------
__global__ void __launch_bounds__(256)
kc_kernel(const float* __restrict__ wk_w,
          const float* __restrict__ wk_g,
          const float* __restrict__ wk_b,
          const float* __restrict__ wk_m,
          const float* __restrict__ wk_v,
          const float* __restrict__ proj_w,
          const float* __restrict__ wq_w,
          const float* __restrict__ wq_g,
          const float* __restrict__ wq_b,
          const float* __restrict__ wq_m,
          const float* __restrict__ wq_v,
          const float* __restrict__ dy_w,
          const float* __restrict__ dy_g,
          const float* __restrict__ dy_b,
          const float* __restrict__ dy_m,
          const float* __restrict__ dy_v)
{
    __shared__ float kpin[1568];
    __shared__ float kt[1568];
    __shared__ float pws[74 * 49];

    const int b = blockIdx.x;
    const int tid = threadIdx.x;

    if (b == 0) {
        for (int idx = tid; idx < 1024; idx += 256) {
            const int o = idx >> 5, i = idx & 31;
            const float alpha = wq_g[o] * rsqrtf(wq_v[o] + EPSF) * 0.25f;
            g_wq[idx] = alpha * wq_w[idx];
            if (i == 0) g_qb[o] = 0.25f * wq_b[o] - wq_m[o] * alpha;
        }
        for (int idx = tid; idx < 4096; idx += 256) {
            const int o = idx >> 6;
            const float alpha = dy_g[o] * rsqrtf(dy_v[o] + EPSF);
            g_dyw[idx] = alpha * dy_w[idx];
            if ((idx & 63) == 0) g_dyb[o] = dy_b[o] - dy_m[o] * alpha;
        }
    }

    for (int idx = tid; idx < 1568; idx += 256)
        kpin[idx] = g_kp[(size_t)b * 1568 + idx];
    for (int idx = tid; idx < 74 * 49; idx += 256) pws[idx] = proj_w[idx];
    __syncthreads();

    for (int idx = tid; idx < 1568; idx += 256) {
        const int o = idx / 49, pos = idx % 49;
        const float alpha = wk_g[o] * rsqrtf(wk_v[o] + EPSF);
        const float beta  = wk_b[o] - wk_m[o] * alpha;
        float acc = 0.f;
        #pragma unroll
        for (int i = 0; i < 32; i++)
            acc += wk_w[o * 32 + i] * kpin[i * 49 + pos];
        kt[(((o >> 3) * 49) + pos) * 8 + (o & 7)] = alpha * acc + beta;
    }
    __syncthreads();

    // paired kproj: g_kpp[b][g][row 38][c 8][par 2]
    for (int idx = tid; idx < 2432; idx += 256) {
        const int g = idx / 608;
        const int r16 = idx % 608;
        const int row = r16 >> 4;
        const int c = (r16 & 15) >> 1;
        const int par = r16 & 1;
        const int o = omap(row, par);
        float acc = 0.f;
        if (o >= 0) {
            #pragma unroll
            for (int l = 0; l < 49; l++)
                acc += pws[o * 49 + l] * kt[(g * 49 + l) * 8 + c];
        }
        g_kpp[(size_t)b * 2432 + idx] = acc;
    }
}

// ---------------------------------------------------------------------------
// Kernel M: fully fused main kernel.  512 threads, 16x8 tile, 2 CTAs/SM.
// ---------------------------------------------------------------------------
constexpr int M_XT1 = 0;        // 20*12*36 = 8640 ; scr/obs2 alias here later
constexpr int M_XT2 = 8640;     // 22*14*36 = 11088
constexpr int M_BUF = 19728;    // 2432: wq (first 1024) then kpp
constexpr int M_QB  = 22160;    // 32
constexpr int M_PBP = 22192;    // 76 (38 u64, 8B aligned)
constexpr int M_R1  = 22268;    // 324
constexpr int M_R2  = 22592;    // 676
constexpr int M_DYW = 23268;    // 4096
constexpr int M_DYB = 27364;    // 64
constexpr int M_TOT = 27428;    // floats -> 109712 B (x2 = 219424)

__global__ void __launch_bounds__(512, 2)
m_kernel(const float* __restrict__ x,
         const float* __restrict__ proj_b,
         const float* __restrict__ rpb1, const float* __restrict__ rpb2,
         float* __restrict__ out)
{
    extern __shared__ float sm[];
    float* xt1 = sm + M_XT1;
    float* xt2 = sm + M_XT2;
    float* buf = sm + M_BUF;
    float* qbs = sm + M_QB;
    float* pbp = sm + M_PBP;
    float* r1s = sm + M_R1;
    float* r2s = sm + M_R2;
    float* dyws = sm + M_DYW;
    float* dybs = sm + M_DYB;
    float* scr  = sm + M_XT1;          // part1 results, alias (after barrier)
    float* obs2 = sm + M_XT1 + 4096;   // part2 results, alias

    const int tid = threadIdx.x;
    const int b  = blockIdx.z;
    const int h0 = blockIdx.y * 16;
    const int w0 = blockIdx.x * 8;
    const float* xb = x + (size_t)b * 64 * 4096;

    // ---- stage ----
    for (int idx = tid; idx < 32 * 240; idx += 512) {
        const int t = idx % 12, s0 = (idx / 12) % 20, ch = idx / 240;
        const int gr = min(max(h0 - 2 + s0, 0), 63);
        const int gc = min(max(w0 - 2 + t, 0), 63);
        xt1[(s0 * 12 + t) * 36 + ch] = xb[ch * 4096 + gr * 64 + gc];
    }
    for (int idx = tid; idx < 32 * 308; idx += 512) {
        const int t = idx % 14, s0 = (idx / 14) % 22, ch = idx / 308;
        const int gr = min(max(h0 - 3 + s0, 0), 63);
        const int gc = min(max(w0 - 3 + t, 0), 63);
        xt2[(s0 * 14 + t) * 36 + ch] = xb[(32 + ch) * 4096 + gr * 64 + gc];
    }
    for (int idx = tid; idx < 1024; idx += 512) buf[idx] = g_wq[idx];
    if (tid < 32) qbs[tid] = g_qb[tid];
    if (tid < 38) {
        const int o0 = omap(tid, 0), o1 = omap(tid, 1);
        pbp[2 * tid] = proj_b[o0];
        pbp[2 * tid + 1] = (o1 >= 0) ? proj_b[o1] : -1e30f;
    }
    for (int idx = tid; idx < 324; idx += 512) r1s[idx] = rpb1[idx];
    for (int idx = tid; idx < 676; idx += 512) r2s[idx] = rpb2[idx];
    for (int idx = tid; idx < 4096; idx += 512) dyws[idx] = g_dyw[idx];
    if (tid < 64) dybs[tid] = g_dyb[tid];
    __syncthreads();

    const int p = tid & 127;
    const int g = tid >> 7;
    const int ph = p >> 3, pwd = p & 7;
    const int h = h0 + ph, w = w0 + pwd;

    // ---- q (8 channels of this head) from xt1; pack qq[c]=(q[c],q[c]) ----
    u64 qq[8];
    {
        const float* xpix = xt1 + ((ph + 2) * 12 + (pwd + 2)) * 36;
        const float* wrow = buf + g * 8 * 32;
        u64 acc[8];
        #pragma unroll
        for (int c = 0; c < 8; c++) acc[c] = 0ull;
        #pragma unroll
        for (int i4 = 0; i4 < 8; i4++) {
            const ulonglong2 xv = *(const ulonglong2*)(xpix + i4 * 4);
            #pragma unroll
            for (int c = 0; c < 8; c++) {
                const ulonglong2 wv =
                    *(const ulonglong2*)(wrow + c * 32 + i4 * 4);
                acc[c] = ffma2(xv.x, wv.x, acc[c]);
                acc[c] = ffma2(xv.y, wv.y, acc[c]);
            }
        }
        #pragma unroll
        for (int c = 0; c < 8; c++) {
            const float2 f = unpack2(acc[c]);
            const float qc = qbs[g * 8 + c] + f.x + f.y;
            qq[c] = pack2(qc, qc);
        }
    }
    __syncthreads();   // wq dead -> stage kpp into buf

    for (int idx = tid; idx < 2432; idx += 512)
        buf[idx] = g_kpp[(size_t)b * 2432 + idx];
    __syncthreads();

    const int ihr = 63 - h, iwr = 63 - w;
    const float* kb = buf + g * 608;
    const u64* pbpu = (const u64*)pbp;

    // paired logit dot: returns packed logits for (o0,o1) before bias
    #define PAIR_DOT(PR, ACCP) do {                                        \
        const float* kr_ = kb + (PR) * 16;                                 \
        const ulonglong2 kA_ = *(const ulonglong2*)kr_;                    \
        const ulonglong2 kB_ = *(const ulonglong2*)(kr_ + 4);              \
        const ulonglong2 kC_ = *(const ulonglong2*)(kr_ + 8);              \
        const ulonglong2 kD_ = *(const ulonglong2*)(kr_ + 12);             \
        u64 a0_ = ffma2(qq[0], kA_.x, 0ull);                               \
        u64 a1_ = ffma2(qq[1], kA_.y, 0ull);                               \
        a0_ = ffma2(qq[2], kB_.x, a0_);                                    \
        a1_ = ffma2(qq[3], kB_.y, a1_);                                    \
        a0_ = ffma2(qq[4], kC_.x, a0_);                                    \
        a1_ = ffma2(qq[5], kC_.y, a1_);                                    \
        a0_ = ffma2(qq[6], kD_.x, a0_);                                    \
        a1_ = ffma2(qq[7], kD_.y, a1_);                                    \
        ACCP = fadd2(a0_, a1_);                                            \
    } while (0)

    #define AGG(EE, ROWPTR) do {                                           \
        const ulonglong2 v0_ = *(const ulonglong2*)(ROWPTR);               \
        const ulonglong2 v1_ = *(const ulonglong2*)((ROWPTR) + 4);         \
        c0 = ffma2(EE, v0_.x, c0);                                         \
        c1 = ffma2(EE, v0_.y, c1);                                         \
        c2 = ffma2(EE, v1_.x, c2);                                         \
        c3 = ffma2(EE, v1_.y, c3);                                         \
    } while (0)

    // ===== part 1: 5x5 =====
    float o1v[8];
    {
        const int ih1 = min(ihr, 2) + max(0, ihr - 61);
        const int iw1 = min(iwr, 2) + max(0, iwr - 61);
        const float* r1g = r1s + g * 81 + ih1 * 9 + iw1;
        const int si = min(max(h - 2, 0), 59) - (h0 - 2);
        const int sj = min(max(w - 2, 0), 59) - (w0 - 2);

        u64 c0 = 0ull, c1 = 0ull, c2 = 0ull, c3 = 0ull;
        float sum = 0.f;
        #pragma unroll
        for (int ki = 0; ki < 5; ki++) {
            const float* row = xt1 + ((si + ki) * 12 + sj) * 36 + g * 8;
            #pragma unroll
            for (int j = 0; j < 2; j++) {
                const int pr = ki * 2 + j;
                u64 accp;
                PAIR_DOT(pr, accp);
                const u64 rp = pack2(r1g[ki * 9 + 2 * j],
                                     r1g[ki * 9 + 2 * j + 1]);
                const float2 f = unpack2(fadd2(accp, fadd2(pbpu[pr], rp)));
                const float e0 = __expf(f.x), e1 = __expf(f.y);
                sum += e0 + e1;
                AGG(pack2(e0, e0), row + (2 * j) * 36);
                AGG(pack2(e1, e1), row + (2 * j + 1) * 36);
            }
        }
        // kj=4 singles paired across rows: sp=0:(ki0,ki1) sp=1:(ki2,ki3) sp=2:(ki4,pad)
        #pragma unroll
        for (int sp = 0; sp < 3; sp++) {
            u64 accp;
            PAIR_DOT(10 + sp, accp);
            const float rb0 = r1g[(2 * sp) * 9 + 4];
            const float rb1 = (sp < 2) ? r1g[(2 * sp + 1) * 9 + 4] : 0.f;
            const float2 f = unpack2(fadd2(accp,
                                     fadd2(pbpu[10 + sp], pack2(rb0, rb1))));
            const float e0 = __expf(f.x), e1 = __expf(f.y);
            sum += e0 + e1;   // e1 == 0 exactly for sp==2 (bias -1e30)
            const float* rowA =
                xt1 + ((si + 2 * sp) * 12 + sj) * 36 + g * 8 + 4 * 36;
            AGG(pack2(e0, e0), rowA);
            if (sp < 2) {
                const float* rowB =
                    xt1 + ((si + 2 * sp + 1) * 12 + sj) * 36 + g * 8 + 4 * 36;
                AGG(pack2(e1, e1), rowB);
            }
        }
        const float inv = 1.0f / sum;
        float2 f;
        f = unpack2(c0); o1v[0] = f.x * inv; o1v[1] = f.y * inv;
        f = unpack2(c1); o1v[2] = f.x * inv; o1v[3] = f.y * inv;
        f = unpack2(c2); o1v[4] = f.x * inv; o1v[5] = f.y * inv;
        f = unpack2(c3); o1v[6] = f.x * inv; o1v[7] = f.y * inv;
    }
    __syncthreads();   // all xt1 reads done

    // store part1 results to scr (rows of 32, group-rotation swizzle mod 8)
    *(float4*)(scr + p * 32 + ((2 * g + p) & 7) * 4) =
        make_float4(o1v[0], o1v[1], o1v[2], o1v[3]);
    *(float4*)(scr + p * 32 + ((2 * g + 1 + p) & 7) * 4) =
        make_float4(o1v[4], o1v[5], o1v[6], o1v[7]);

    // ===== part 2: 7x7 =====
    {
        const int ih2 = min(ihr, 3) + max(0, ihr - 60);
        const int iw2 = min(iwr, 3) + max(0, iwr - 60);
        const float* r2g = r2s + g * 169 + ih2 * 13 + iw2;
        const int si = min(max(h - 3, 0), 57) - (h0 - 3);
        const int sj = min(max(w - 3, 0), 57) - (w0 - 3);

        u64 c0 = 0ull, c1 = 0ull, c2 = 0ull, c3 = 0ull;
        float sum = 0.f;
        #pragma unroll
        for (int ki = 0; ki < 7; ki++) {
            const float* row = xt2 + ((si + ki) * 14 + sj) * 36 + g * 8;
            #pragma unroll
            for (int j = 0; j < 3; j++) {
                const int pr = 13 + ki * 3 + j;
                u64 accp;
                PAIR_DOT(pr, accp);
                const u64 rp = pack2(r2g[ki * 13 + 2 * j],
                                     r2g[ki * 13 + 2 * j + 1]);
                const float2 f = unpack2(fadd2(accp, fadd2(pbpu[pr], rp)));
                const float e0 = __expf(f.x), e1 = __expf(f.y);
                sum += e0 + e1;
                AGG(pack2(e0, e0), row + (2 * j) * 36);
                AGG(pack2(e1, e1), row + (2 * j + 1) * 36);
            }
        }
        // kj=6 singles: sp=0..3 rows (ki 2sp, 2sp+1), pad at sp=3 lane1
        #pragma unroll
        for (int sp = 0; sp < 4; sp++) {
            u64 accp;
            PAIR_DOT(34 + sp, accp);
            const float rb0 = r2g[(2 * sp) * 13 + 6];
            const float rb1 = (sp < 3) ? r2g[(2 * sp + 1) * 13 + 6] : 0.f;
            const float2 f = unpack2(fadd2(accp,
                                     fadd2(pbpu[34 + sp], pack2(rb0, rb1))));
            const float e0 = __expf(f.x), e1 = __expf(f.y);
            sum += e0 + e1;
            const float* rowA =
                xt2 + ((si + 2 * sp) * 14 + sj) * 36 + g * 8 + 6 * 36;
            AGG(pack2(e0, e0), rowA);
            if (sp < 3) {
                const float* rowB =
                    xt2 + ((si + 2 * sp + 1) * 14 + sj) * 36 + g * 8 + 6 * 36;
                AGG(pack2(e1, e1), rowB);
            }
        }
        const float inv = 1.0f / sum;
        float2 f0 = unpack2(c0), f1 = unpack2(c1);
        float2 f2 = unpack2(c2), f3 = unpack2(c3);
        *(float4*)(obs2 + p * 32 + ((2 * g + p) & 7) * 4) =
            make_float4(f0.x * inv, f0.y * inv, f1.x * inv, f1.y * inv);
        *(float4*)(obs2 + p * 32 + ((2 * g + 1 + p) & 7) * 4) =
            make_float4(f2.x * inv, f2.y * inv, f3.x * inv, f3.y * inv);
    }
    __syncthreads();

    // ===== dy conv + BN: 2 pixels x 8 channels per thread =====
    {
        const int pp = tid & 63;        // pixels pp and pp+64
        const int cg = tid >> 6;        // output channels 8cg..8cg+7
        u64 acc[16];
        #pragma unroll
        for (int k = 0; k < 16; k++) acc[k] = 0ull;

        #pragma unroll
        for (int s = 0; s < 16; s++) {
            const float* sb = (s < 8) ? scr : obs2;
            const int lc = s & 7;
            const ulonglong2 xvA =
                *(const ulonglong2*)(sb + pp * 32 + ((lc + pp) & 7) * 4);
            const ulonglong2 xvB =
                *(const ulonglong2*)(sb + (pp + 64) * 32 + ((lc + pp + 64) & 7) * 4);
            #pragma unroll
            for (int k = 0; k < 8; k++) {
                const ulonglong2 wv =
                    *(const ulonglong2*)(dyws + (cg * 8 + k) * 64 + s * 4);
                acc[k]     = ffma2(xvA.x, wv.x, acc[k]);
                acc[k]     = ffma2(xvA.y, wv.y, acc[k]);
                acc[8 + k] = ffma2(xvB.x, wv.x, acc[8 + k]);
                acc[8 + k] = ffma2(xvB.y, wv.y, acc[8 + k]);
            }
        }
        const int hA = h0 + (pp >> 3), wA = w0 + (pp & 7);
        const int hB = h0 + ((pp + 64) >> 3), wB = w0 + (pp & 7);
        float* outA = out + (size_t)b * 262144 + hA * 64 + wA;
        float* outB = out + (size_t)b * 262144 + hB * 64 + wB;
        #pragma unroll
        for (int k = 0; k < 8; k++) {
            const int oc = cg * 8 + k;
            const float2 fA = unpack2(acc[k]);
            const float2 fB = unpack2(acc[8 + k]);
            outA[(size_t)oc * 4096] = fA.x + fA.y + dybs[oc];
            outB[(size_t)oc * 4096] = fB.x + fB.y + dybs[oc];
        }
    }
    #undef PAIR_DOT
    #undef AGG
}

// ---------------------------------------------------------------------------
extern "C" void kernel_launch(void* const* d_in, const int* in_sizes, int n_in,
                              void* d_out, int out_size)
{
    const float* x      = (const float*)d_in[0];
    const float* wq_w   = (const float*)d_in[1];
    const float* wq_g   = (const float*)d_in[2];
    const float* wq_b   = (const float*)d_in[3];
    const float* wq_m   = (const float*)d_in[4];
    const float* wq_v   = (const float*)d_in[5];
    const float* wk_w   = (const float*)d_in[6];
    const float* wk_g   = (const float*)d_in[7];
    const float* wk_b   = (const float*)d_in[8];
    const float* wk_m   = (const float*)d_in[9];
    const float* wk_v   = (const float*)d_in[10];
    const float* proj_w = (const float*)d_in[11];
    const float* proj_b = (const float*)d_in[12];
    const float* rpb1   = (const float*)d_in[13];
    const float* rpb2   = (const float*)d_in[14];
    const float* dy_w   = (const float*)d_in[15];
    const float* dy_g   = (const float*)d_in[16];
    const float* dy_b   = (const float*)d_in[17];
    const float* dy_m   = (const float*)d_in[18];
    const float* dy_v   = (const float*)d_in[19];
    float* out = (float*)d_out;

    cudaFuncSetAttribute(m_kernel, cudaFuncAttributeMaxDynamicSharedMemorySize,
                         M_TOT * (int)sizeof(float));

    pool_kernel<<<256, 512>>>(x);
    kc_kernel<<<8, 256>>>(wk_w, wk_g, wk_b, wk_m, wk_v, proj_w,
                          wq_w, wq_g, wq_b, wq_m, wq_v,
                          dy_w, dy_g, dy_b, dy_m, dy_v);

    dim3 gm(8, 4, 8);
    m_kernel<<<gm, 512, M_TOT * (int)sizeof(float)>>>(
        x, proj_b, rpb1, rpb2, out);
}

// round 9
// speedup vs baseline: 3.1818x; 1.1372x over previous
#include <cuda_runtime.h>

#define EPSF 1e-5f
#define LOG2E 1.4426950408889634f

typedef unsigned long long u64;

__device__ __forceinline__ u64 ffma2(u64 a, u64 b, u64 c) {
    u64 d;
    asm("fma.rn.f32x2 %0, %1, %2, %3;" : "=l"(d) : "l"(a), "l"(b), "l"(c));
    return d;
}
__device__ __forceinline__ u64 fadd2(u64 a, u64 b) {
    u64 d;
    asm("add.rn.f32x2 %0, %1, %2;" : "=l"(d) : "l"(a), "l"(b));
    return d;
}
__device__ __forceinline__ u64 pack2(float lo, float hi) {
    u64 d;
    asm("mov.b64 %0, {%1, %2};" : "=l"(d) : "f"(lo), "f"(hi));
    return d;
}
__device__ __forceinline__ float2 unpack2(u64 a) {
    float2 r;
    asm("mov.b64 {%0, %1}, %2;" : "=f"(r.x), "=f"(r.y) : "l"(a));
    return r;
}

// pair-row -> o mapping (38 rows per head; -1 = pad lane)
__host__ __device__ __forceinline__ int omap(int row, int par) {
    if (row < 10) { int ki = row >> 1, j = row & 1; return ki * 5 + 2 * j + par; }
    if (row < 13) { int sp = row - 10; int ki = 2 * sp + par;
                    return (sp == 2 && par == 1) ? -1 : (ki * 5 + 4); }
    if (row < 34) { int r2 = row - 13; int ki = r2 / 3, j = r2 % 3;
                    return 25 + ki * 7 + 2 * j + par; }
    int sp = row - 34; int ki = 2 * sp + par;
    return (sp == 3 && par == 1) ? -1 : (25 + ki * 7 + 6);
}

// ---------------------------------------------------------------------------
// device scratch (static allocation only)
// ---------------------------------------------------------------------------
__device__ float g_kp[8 * 32 * 49];         // pooled context [b][ci][pos]
__device__ float g_kpp[8 * 4 * 38 * 16];    // pair-interleaved proj-keys
__device__ unsigned int g_arrive;           // pool units done (target 256)
__device__ unsigned int g_ready;            // kc halves done (target 16)
__device__ unsigned int g_done;             // blocks finished (reset at 256)

// ---------------------------------------------------------------------------
// Shared memory layout (floats) -- identical budget to R8: 109712 B, 2 CTAs/SM
// ---------------------------------------------------------------------------
constexpr int M_XT1 = 0;        // 8640 ; pool scratch / scr / obs2 alias here
constexpr int M_XT2 = 8640;     // 11088
constexpr int M_BUF = 19728;    // 2432: wq(1024) -> kc kt(1568) -> kpp(2432)
constexpr int M_QB  = 22160;    // 32
constexpr int M_PBP = 22192;    // 76 (38 u64)
constexpr int M_R1  = 22268;    // 324
constexpr int M_R2  = 22592;    // 676
constexpr int M_DYW = 23268;    // 4096: pws(3626, kc blocks) -> folded dyw
constexpr int M_DYB = 27364;    // 64
constexpr int M_TOT = 27428;

__global__ void __launch_bounds__(512, 2)
mega_kernel(const float* __restrict__ x,
            const float* __restrict__ wq_w, const float* __restrict__ wq_g,
            const float* __restrict__ wq_b, const float* __restrict__ wq_m,
            const float* __restrict__ wq_v,
            const float* __restrict__ wk_w, const float* __restrict__ wk_g,
            const float* __restrict__ wk_b, const float* __restrict__ wk_m,
            const float* __restrict__ wk_v,
            const float* __restrict__ proj_w, const float* __restrict__ proj_b,
            const float* __restrict__ rpb1, const float* __restrict__ rpb2,
            const float* __restrict__ dy_w, const float* __restrict__ dy_g,
            const float* __restrict__ dy_b, const float* __restrict__ dy_m,
            const float* __restrict__ dy_v,
            float* __restrict__ out)
{
    extern __shared__ float sm[];
    float* xt1 = sm + M_XT1;
    float* xt2 = sm + M_XT2;
    float* buf = sm + M_BUF;
    float* qbs = sm + M_QB;
    float* pbp = sm + M_PBP;
    float* r1s = sm + M_R1;
    float* r2s = sm + M_R2;
    float* dyws = sm + M_DYW;
    float* dybs = sm + M_DYB;
    float* scr  = sm + M_XT1;          // part1 results alias
    float* obs2 = sm + M_XT1 + 4096;   // part2 results alias

    const int tid = threadIdx.x;
    const int b  = blockIdx.z;
    const int h0 = blockIdx.y * 16;
    const int w0 = blockIdx.x * 8;
    const int flat = (blockIdx.z * 4 + blockIdx.y) * 8 + blockIdx.x;  // 0..255
    const float* xb = x + (size_t)b * 64 * 4096;

    // ================= phase 0: pool one (batch, channel) unit =============
    {
        float* ch = xt1;            // 4096
        float* rp = xt1 + 4096;     // 448
        const int bp = flat >> 5;
        const int ci = flat & 31;
        const float4* src =
            (const float4*)(x + ((size_t)bp * 64 + 32 + ci) * 4096);
        float4* dst = (float4*)ch;
        dst[tid] = src[tid];
        dst[tid + 512] = src[tid + 512];
        __syncthreads();

        if (tid < 448) {
            const int r = tid / 7, q = tid % 7;
            const int sw = (q * 64) / 7;
            const int ew = ((q + 1) * 64 + 6) / 7;
            float acc = 0.f;
            for (int v = sw; v < ew; v++) acc += ch[r * 64 + v];
            rp[tid] = acc;
        }
        __syncthreads();

        if (tid < 49) {
            const int p = tid / 7, q = tid % 7;
            const int sh = (p * 64) / 7;
            const int eh = ((p + 1) * 64 + 6) / 7;
            const int sw = (q * 64) / 7;
            const int ew = ((q + 1) * 64 + 6) / 7;
            float acc = 0.f;
            for (int r = sh; r < eh; r++) acc += rp[r * 7 + q];
            g_kp[((size_t)bp * 32 + ci) * 49 + tid] =
                acc / (float)((eh - sh) * (ew - sw));
            __threadfence();
        }
        __syncthreads();
        if (tid == 0) atomicAdd(&g_arrive, 1u);
    }

    // ================= phase 1: staging (overwrites pool scratch) ==========
    for (int idx = tid; idx < 32 * 240; idx += 512) {
        const int t = idx % 12, s0 = (idx / 12) % 20, ch = idx / 240;
        const int gr = min(max(h0 - 2 + s0, 0), 63);
        const int gc = min(max(w0 - 2 + t, 0), 63);
        xt1[(s0 * 12 + t) * 36 + ch] = xb[ch * 4096 + gr * 64 + gc];
    }
    for (int idx = tid; idx < 32 * 308; idx += 512) {
        const int t = idx % 14, s0 = (idx / 14) % 22, ch = idx / 308;
        const int gr = min(max(h0 - 3 + s0, 0), 63);
        const int gc = min(max(w0 - 3 + t, 0), 63);
        xt2[(s0 * 14 + t) * 36 + ch] = xb[(32 + ch) * 4096 + gr * 64 + gc];
    }
    // wq fold (BN + SCALE + LOG2E) into buf
    for (int idx = tid; idx < 1024; idx += 512) {
        const int o = idx >> 5, i = idx & 31;
        const float alpha = wq_g[o] * rsqrtf(wq_v[o] + EPSF) * 0.25f * LOG2E;
        buf[idx] = alpha * wq_w[idx];
        if (i == 0)
            qbs[o] = 0.25f * LOG2E * wq_b[o] - wq_m[o] * alpha;
    }
    if (tid < 38) {
        const int o0 = omap(tid, 0), o1 = omap(tid, 1);
        pbp[2 * tid] = proj_b[o0] * LOG2E;
        pbp[2 * tid + 1] = (o1 >= 0) ? proj_b[o1] * LOG2E : -1e30f;
    }
    for (int idx = tid; idx < 324; idx += 512) r1s[idx] = rpb1[idx] * LOG2E;
    for (int idx = tid; idx < 676; idx += 512) r2s[idx] = rpb2[idx] * LOG2E;
    if (tid < 64) {
        const float alpha = dy_g[tid] * rsqrtf(dy_v[tid] + EPSF);
        dybs[tid] = dy_b[tid] - dy_m[tid] * alpha;
    }
    // kc blocks stage proj_w into the dyw region; others prefetch nothing extra
    if (flat < 16) {
        for (int idx = tid; idx < 74 * 49; idx += 512) dyws[idx] = proj_w[idx];
    }
    __syncthreads();

    const int p = tid & 127;
    const int g = tid >> 7;
    const int ph = p >> 3, pwd = p & 7;
    const int h = h0 + ph, w = w0 + pwd;

    // ================= phase 2: q (log2-scaled) =============================
    u64 qq[8];
    {
        const float* xpix = xt1 + ((ph + 2) * 12 + (pwd + 2)) * 36;
        const float* wrow = buf + g * 8 * 32;
        u64 acc[8];
        #pragma unroll
        for (int c = 0; c < 8; c++) acc[c] = 0ull;
        #pragma unroll
        for (int i4 = 0; i4 < 8; i4++) {
            const ulonglong2 xv = *(const ulonglong2*)(xpix + i4 * 4);
            #pragma unroll
            for (int c = 0; c < 8; c++) {
                const ulonglong2 wv =
                    *(const ulonglong2*)(wrow + c * 32 + i4 * 4);
                acc[c] = ffma2(xv.x, wv.x, acc[c]);
                acc[c] = ffma2(xv.y, wv.y, acc[c]);
            }
        }
        #pragma unroll
        for (int c = 0; c < 8; c++) {
            const float2 f = unpack2(acc[c]);
            const float qc = qbs[g * 8 + c] + f.x + f.y;
            qq[c] = pack2(qc, qc);
        }
    }
    __syncthreads();   // wq dead; buf free for kc / kpp

    // ================= phase 3: kc (blocks 0..15 only) ======================
    if (flat < 16) {
        const int bkc = flat >> 1;
        const int half = flat & 1;
        if (tid == 0) { while (atomicAdd(&g_arrive, 0u) < 256u) { } }
        __syncthreads();
        __threadfence();

        // k conv + BN: kt into buf [g][l][c]
        for (int idx = tid; idx < 1568; idx += 512) {
            const int o = idx / 49, pos = idx % 49;
            const float alpha = wk_g[o] * rsqrtf(wk_v[o] + EPSF);
            const float beta  = wk_b[o] - wk_m[o] * alpha;
            float acc = 0.f;
            #pragma unroll
            for (int i = 0; i < 32; i++)
                acc += wk_w[o * 32 + i] * g_kp[((size_t)bkc * 32 + i) * 49 + pos];
            buf[(((o >> 3) * 49) + pos) * 8 + (o & 7)] = alpha * acc + beta;
        }
        __syncthreads();

        // paired proj: half of g_kpp[bkc]
        for (int idx = half * 1216 + tid; idx < half * 1216 + 1216; idx += 512) {
            const int gg = idx / 608;
            const int r16 = idx % 608;
            const int row = r16 >> 4;
            const int c = (r16 & 15) >> 1;
            const int par = r16 & 1;
            const int o = omap(row, par);
            float acc = 0.f;
            if (o >= 0) {
                #pragma unroll
                for (int l = 0; l < 49; l++)
                    acc += dyws[o * 49 + l] * buf[(gg * 49 + l) * 8 + c];
            }
            g_kpp[(size_t)bkc * 2432 + idx] = acc;
        }
        __threadfence();
        __syncthreads();
        if (tid == 0) atomicAdd(&g_ready, 1u);
    }

    // ================= phase 4: wait for kpp; stage kpp + dyw ===============
    if (tid == 0) { while (atomicAdd(&g_ready, 0u) < 16u) { } }
    __syncthreads();
    __threadfence();

    for (int idx = tid; idx < 2432; idx += 512)
        buf[idx] = g_kpp[(size_t)b * 2432 + idx];
    for (int idx = tid; idx < 4096; idx += 512) {
        const int o = idx >> 6;
        const float alpha = dy_g[o] * rsqrtf(dy_v[o] + EPSF);
        dyws[idx] = alpha * dy_w[idx];
    }
    __syncthreads();

    const int ihr = 63 - h, iwr = 63 - w;
    const float* kb = buf + g * 608;
    const u64* pbpu = (const u64*)pbp;

    #define PAIR_DOT(PR, ACCP) do {                                        \
        const float* kr_ = kb + (PR) * 16;                                 \
        const ulonglong2 kA_ = *(const ulonglong2*)kr_;                    \
        const ulonglong2 kB_ = *(const ulonglong2*)(kr_ + 4);              \
        const ulonglong2 kC_ = *(const ulonglong2*)(kr_ + 8);              \
        const ulonglong2 kD_ = *(const ulonglong2*)(kr_ + 12);             \
        u64 a0_ = ffma2(qq[0], kA_.x, 0ull);                               \
        u64 a1_ = ffma2(qq[1], kA_.y, 0ull);                               \
        a0_ = ffma2(qq[2], kB_.x, a0_);                                    \
        a1_ = ffma2(qq[3], kB_.y, a1_);                                    \
        a0_ = ffma2(qq[4], kC_.x, a0_);                                    \
        a1_ = ffma2(qq[5], kC_.y, a1_);                                    \
        a0_ = ffma2(qq[6], kD_.x, a0_);                                    \
        a1_ = ffma2(qq[7], kD_.y, a1_);                                    \
        ACCP = fadd2(a0_, a1_);                                            \
    } while (0)

    #define AGG(EE, ROWPTR) do {                                           \
        const ulonglong2 v0_ = *(const ulonglong2*)(ROWPTR);               \
        const ulonglong2 v1_ = *(const ulonglong2*)((ROWPTR) + 4);         \
        c0 = ffma2(EE, v0_.x, c0);                                         \
        c1 = ffma2(EE, v0_.y, c1);                                         \
        c2 = ffma2(EE, v1_.x, c2);                                         \
        c3 = ffma2(EE, v1_.y, c3);                                         \
    } while (0)

    // ===== part 1: 5x5 =====
    float o1v[8];
    {
        const int ih1 = min(ihr, 2) + max(0, ihr - 61);
        const int iw1 = min(iwr, 2) + max(0, iwr - 61);
        const float* r1g = r1s + g * 81 + ih1 * 9 + iw1;
        const int si = min(max(h - 2, 0), 59) - (h0 - 2);
        const int sj = min(max(w - 2, 0), 59) - (w0 - 2);

        u64 c0 = 0ull, c1 = 0ull, c2 = 0ull, c3 = 0ull;
        float sum = 0.f;
        #pragma unroll
        for (int ki = 0; ki < 5; ki++) {
            const float* row = xt1 + ((si + ki) * 12 + sj) * 36 + g * 8;
            #pragma unroll
            for (int j = 0; j < 2; j++) {
                const int pr = ki * 2 + j;
                u64 accp;
                PAIR_DOT(pr, accp);
                const u64 rp = pack2(r1g[ki * 9 + 2 * j],
                                     r1g[ki * 9 + 2 * j + 1]);
                const float2 f = unpack2(fadd2(accp, fadd2(pbpu[pr], rp)));
                const float e0 = exp2f(f.x), e1 = exp2f(f.y);
                sum += e0 + e1;
                AGG(pack2(e0, e0), row + (2 * j) * 36);
                AGG(pack2(e1, e1), row + (2 * j + 1) * 36);
            }
        }
        #pragma unroll
        for (int sp = 0; sp < 3; sp++) {
            u64 accp;
            PAIR_DOT(10 + sp, accp);
            const float rb0 = r1g[(2 * sp) * 9 + 4];
            const float rb1 = (sp < 2) ? r1g[(2 * sp + 1) * 9 + 4] : 0.f;
            const float2 f = unpack2(fadd2(accp,
                                     fadd2(pbpu[10 + sp], pack2(rb0, rb1))));
            const float e0 = exp2f(f.x), e1 = exp2f(f.y);
            sum += e0 + e1;   // e1 == 0 exactly for sp==2 (bias -1e30)
            const float* rowA =
                xt1 + ((si + 2 * sp) * 12 + sj) * 36 + g * 8 + 4 * 36;
            AGG(pack2(e0, e0), rowA);
            if (sp < 2) {
                const float* rowB =
                    xt1 + ((si + 2 * sp + 1) * 12 + sj) * 36 + g * 8 + 4 * 36;
                AGG(pack2(e1, e1), rowB);
            }
        }
        const float inv = 1.0f / sum;
        float2 f;
        f = unpack2(c0); o1v[0] = f.x * inv; o1v[1] = f.y * inv;
        f = unpack2(c1); o1v[2] = f.x * inv; o1v[3] = f.y * inv;
        f = unpack2(c2); o1v[4] = f.x * inv; o1v[5] = f.y * inv;
        f = unpack2(c3); o1v[6] = f.x * inv; o1v[7] = f.y * inv;
    }
    __syncthreads();   // all xt1 reads done

    *(float4*)(scr + p * 32 + ((2 * g + p) & 7) * 4) =
        make_float4(o1v[0], o1v[1], o1v[2], o1v[3]);
    *(float4*)(scr + p * 32 + ((2 * g + 1 + p) & 7) * 4) =
        make_float4(o1v[4], o1v[5], o1v[6], o1v[7]);

    // ===== part 2: 7x7 =====
    {
        const int ih2 = min(ihr, 3) + max(0, ihr - 60);
        const int iw2 = min(iwr, 3) + max(0, iwr - 60);
        const float* r2g = r2s + g * 169 + ih2 * 13 + iw2;
        const int si = min(max(h - 3, 0), 57) - (h0 - 3);
        const int sj = min(max(w - 3, 0), 57) - (w0 - 3);

        u64 c0 = 0ull, c1 = 0ull, c2 = 0ull, c3 = 0ull;
        float sum = 0.f;
        #pragma unroll
        for (int ki = 0; ki < 7; ki++) {
            const float* row = xt2 + ((si + ki) * 14 + sj) * 36 + g * 8;
            #pragma unroll
            for (int j = 0; j < 3; j++) {
                const int pr = 13 + ki * 3 + j;
                u64 accp;
                PAIR_DOT(pr, accp);
                const u64 rp = pack2(r2g[ki * 13 + 2 * j],
                                     r2g[ki * 13 + 2 * j + 1]);
                const float2 f = unpack2(fadd2(accp, fadd2(pbpu[pr], rp)));
                const float e0 = exp2f(f.x), e1 = exp2f(f.y);
                sum += e0 + e1;
                AGG(pack2(e0, e0), row + (2 * j) * 36);
                AGG(pack2(e1, e1), row + (2 * j + 1) * 36);
            }
        }
        #pragma unroll
        for (int sp = 0; sp < 4; sp++) {
            u64 accp;
            PAIR_DOT(34 + sp, accp);
            const float rb0 = r2g[(2 * sp) * 13 + 6];
            const float rb1 = (sp < 3) ? r2g[(2 * sp + 1) * 13 + 6] : 0.f;
            const float2 f = unpack2(fadd2(accp,
                                     fadd2(pbpu[34 + sp], pack2(rb0, rb1))));
            const float e0 = exp2f(f.x), e1 = exp2f(f.y);
            sum += e0 + e1;
            const float* rowA =
                xt2 + ((si + 2 * sp) * 14 + sj) * 36 + g * 8 + 6 * 36;
            AGG(pack2(e0, e0), rowA);
            if (sp < 3) {
                const float* rowB =
                    xt2 + ((si + 2 * sp + 1) * 14 + sj) * 36 + g * 8 + 6 * 36;
                AGG(pack2(e1, e1), rowB);
            }
        }
        const float inv = 1.0f / sum;
        float2 f0 = unpack2(c0), f1 = unpack2(c1);
        float2 f2 = unpack2(c2), f3 = unpack2(c3);
        *(float4*)(obs2 + p * 32 + ((2 * g + p) & 7) * 4) =
            make_float4(f0.x * inv, f0.y * inv, f1.x * inv, f1.y * inv);
        *(float4*)(obs2 + p * 32 + ((2 * g + 1 + p) & 7) * 4) =
            make_float4(f2.x * inv, f2.y * inv, f3.x * inv, f3.y * inv);
    }
    __syncthreads();

    // ===== dy conv + BN: 2 pixels x 8 channels per thread =====
    {
        const int pp = tid & 63;
        const int cg = tid >> 6;
        u64 acc[16];
        #pragma unroll
        for (int k = 0; k < 16; k++) acc[k] = 0ull;

        #pragma unroll
        for (int s = 0; s < 16; s++) {
            const float* sb = (s < 8) ? scr : obs2;
            const int lc = s & 7;
            const ulonglong2 xvA =
                *(const ulonglong2*)(sb + pp * 32 + ((lc + pp) & 7) * 4);
            const ulonglong2 xvB =
                *(const ulonglong2*)(sb + (pp + 64) * 32 + ((lc + pp + 64) & 7) * 4);
            #pragma unroll
            for (int k = 0; k < 8; k++) {
                const ulonglong2 wv =
                    *(const ulonglong2*)(dyws + (cg * 8 + k) * 64 + s * 4);
                acc[k]     = ffma2(xvA.x, wv.x, acc[k]);
                acc[k]     = ffma2(xvA.y, wv.y, acc[k]);
                acc[8 + k] = ffma2(xvB.x, wv.x, acc[8 + k]);
                acc[8 + k] = ffma2(xvB.y, wv.y, acc[8 + k]);
            }
        }
        const int hA = h0 + (pp >> 3), wA = w0 + (pp & 7);
        const int hB = h0 + ((pp + 64) >> 3), wB = w0 + (pp & 7);
        float* outA = out + (size_t)b * 262144 + hA * 64 + wA;
        float* outB = out + (size_t)b * 262144 + hB * 64 + wB;
        #pragma unroll
        for (int k = 0; k < 8; k++) {
            const int oc = cg * 8 + k;
            const float2 fA = unpack2(acc[k]);
            const float2 fB = unpack2(acc[8 + k]);
            outA[(size_t)oc * 4096] = fA.x + fA.y + dybs[oc];
            outB[(size_t)oc * 4096] = fB.x + fB.y + dybs[oc];
        }
    }
    #undef PAIR_DOT
    #undef AGG

    // ================= phase 6: counter reset (graph-replay safe) ==========
    __syncthreads();
    if (tid == 0) {
        const unsigned old = atomicAdd(&g_done, 1u);
        if (old == 255u) {
            atomicExch(&g_arrive, 0u);
            atomicExch(&g_ready, 0u);
            atomicExch(&g_done, 0u);
        }
    }
}

// ---------------------------------------------------------------------------
extern "C" void kernel_launch(void* const* d_in, const int* in_sizes, int n_in,
                              void* d_out, int out_size)
{
    const float* x      = (const float*)d_in[0];
    const float* wq_w   = (const float*)d_in[1];
    const float* wq_g   = (const float*)d_in[2];
    const float* wq_b   = (const float*)d_in[3];
    const float* wq_m   = (const float*)d_in[4];
    const float* wq_v   = (const float*)d_in[5];
    const float* wk_w   = (const float*)d_in[6];
    const float* wk_g   = (const float*)d_in[7];
    const float* wk_b   = (const float*)d_in[8];
    const float* wk_m   = (const float*)d_in[9];
    const float* wk_v   = (const float*)d_in[10];
    const float* proj_w = (const float*)d_in[11];
    const float* proj_b = (const float*)d_in[12];
    const float* rpb1   = (const float*)d_in[13];
    const float* rpb2   = (const float*)d_in[14];
    const float* dy_w   = (const float*)d_in[15];
    const float* dy_g   = (const float*)d_in[16];
    const float* dy_b   = (const float*)d_in[17];
    const float* dy_m   = (const float*)d_in[18];
    const float* dy_v   = (const float*)d_in[19];
    float* out = (float*)d_out;

    cudaFuncSetAttribute(mega_kernel,
                         cudaFuncAttributeMaxDynamicSharedMemorySize,
                         M_TOT * (int)sizeof(float));

    dim3 gm(8, 4, 8);
    mega_kernel<<<gm, 512, M_TOT * (int)sizeof(float)>>>(
        x, wq_w, wq_g, wq_b, wq_m, wq_v,
        wk_w, wk_g, wk_b, wk_m, wk_v,
        proj_w, proj_b, rpb1, rpb2,
        dy_w, dy_g, dy_b, dy_m, dy_v, out);
}

// round 10
// speedup vs baseline: 3.1941x; 1.0039x over previous
#include <cuda_runtime.h>

#define EPSF 1e-5f
#define LOG2E 1.4426950408889634f

typedef unsigned long long u64;

__device__ __forceinline__ u64 ffma2(u64 a, u64 b, u64 c) {
    u64 d;
    asm("fma.rn.f32x2 %0, %1, %2, %3;" : "=l"(d) : "l"(a), "l"(b), "l"(c));
    return d;
}
__device__ __forceinline__ u64 fadd2(u64 a, u64 b) {
    u64 d;
    asm("add.rn.f32x2 %0, %1, %2;" : "=l"(d) : "l"(a), "l"(b));
    return d;
}
__device__ __forceinline__ u64 pack2(float lo, float hi) {
    u64 d;
    asm("mov.b64 %0, {%1, %2};" : "=l"(d) : "f"(lo), "f"(hi));
    return d;
}
__device__ __forceinline__ float2 unpack2(u64 a) {
    float2 r;
    asm("mov.b64 {%0, %1}, %2;" : "=f"(r.x), "=f"(r.y) : "l"(a));
    return r;
}
// guaranteed single MUFU.EX2 (2^x), independent of fast-math flags
__device__ __forceinline__ float ex2a(float x) {
    float y;
    asm("ex2.approx.f32 %0, %1;" : "=f"(y) : "f"(x));
    return y;
}

// pair-row -> o mapping (38 rows per head; -1 = pad lane)
__host__ __device__ __forceinline__ int omap(int row, int par) {
    if (row < 10) { int ki = row >> 1, j = row & 1; return ki * 5 + 2 * j + par; }
    if (row < 13) { int sp = row - 10; int ki = 2 * sp + par;
                    return (sp == 2 && par == 1) ? -1 : (ki * 5 + 4); }
    if (row < 34) { int r2 = row - 13; int ki = r2 / 3, j = r2 % 3;
                    return 25 + ki * 7 + 2 * j + par; }
    int sp = row - 34; int ki = 2 * sp + par;
    return (sp == 3 && par == 1) ? -1 : (25 + ki * 7 + 6);
}

// ---------------------------------------------------------------------------
// device scratch (static allocation only)
// ---------------------------------------------------------------------------
__device__ float g_kp[8 * 32 * 49];         // pooled context [b][ci][pos]
__device__ float g_kpp[8 * 4 * 38 * 16];    // pair-interleaved proj-keys
__device__ unsigned int g_arrive;           // pool units done (target 256)
__device__ unsigned int g_ready;            // kc halves done (target 16)
__device__ unsigned int g_done;             // blocks finished (reset at 256)

// ---------------------------------------------------------------------------
// Shared memory layout (floats) -- 109712 B, 2 CTAs/SM
// ---------------------------------------------------------------------------
constexpr int M_XT1 = 0;        // 8640 ; pool scratch / scr / obs2 alias here
constexpr int M_XT2 = 8640;     // 11088
constexpr int M_BUF = 19728;    // 2432: wq(1024) -> kc kt(1568) -> kpp(2432)
constexpr int M_QB  = 22160;    // 32
constexpr int M_PBP = 22192;    // 76 (38 u64)
constexpr int M_R1  = 22268;    // 324
constexpr int M_R2  = 22592;    // 676
constexpr int M_DYW = 23268;    // 4096: pws(3626, kc blocks) -> folded dyw
constexpr int M_DYB = 27364;    // 64
constexpr int M_TOT = 27428;

__global__ void __launch_bounds__(512, 2)
mega_kernel(const float* __restrict__ x,
            const float* __restrict__ wq_w, const float* __restrict__ wq_g,
            const float* __restrict__ wq_b, const float* __restrict__ wq_m,
            const float* __restrict__ wq_v,
            const float* __restrict__ wk_w, const float* __restrict__ wk_g,
            const float* __restrict__ wk_b, const float* __restrict__ wk_m,
            const float* __restrict__ wk_v,
            const float* __restrict__ proj_w, const float* __restrict__ proj_b,
            const float* __restrict__ rpb1, const float* __restrict__ rpb2,
            const float* __restrict__ dy_w, const float* __restrict__ dy_g,
            const float* __restrict__ dy_b, const float* __restrict__ dy_m,
            const float* __restrict__ dy_v,
            float* __restrict__ out)
{
    extern __shared__ float sm[];
    float* xt1 = sm + M_XT1;
    float* xt2 = sm + M_XT2;
    float* buf = sm + M_BUF;
    float* qbs = sm + M_QB;
    float* pbp = sm + M_PBP;
    float* r1s = sm + M_R1;
    float* r2s = sm + M_R2;
    float* dyws = sm + M_DYW;
    float* dybs = sm + M_DYB;
    float* scr  = sm + M_XT1;          // part1 results alias
    float* obs2 = sm + M_XT1 + 4096;   // part2 results alias

    const int tid = threadIdx.x;
    const int b  = blockIdx.z;
    const int h0 = blockIdx.y * 16;
    const int w0 = blockIdx.x * 8;
    const int flat = (blockIdx.z * 4 + blockIdx.y) * 8 + blockIdx.x;  // 0..255
    const float* xb = x + (size_t)b * 64 * 4096;

    // ================= phase 0: pool one (batch, channel) unit =============
    {
        float* ch = xt1;            // 4096
        float* rp = xt1 + 4096;     // 448
        const int bp = flat >> 5;
        const int ci = flat & 31;
        const float4* src =
            (const float4*)(x + ((size_t)bp * 64 + 32 + ci) * 4096);
        float4* dst = (float4*)ch;
        dst[tid] = src[tid];
        dst[tid + 512] = src[tid + 512];
        __syncthreads();

        if (tid < 448) {
            const int r = tid / 7, q = tid % 7;
            const int sw = (q * 64) / 7;
            const int ew = ((q + 1) * 64 + 6) / 7;
            float acc = 0.f;
            for (int v = sw; v < ew; v++) acc += ch[r * 64 + v];
            rp[tid] = acc;
        }
        __syncthreads();

        if (tid < 49) {
            const int p = tid / 7, q = tid % 7;
            const int sh = (p * 64) / 7;
            const int eh = ((p + 1) * 64 + 6) / 7;
            const int sw = (q * 64) / 7;
            const int ew = ((q + 1) * 64 + 6) / 7;
            float acc = 0.f;
            for (int r = sh; r < eh; r++) acc += rp[r * 7 + q];
            g_kp[((size_t)bp * 32 + ci) * 49 + tid] =
                acc / (float)((eh - sh) * (ew - sw));
            __threadfence();
        }
        __syncthreads();
        if (tid == 0) atomicAdd(&g_arrive, 1u);
    }

    // ================= phase 1: staging (overwrites pool scratch) ==========
    for (int idx = tid; idx < 32 * 240; idx += 512) {
        const int t = idx % 12, s0 = (idx / 12) % 20, ch = idx / 240;
        const int gr = min(max(h0 - 2 + s0, 0), 63);
        const int gc = min(max(w0 - 2 + t, 0), 63);
        xt1[(s0 * 12 + t) * 36 + ch] = xb[ch * 4096 + gr * 64 + gc];
    }
    for (int idx = tid; idx < 32 * 308; idx += 512) {
        const int t = idx % 14, s0 = (idx / 14) % 22, ch = idx / 308;
        const int gr = min(max(h0 - 3 + s0, 0), 63);
        const int gc = min(max(w0 - 3 + t, 0), 63);
        xt2[(s0 * 14 + t) * 36 + ch] = xb[(32 + ch) * 4096 + gr * 64 + gc];
    }
    // wq fold (BN + SCALE + LOG2E) into buf
    for (int idx = tid; idx < 1024; idx += 512) {
        const int o = idx >> 5, i = idx & 31;
        const float alpha = wq_g[o] * rsqrtf(wq_v[o] + EPSF) * 0.25f * LOG2E;
        buf[idx] = alpha * wq_w[idx];
        if (i == 0)
            qbs[o] = 0.25f * LOG2E * wq_b[o] - wq_m[o] * alpha;
    }
    if (tid < 38) {
        const int o0 = omap(tid, 0), o1 = omap(tid, 1);
        pbp[2 * tid] = proj_b[o0] * LOG2E;
        pbp[2 * tid + 1] = (o1 >= 0) ? proj_b[o1] * LOG2E : -1e30f;
    }
    for (int idx = tid; idx < 324; idx += 512) r1s[idx] = rpb1[idx] * LOG2E;
    for (int idx = tid; idx < 676; idx += 512) r2s[idx] = rpb2[idx] * LOG2E;
    if (tid < 64) {
        const float alpha = dy_g[tid] * rsqrtf(dy_v[tid] + EPSF);
        dybs[tid] = dy_b[tid] - dy_m[tid] * alpha;
    }
    if (flat < 16) {
        for (int idx = tid; idx < 74 * 49; idx += 512) dyws[idx] = proj_w[idx];
    }
    __syncthreads();

    const int p = tid & 127;
    const int g = tid >> 7;
    const int ph = p >> 3, pwd = p & 7;
    const int h = h0 + ph, w = w0 + pwd;

    // ================= phase 2: q (log2-scaled) =============================
    u64 qq[8];
    {
        const float* xpix = xt1 + ((ph + 2) * 12 + (pwd + 2)) * 36;
        const float* wrow = buf + g * 8 * 32;
        u64 acc[8];
        #pragma unroll
        for (int c = 0; c < 8; c++) acc[c] = 0ull;
        #pragma unroll
        for (int i4 = 0; i4 < 8; i4++) {
            const ulonglong2 xv = *(const ulonglong2*)(xpix + i4 * 4);
            #pragma unroll
            for (int c = 0; c < 8; c++) {
                const ulonglong2 wv =
                    *(const ulonglong2*)(wrow + c * 32 + i4 * 4);
                acc[c] = ffma2(xv.x, wv.x, acc[c]);
                acc[c] = ffma2(xv.y, wv.y, acc[c]);
            }
        }
        #pragma unroll
        for (int c = 0; c < 8; c++) {
            const float2 f = unpack2(acc[c]);
            const float qc = qbs[g * 8 + c] + f.x + f.y;
            qq[c] = pack2(qc, qc);
        }
    }
    __syncthreads();   // wq dead; buf free for kc / kpp

    // ================= phase 3: kc (blocks 0..15 only) ======================
    if (flat < 16) {
        const int bkc = flat >> 1;
        const int half = flat & 1;
        if (tid == 0) { while (atomicAdd(&g_arrive, 0u) < 256u) { } }
        __syncthreads();
        __threadfence();

        for (int idx = tid; idx < 1568; idx += 512) {
            const int o = idx / 49, pos = idx % 49;
            const float alpha = wk_g[o] * rsqrtf(wk_v[o] + EPSF);
            const float beta  = wk_b[o] - wk_m[o] * alpha;
            float acc = 0.f;
            #pragma unroll
            for (int i = 0; i < 32; i++)
                acc += wk_w[o * 32 + i] * g_kp[((size_t)bkc * 32 + i) * 49 + pos];
            buf[(((o >> 3) * 49) + pos) * 8 + (o & 7)] = alpha * acc + beta;
        }
        __syncthreads();

        for (int idx = half * 1216 + tid; idx < half * 1216 + 1216; idx += 512) {
            const int gg = idx / 608;
            const int r16 = idx % 608;
            const int row = r16 >> 4;
            const int c = (r16 & 15) >> 1;
            const int par = r16 & 1;
            const int o = omap(row, par);
            float acc = 0.f;
            if (o >= 0) {
                #pragma unroll
                for (int l = 0; l < 49; l++)
                    acc += dyws[o * 49 + l] * buf[(gg * 49 + l) * 8 + c];
            }
            g_kpp[(size_t)bkc * 2432 + idx] = acc;
        }
        __threadfence();
        __syncthreads();
        if (tid == 0) atomicAdd(&g_ready, 1u);
    }

    // ================= phase 4: wait for kpp; stage kpp + dyw ===============
    if (tid == 0) { while (atomicAdd(&g_ready, 0u) < 16u) { } }
    __syncthreads();
    __threadfence();

    for (int idx = tid; idx < 2432; idx += 512)
        buf[idx] = g_kpp[(size_t)b * 2432 + idx];
    for (int idx = tid; idx < 4096; idx += 512) {
        const int o = idx >> 6;
        const float alpha = dy_g[o] * rsqrtf(dy_v[o] + EPSF);
        dyws[idx] = alpha * dy_w[idx];
    }
    __syncthreads();

    const int ihr = 63 - h, iwr = 63 - w;
    const float* kb = buf + g * 608;
    const u64* pbpu = (const u64*)pbp;

    #define PAIR_DOT(PR, ACCP) do {                                        \
        const float* kr_ = kb + (PR) * 16;                                 \
        const ulonglong2 kA_ = *(const ulonglong2*)kr_;                    \
        const ulonglong2 kB_ = *(const ulonglong2*)(kr_ + 4);              \
        const ulonglong2 kC_ = *(const ulonglong2*)(kr_ + 8);              \
        const ulonglong2 kD_ = *(const ulonglong2*)(kr_ + 12);             \
        u64 a0_ = ffma2(qq[0], kA_.x, 0ull);                               \
        u64 a1_ = ffma2(qq[1], kA_.y, 0ull);                               \
        a0_ = ffma2(qq[2], kB_.x, a0_);                                    \
        a1_ = ffma2(qq[3], kB_.y, a1_);                                    \
        a0_ = ffma2(qq[4], kC_.x, a0_);                                    \
        a1_ = ffma2(qq[5], kC_.y, a1_);                                    \
        a0_ = ffma2(qq[6], kD_.x, a0_);                                    \
        a1_ = ffma2(qq[7], kD_.y, a1_);                                    \
        ACCP = fadd2(a0_, a1_);                                            \
    } while (0)

    #define AGG(EE, ROWPTR) do {                                           \
        const ulonglong2 v0_ = *(const ulonglong2*)(ROWPTR);               \
        const ulonglong2 v1_ = *(const ulonglong2*)((ROWPTR) + 4);         \
        c0 = ffma2(EE, v0_.x, c0);                                         \
        c1 = ffma2(EE, v0_.y, c1);                                         \
        c2 = ffma2(EE, v1_.x, c2);                                         \
        c3 = ffma2(EE, v1_.y, c3);                                         \
    } while (0)

    // ===== part 1: 5x5 =====
    float o1v[8];
    {
        const int ih1 = min(ihr, 2) + max(0, ihr - 61);
        const int iw1 = min(iwr, 2) + max(0, iwr - 61);
        const float* r1g = r1s + g * 81 + ih1 * 9 + iw1;
        const int si = min(max(h - 2, 0), 59) - (h0 - 2);
        const int sj = min(max(w - 2, 0), 59) - (w0 - 2);

        u64 c0 = 0ull, c1 = 0ull, c2 = 0ull, c3 = 0ull;
        float sum = 0.f;
        #pragma unroll
        for (int ki = 0; ki < 5; ki++) {
            const float* row = xt1 + ((si + ki) * 12 + sj) * 36 + g * 8;
            #pragma unroll
            for (int j = 0; j < 2; j++) {
                const int pr = ki * 2 + j;
                u64 accp;
                PAIR_DOT(pr, accp);
                const u64 rp = pack2(r1g[ki * 9 + 2 * j],
                                     r1g[ki * 9 + 2 * j + 1]);
                const float2 f = unpack2(fadd2(accp, fadd2(pbpu[pr], rp)));
                const float e0 = ex2a(f.x), e1 = ex2a(f.y);
                sum += e0 + e1;
                AGG(pack2(e0, e0), row + (2 * j) * 36);
                AGG(pack2(e1, e1), row + (2 * j + 1) * 36);
            }
        }
        #pragma unroll
        for (int sp = 0; sp < 3; sp++) {
            u64 accp;
            PAIR_DOT(10 + sp, accp);
            const float rb0 = r1g[(2 * sp) * 9 + 4];
            const float rb1 = (sp < 2) ? r1g[(2 * sp + 1) * 9 + 4] : 0.f;
            const float2 f = unpack2(fadd2(accp,
                                     fadd2(pbpu[10 + sp], pack2(rb0, rb1))));
            const float e0 = ex2a(f.x), e1 = ex2a(f.y);
            sum += e0 + e1;   // e1 == 0 exactly for sp==2 (bias -1e30)
            const float* rowA =
                xt1 + ((si + 2 * sp) * 12 + sj) * 36 + g * 8 + 4 * 36;
            AGG(pack2(e0, e0), rowA);
            if (sp < 2) {
                const float* rowB =
                    xt1 + ((si + 2 * sp + 1) * 12 + sj) * 36 + g * 8 + 4 * 36;
                AGG(pack2(e1, e1), rowB);
            }
        }
        const float inv = 1.0f / sum;
        float2 f;
        f = unpack2(c0); o1v[0] = f.x * inv; o1v[1] = f.y * inv;
        f = unpack2(c1); o1v[2] = f.x * inv; o1v[3] = f.y * inv;
        f = unpack2(c2); o1v[4] = f.x * inv; o1v[5] = f.y * inv;
        f = unpack2(c3); o1v[6] = f.x * inv; o1v[7] = f.y * inv;
    }
    __syncthreads();   // all xt1 reads done

    *(float4*)(scr + p * 32 + ((2 * g + p) & 7) * 4) =
        make_float4(o1v[0], o1v[1], o1v[2], o1v[3]);
    *(float4*)(scr + p * 32 + ((2 * g + 1 + p) & 7) * 4) =
        make_float4(o1v[4], o1v[5], o1v[6], o1v[7]);

    // ===== part 2: 7x7 =====
    {
        const int ih2 = min(ihr, 3) + max(0, ihr - 60);
        const int iw2 = min(iwr, 3) + max(0, iwr - 60);
        const float* r2g = r2s + g * 169 + ih2 * 13 + iw2;
        const int si = min(max(h - 3, 0), 57) - (h0 - 3);
        const int sj = min(max(w - 3, 0), 57) - (w0 - 3);

        u64 c0 = 0ull, c1 = 0ull, c2 = 0ull, c3 = 0ull;
        float sum = 0.f;
        #pragma unroll
        for (int ki = 0; ki < 7; ki++) {
            const float* row = xt2 + ((si + ki) * 14 + sj) * 36 + g * 8;
            #pragma unroll
            for (int j = 0; j < 3; j++) {
                const int pr = 13 + ki * 3 + j;
                u64 accp;
                PAIR_DOT(pr, accp);
                const u64 rp = pack2(r2g[ki * 13 + 2 * j],
                                     r2g[ki * 13 + 2 * j + 1]);
                const float2 f = unpack2(fadd2(accp, fadd2(pbpu[pr], rp)));
                const float e0 = ex2a(f.x), e1 = ex2a(f.y);
                sum += e0 + e1;
                AGG(pack2(e0, e0), row + (2 * j) * 36);
                AGG(pack2(e1, e1), row + (2 * j + 1) * 36);
            }
        }
        #pragma unroll
        for (int sp = 0; sp < 4; sp++) {
            u64 accp;
            PAIR_DOT(34 + sp, accp);
            const float rb0 = r2g[(2 * sp) * 13 + 6];
            const float rb1 = (sp < 3) ? r2g[(2 * sp + 1) * 13 + 6] : 0.f;
            const float2 f = unpack2(fadd2(accp,
                                     fadd2(pbpu[34 + sp], pack2(rb0, rb1))));
            const float e0 = ex2a(f.x), e1 = ex2a(f.y);
            sum += e0 + e1;
            const float* rowA =
                xt2 + ((si + 2 * sp) * 14 + sj) * 36 + g * 8 + 6 * 36;
            AGG(pack2(e0, e0), rowA);
            if (sp < 3) {
                const float* rowB =
                    xt2 + ((si + 2 * sp + 1) * 14 + sj) * 36 + g * 8 + 6 * 36;
                AGG(pack2(e1, e1), rowB);
            }
        }
        const float inv = 1.0f / sum;
        float2 f0 = unpack2(c0), f1 = unpack2(c1);
        float2 f2 = unpack2(c2), f3 = unpack2(c3);
        *(float4*)(obs2 + p * 32 + ((2 * g + p) & 7) * 4) =
            make_float4(f0.x * inv, f0.y * inv, f1.x * inv, f1.y * inv);
        *(float4*)(obs2 + p * 32 + ((2 * g + 1 + p) & 7) * 4) =
            make_float4(f2.x * inv, f2.y * inv, f3.x * inv, f3.y * inv);
    }
    __syncthreads();

    // ===== dy conv + BN: 2 pixels x 8 channels per thread =====
    {
        const int pp = tid & 63;
        const int cg = tid >> 6;
        u64 acc[16];
        #pragma unroll
        for (int k = 0; k < 16; k++) acc[k] = 0ull;

        #pragma unroll
        for (int s = 0; s < 16; s++) {
            const float* sb = (s < 8) ? scr : obs2;
            const int lc = s & 7;
            const ulonglong2 xvA =
                *(const ulonglong2*)(sb + pp * 32 + ((lc + pp) & 7) * 4);
            const ulonglong2 xvB =
                *(const ulonglong2*)(sb + (pp + 64) * 32 + ((lc + pp + 64) & 7) * 4);
            #pragma unroll
            for (int k = 0; k < 8; k++) {
                const ulonglong2 wv =
                    *(const ulonglong2*)(dyws + (cg * 8 + k) * 64 + s * 4);
                acc[k]     = ffma2(xvA.x, wv.x, acc[k]);
                acc[k]     = ffma2(xvA.y, wv.y, acc[k]);
                acc[8 + k] = ffma2(xvB.x, wv.x, acc[8 + k]);
                acc[8 + k] = ffma2(xvB.y, wv.y, acc[8 + k]);
            }
        }
        const int hA = h0 + (pp >> 3), wA = w0 + (pp & 7);
        const int hB = h0 + ((pp + 64) >> 3), wB = w0 + (pp & 7);
        float* outA = out + (size_t)b * 262144 + hA * 64 + wA;
        float* outB = out + (size_t)b * 262144 + hB * 64 + wB;
        #pragma unroll
        for (int k = 0; k < 8; k++) {
            const int oc = cg * 8 + k;
            const float2 fA = unpack2(acc[k]);
            const float2 fB = unpack2(acc[8 + k]);
            outA[(size_t)oc * 4096] = fA.x + fA.y + dybs[oc];
            outB[(size_t)oc * 4096] = fB.x + fB.y + dybs[oc];
        }
    }
    #undef PAIR_DOT
    #undef AGG

    // ================= phase 6: counter reset (graph-replay safe) ==========
    __syncthreads();
    if (tid == 0) {
        const unsigned old = atomicAdd(&g_done, 1u);
        if (old == 255u) {
            atomicExch(&g_arrive, 0u);
            atomicExch(&g_ready, 0u);
            atomicExch(&g_done, 0u);
        }
    }
}

// ---------------------------------------------------------------------------
extern "C" void kernel_launch(void* const* d_in, const int* in_sizes, int n_in,
                              void* d_out, int out_size)
{
    const float* x      = (const float*)d_in[0];
    const float* wq_w   = (const float*)d_in[1];
    const float* wq_g   = (const float*)d_in[2];
    const float* wq_b   = (const float*)d_in[3];
    const float* wq_m   = (const float*)d_in[4];
    const float* wq_v   = (const float*)d_in[5];
    const float* wk_w   = (const float*)d_in[6];
    const float* wk_g   = (const float*)d_in[7];
    const float* wk_b   = (const float*)d_in[8];
    const float* wk_m   = (const float*)d_in[9];
    const float* wk_v   = (const float*)d_in[10];
    const float* proj_w = (const float*)d_in[11];
    const float* proj_b = (const float*)d_in[12];
    const float* rpb1   = (const float*)d_in[13];
    const float* rpb2   = (const float*)d_in[14];
    const float* dy_w   = (const float*)d_in[15];
    const float* dy_g   = (const float*)d_in[16];
    const float* dy_b   = (const float*)d_in[17];
    const float* dy_m   = (const float*)d_in[18];
    const float* dy_v   = (const float*)d_in[19];
    float* out = (float*)d_out;

    cudaFuncSetAttribute(mega_kernel,
                         cudaFuncAttributeMaxDynamicSharedMemorySize,
                         M_TOT * (int)sizeof(float));

    dim3 gm(8, 4, 8);
    mega_kernel<<<gm, 512, M_TOT * (int)sizeof(float)>>>(
        x, wq_w, wq_g, wq_b, wq_m, wq_v,
        wk_w, wk_g, wk_b, wk_m, wk_v,
        proj_w, proj_b, rpb1, rpb2,
        dy_w, dy_g, dy_b, dy_m, dy_v, out);
}

// round 11
// speedup vs baseline: 3.3304x; 1.0427x over previous
#include <cuda_runtime.h>

#define EPSF 1e-5f
#define LOG2E 1.4426950408889634f

typedef unsigned long long u64;

__device__ __forceinline__ u64 ffma2(u64 a, u64 b, u64 c) {
    u64 d;
    asm("fma.rn.f32x2 %0, %1, %2, %3;" : "=l"(d) : "l"(a), "l"(b), "l"(c));
    return d;
}
__device__ __forceinline__ u64 fadd2(u64 a, u64 b) {
    u64 d;
    asm("add.rn.f32x2 %0, %1, %2;" : "=l"(d) : "l"(a), "l"(b));
    return d;
}
__device__ __forceinline__ u64 pack2(float lo, float hi) {
    u64 d;
    asm("mov.b64 %0, {%1, %2};" : "=l"(d) : "f"(lo), "f"(hi));
    return d;
}
__device__ __forceinline__ float2 unpack2(u64 a) {
    float2 r;
    asm("mov.b64 {%0, %1}, %2;" : "=f"(r.x), "=f"(r.y) : "l"(a));
    return r;
}
// guaranteed single MUFU.EX2 (2^x)
__device__ __forceinline__ float ex2a(float x) {
    float y;
    asm("ex2.approx.f32 %0, %1;" : "=f"(y) : "f"(x));
    return y;
}
// acquire load for spin-waits (cheaper than atomicAdd polling)
__device__ __forceinline__ unsigned int ld_acq(const unsigned int* p) {
    unsigned int v;
    asm volatile("ld.global.acquire.gpu.u32 %0, [%1];" : "=r"(v) : "l"(p));
    return v;
}

// pair-row -> o mapping (38 rows per head; -1 = pad lane)
__host__ __device__ __forceinline__ int omap(int row, int par) {
    if (row < 10) { int ki = row >> 1, j = row & 1; return ki * 5 + 2 * j + par; }
    if (row < 13) { int sp = row - 10; int ki = 2 * sp + par;
                    return (sp == 2 && par == 1) ? -1 : (ki * 5 + 4); }
    if (row < 34) { int r2 = row - 13; int ki = r2 / 3, j = r2 % 3;
                    return 25 + ki * 7 + 2 * j + par; }
    int sp = row - 34; int ki = 2 * sp + par;
    return (sp == 3 && par == 1) ? -1 : (25 + ki * 7 + 6);
}

// ---------------------------------------------------------------------------
// device scratch (static allocation only)
// ---------------------------------------------------------------------------
__device__ float g_kp[8 * 32 * 49];         // pooled context [b][ci][pos]
__device__ float g_kpp[8 * 4 * 38 * 16];    // pair-interleaved proj-keys
__device__ unsigned int g_arriveB[8];       // per-batch pool units done (32)
__device__ unsigned int g_readyB[8];        // per-batch kc halves done (2)
__device__ unsigned int g_done;             // blocks finished (reset at 256)

// ---------------------------------------------------------------------------
// Shared memory layout (floats) -- 109712 B, 2 CTAs/SM
// ---------------------------------------------------------------------------
constexpr int M_XT1 = 0;        // 8640 ; pool scratch / scr / obs2 alias here
constexpr int M_XT2 = 8640;     // 11088
constexpr int M_BUF = 19728;    // 2432: wq(1024) -> kc kt(1568) -> kpp(2432)
constexpr int M_QB  = 22160;    // 32
constexpr int M_PBP = 22192;    // 76 (38 u64)
constexpr int M_R1  = 22268;    // 324
constexpr int M_R2  = 22592;    // 676
constexpr int M_DYW = 23268;    // 4096: pws (kc blocks) / folded dyw (others)
constexpr int M_DYB = 27364;    // 64
constexpr int M_TOT = 27428;

__global__ void __launch_bounds__(512, 2)
mega_kernel(const float* __restrict__ x,
            const float* __restrict__ wq_w, const float* __restrict__ wq_g,
            const float* __restrict__ wq_b, const float* __restrict__ wq_m,
            const float* __restrict__ wq_v,
            const float* __restrict__ wk_w, const float* __restrict__ wk_g,
            const float* __restrict__ wk_b, const float* __restrict__ wk_m,
            const float* __restrict__ wk_v,
            const float* __restrict__ proj_w, const float* __restrict__ proj_b,
            const float* __restrict__ rpb1, const float* __restrict__ rpb2,
            const float* __restrict__ dy_w, const float* __restrict__ dy_g,
            const float* __restrict__ dy_b, const float* __restrict__ dy_m,
            const float* __restrict__ dy_v,
            float* __restrict__ out)
{
    extern __shared__ float sm[];
    float* xt1 = sm + M_XT1;
    float* xt2 = sm + M_XT2;
    float* buf = sm + M_BUF;
    float* qbs = sm + M_QB;
    float* pbp = sm + M_PBP;
    float* r1s = sm + M_R1;
    float* r2s = sm + M_R2;
    float* dyws = sm + M_DYW;
    float* dybs = sm + M_DYB;
    float* scr  = sm + M_XT1;          // part1 results alias
    float* obs2 = sm + M_XT1 + 4096;   // part2 results alias

    const int tid = threadIdx.x;
    const int b  = blockIdx.z;
    const int h0 = blockIdx.y * 16;
    const int w0 = blockIdx.x * 8;
    const int flat = (blockIdx.z * 4 + blockIdx.y) * 8 + blockIdx.x;  // 0..255
    const float* xb = x + (size_t)b * 64 * 4096;

    // ================= phase 0: pool one (batch, channel) unit =============
    {
        float* ch = xt1;            // 4096
        float* rp = xt1 + 4096;     // 448
        const int bp = flat >> 5;
        const int ci = flat & 31;
        const float4* src =
            (const float4*)(x + ((size_t)bp * 64 + 32 + ci) * 4096);
        float4* dst = (float4*)ch;
        dst[tid] = src[tid];
        dst[tid + 512] = src[tid + 512];
        __syncthreads();

        if (tid < 448) {
            const int r = tid / 7, q = tid % 7;
            const int sw = (q * 64) / 7;
            const int ew = ((q + 1) * 64 + 6) / 7;
            float acc = 0.f;
            for (int v = sw; v < ew; v++) acc += ch[r * 64 + v];
            rp[tid] = acc;
        }
        __syncthreads();

        if (tid < 49) {
            const int p = tid / 7, q = tid % 7;
            const int sh = (p * 64) / 7;
            const int eh = ((p + 1) * 64 + 6) / 7;
            const int sw = (q * 64) / 7;
            const int ew = ((q + 1) * 64 + 6) / 7;
            float acc = 0.f;
            for (int r = sh; r < eh; r++) acc += rp[r * 7 + q];
            g_kp[((size_t)bp * 32 + ci) * 49 + tid] =
                acc / (float)((eh - sh) * (ew - sw));
        }
        __syncthreads();
        if (tid == 0) {
            __threadfence();
            atomicAdd(&g_arriveB[bp], 1u);
        }
    }

    // ================= phase 1: staging (overwrites pool scratch) ==========
    for (int idx = tid; idx < 32 * 240; idx += 512) {
        const int t = idx % 12, s0 = (idx / 12) % 20, ch = idx / 240;
        const int gr = min(max(h0 - 2 + s0, 0), 63);
        const int gc = min(max(w0 - 2 + t, 0), 63);
        xt1[(s0 * 12 + t) * 36 + ch] = xb[ch * 4096 + gr * 64 + gc];
    }
    for (int idx = tid; idx < 32 * 308; idx += 512) {
        const int t = idx % 14, s0 = (idx / 14) % 22, ch = idx / 308;
        const int gr = min(max(h0 - 3 + s0, 0), 63);
        const int gc = min(max(w0 - 3 + t, 0), 63);
        xt2[(s0 * 14 + t) * 36 + ch] = xb[(32 + ch) * 4096 + gr * 64 + gc];
    }
    // wq fold (BN + SCALE + LOG2E) into buf
    for (int idx = tid; idx < 1024; idx += 512) {
        const int o = idx >> 5, i = idx & 31;
        const float alpha = wq_g[o] * rsqrtf(wq_v[o] + EPSF) * 0.25f * LOG2E;
        buf[idx] = alpha * wq_w[idx];
        if (i == 0)
            qbs[o] = 0.25f * LOG2E * wq_b[o] - wq_m[o] * alpha;
    }
    if (tid < 38) {
        const int o0 = omap(tid, 0), o1 = omap(tid, 1);
        pbp[2 * tid] = proj_b[o0] * LOG2E;
        pbp[2 * tid + 1] = (o1 >= 0) ? proj_b[o1] * LOG2E : -1e30f;
    }
    for (int idx = tid; idx < 324; idx += 512) r1s[idx] = rpb1[idx] * LOG2E;
    for (int idx = tid; idx < 676; idx += 512) r2s[idx] = rpb2[idx] * LOG2E;
    if (tid < 64) {
        const float alpha = dy_g[tid] * rsqrtf(dy_v[tid] + EPSF);
        dybs[tid] = dy_b[tid] - dy_m[tid] * alpha;
    }
    if (flat < 16) {
        // kc blocks: dyws region holds proj_w for the kpp fold
        for (int idx = tid; idx < 74 * 49; idx += 512) dyws[idx] = proj_w[idx];
    } else {
        // everyone else: fold dyw now (pre-spin), nothing to do later
        for (int idx = tid; idx < 4096; idx += 512) {
            const int o = idx >> 6;
            const float alpha = dy_g[o] * rsqrtf(dy_v[o] + EPSF);
            dyws[idx] = alpha * dy_w[idx];
        }
    }
    __syncthreads();

    const int p = tid & 127;
    const int g = tid >> 7;
    const int ph = p >> 3, pwd = p & 7;
    const int h = h0 + ph, w = w0 + pwd;

    // ================= phase 2: q (log2-scaled) =============================
    u64 qq[8];
    {
        const float* xpix = xt1 + ((ph + 2) * 12 + (pwd + 2)) * 36;
        const float* wrow = buf + g * 8 * 32;
        u64 acc[8];
        #pragma unroll
        for (int c = 0; c < 8; c++) acc[c] = 0ull;
        #pragma unroll
        for (int i4 = 0; i4 < 8; i4++) {
            const ulonglong2 xv = *(const ulonglong2*)(xpix + i4 * 4);
            #pragma unroll
            for (int c = 0; c < 8; c++) {
                const ulonglong2 wv =
                    *(const ulonglong2*)(wrow + c * 32 + i4 * 4);
                acc[c] = ffma2(xv.x, wv.x, acc[c]);
                acc[c] = ffma2(xv.y, wv.y, acc[c]);
            }
        }
        #pragma unroll
        for (int c = 0; c < 8; c++) {
            const float2 f = unpack2(acc[c]);
            const float qc = qbs[g * 8 + c] + f.x + f.y;
            qq[c] = pack2(qc, qc);
        }
    }
    __syncthreads();   // wq dead; buf free for kc / kpp

    // ================= phase 3: kc (blocks 0..15 only) ======================
    if (flat < 16) {
        const int bkc = flat >> 1;
        const int half = flat & 1;
        if (tid == 0) { while (ld_acq(&g_arriveB[bkc]) < 32u) { } }
        __syncthreads();
        __threadfence();

        for (int idx = tid; idx < 1568; idx += 512) {
            const int o = idx / 49, pos = idx % 49;
            const float alpha = wk_g[o] * rsqrtf(wk_v[o] + EPSF);
            const float beta  = wk_b[o] - wk_m[o] * alpha;
            float acc = 0.f;
            #pragma unroll
            for (int i = 0; i < 32; i++)
                acc += wk_w[o * 32 + i] * g_kp[((size_t)bkc * 32 + i) * 49 + pos];
            buf[(((o >> 3) * 49) + pos) * 8 + (o & 7)] = alpha * acc + beta;
        }
        __syncthreads();

        for (int idx = half * 1216 + tid; idx < half * 1216 + 1216; idx += 512) {
            const int gg = idx / 608;
            const int r16 = idx % 608;
            const int row = r16 >> 4;
            const int c = (r16 & 15) >> 1;
            const int par = r16 & 1;
            const int o = omap(row, par);
            float acc = 0.f;
            if (o >= 0) {
                #pragma unroll
                for (int l = 0; l < 49; l++)
                    acc += dyws[o * 49 + l] * buf[(gg * 49 + l) * 8 + c];
            }
            g_kpp[(size_t)bkc * 2432 + idx] = acc;
        }
        __threadfence();
        __syncthreads();
        if (tid == 0) atomicAdd(&g_readyB[bkc], 1u);
    }

    // ================= phase 4: wait for own batch's kpp ====================
    if (tid == 0) { while (ld_acq(&g_readyB[b]) < 2u) { } }
    __syncthreads();
    __threadfence();

    for (int idx = tid; idx < 2432; idx += 512)
        buf[idx] = g_kpp[(size_t)b * 2432 + idx];
    if (flat < 16) {
        // kc blocks fold dyw now (their dyws held proj_w until here)
        for (int idx = tid; idx < 4096; idx += 512) {
            const int o = idx >> 6;
            const float alpha = dy_g[o] * rsqrtf(dy_v[o] + EPSF);
            dyws[idx] = alpha * dy_w[idx];
        }
    }
    __syncthreads();

    const int ihr = 63 - h, iwr = 63 - w;
    const float* kb = buf + g * 608;
    const u64* pbpu = (const u64*)pbp;

    #define PAIR_DOT(PR, ACCP) do {                                        \
        const float* kr_ = kb + (PR) * 16;                                 \
        const ulonglong2 kA_ = *(const ulonglong2*)kr_;                    \
        const ulonglong2 kB_ = *(const ulonglong2*)(kr_ + 4);              \
        const ulonglong2 kC_ = *(const ulonglong2*)(kr_ + 8);              \
        const ulonglong2 kD_ = *(const ulonglong2*)(kr_ + 12);             \
        u64 a0_ = ffma2(qq[0], kA_.x, 0ull);                               \
        u64 a1_ = ffma2(qq[1], kA_.y, 0ull);                               \
        a0_ = ffma2(qq[2], kB_.x, a0_);                                    \
        a1_ = ffma2(qq[3], kB_.y, a1_);                                    \
        a0_ = ffma2(qq[4], kC_.x, a0_);                                    \
        a1_ = ffma2(qq[5], kC_.y, a1_);                                    \
        a0_ = ffma2(qq[6], kD_.x, a0_);                                    \
        a1_ = ffma2(qq[7], kD_.y, a1_);                                    \
        ACCP = fadd2(a0_, a1_);                                            \
    } while (0)

    #define AGG(EE, ROWPTR) do {                                           \
        const ulonglong2 v0_ = *(const ulonglong2*)(ROWPTR);               \
        const ulonglong2 v1_ = *(const ulonglong2*)((ROWPTR) + 4);         \
        c0 = ffma2(EE, v0_.x, c0);                                         \
        c1 = ffma2(EE, v0_.y, c1);                                         \
        c2 = ffma2(EE, v1_.x, c2);                                         \
        c3 = ffma2(EE, v1_.y, c3);                                         \
    } while (0)

    // ===== part 1: 5x5 =====
    float o1v[8];
    {
        const int ih1 = min(ihr, 2) + max(0, ihr - 61);
        const int iw1 = min(iwr, 2) + max(0, iwr - 61);
        const float* r1g = r1s + g * 81 + ih1 * 9 + iw1;
        const int si = min(max(h - 2, 0), 59) - (h0 - 2);
        const int sj = min(max(w - 2, 0), 59) - (w0 - 2);

        u64 c0 = 0ull, c1 = 0ull, c2 = 0ull, c3 = 0ull;
        float sum0 = 0.f, sum1 = 0.f;
        #pragma unroll
        for (int ki = 0; ki < 5; ki++) {
            const float* row = xt1 + ((si + ki) * 12 + sj) * 36 + g * 8;
            #pragma unroll
            for (int j = 0; j < 2; j++) {
                const int pr = ki * 2 + j;
                u64 accp;
                PAIR_DOT(pr, accp);
                const u64 rp = pack2(r1g[ki * 9 + 2 * j],
                                     r1g[ki * 9 + 2 * j + 1]);
                const float2 f = unpack2(fadd2(accp, fadd2(pbpu[pr], rp)));
                const float e0 = ex2a(f.x), e1 = ex2a(f.y);
                sum0 += e0; sum1 += e1;
                AGG(pack2(e0, e0), row + (2 * j) * 36);
                AGG(pack2(e1, e1), row + (2 * j + 1) * 36);
            }
        }
        #pragma unroll
        for (int sp = 0; sp < 3; sp++) {
            u64 accp;
            PAIR_DOT(10 + sp, accp);
            const float rb0 = r1g[(2 * sp) * 9 + 4];
            const float rb1 = (sp < 2) ? r1g[(2 * sp + 1) * 9 + 4] : 0.f;
            const float2 f = unpack2(fadd2(accp,
                                     fadd2(pbpu[10 + sp], pack2(rb0, rb1))));
            const float e0 = ex2a(f.x), e1 = ex2a(f.y);
            sum0 += e0; sum1 += e1;   // e1 == 0 exactly for sp==2
            const float* rowA =
                xt1 + ((si + 2 * sp) * 12 + sj) * 36 + g * 8 + 4 * 36;
            AGG(pack2(e0, e0), rowA);
            if (sp < 2) {
                const float* rowB =
                    xt1 + ((si + 2 * sp + 1) * 12 + sj) * 36 + g * 8 + 4 * 36;
                AGG(pack2(e1, e1), rowB);
            }
        }
        const float inv = 1.0f / (sum0 + sum1);
        float2 f;
        f = unpack2(c0); o1v[0] = f.x * inv; o1v[1] = f.y * inv;
        f = unpack2(c1); o1v[2] = f.x * inv; o1v[3] = f.y * inv;
        f = unpack2(c2); o1v[4] = f.x * inv; o1v[5] = f.y * inv;
        f = unpack2(c3); o1v[6] = f.x * inv; o1v[7] = f.y * inv;
    }
    __syncthreads();   // all xt1 reads done

    *(float4*)(scr + p * 32 + ((2 * g + p) & 7) * 4) =
        make_float4(o1v[0], o1v[1], o1v[2], o1v[3]);
    *(float4*)(scr + p * 32 + ((2 * g + 1 + p) & 7) * 4) =
        make_float4(o1v[4], o1v[5], o1v[6], o1v[7]);

    // ===== part 2: 7x7 =====
    {
        const int ih2 = min(ihr, 3) + max(0, ihr - 60);
        const int iw2 = min(iwr, 3) + max(0, iwr - 60);
        const float* r2g = r2s + g * 169 + ih2 * 13 + iw2;
        const int si = min(max(h - 3, 0), 57) - (h0 - 3);
        const int sj = min(max(w - 3, 0), 57) - (w0 - 3);

        u64 c0 = 0ull, c1 = 0ull, c2 = 0ull, c3 = 0ull;
        float sum0 = 0.f, sum1 = 0.f;
        #pragma unroll
        for (int ki = 0; ki < 7; ki++) {
            const float* row = xt2 + ((si + ki) * 14 + sj) * 36 + g * 8;
            #pragma unroll
            for (int j = 0; j < 3; j++) {
                const int pr = 13 + ki * 3 + j;
                u64 accp;
                PAIR_DOT(pr, accp);
                const u64 rp = pack2(r2g[ki * 13 + 2 * j],
                                     r2g[ki * 13 + 2 * j + 1]);
                const float2 f = unpack2(fadd2(accp, fadd2(pbpu[pr], rp)));
                const float e0 = ex2a(f.x), e1 = ex2a(f.y);
                sum0 += e0; sum1 += e1;
                AGG(pack2(e0, e0), row + (2 * j) * 36);
                AGG(pack2(e1, e1), row + (2 * j + 1) * 36);
            }
        }
        #pragma unroll
        for (int sp = 0; sp < 4; sp++) {
            u64 accp;
            PAIR_DOT(34 + sp, accp);
            const float rb0 = r2g[(2 * sp) * 13 + 6];
            const float rb1 = (sp < 3) ? r2g[(2 * sp + 1) * 13 + 6] : 0.f;
            const float2 f = unpack2(fadd2(accp,
                                     fadd2(pbpu[34 + sp], pack2(rb0, rb1))));
            const float e0 = ex2a(f.x), e1 = ex2a(f.y);
            sum0 += e0; sum1 += e1;
            const float* rowA =
                xt2 + ((si + 2 * sp) * 14 + sj) * 36 + g * 8 + 6 * 36;
            AGG(pack2(e0, e0), rowA);
            if (sp < 3) {
                const float* rowB =
                    xt2 + ((si + 2 * sp + 1) * 14 + sj) * 36 + g * 8 + 6 * 36;
                AGG(pack2(e1, e1), rowB);
            }
        }
        const float inv = 1.0f / (sum0 + sum1);
        float2 f0 = unpack2(c0), f1 = unpack2(c1);
        float2 f2 = unpack2(c2), f3 = unpack2(c3);
        *(float4*)(obs2 + p * 32 + ((2 * g + p) & 7) * 4) =
            make_float4(f0.x * inv, f0.y * inv, f1.x * inv, f1.y * inv);
        *(float4*)(obs2 + p * 32 + ((2 * g + 1 + p) & 7) * 4) =
            make_float4(f2.x * inv, f2.y * inv, f3.x * inv, f3.y * inv);
    }
    __syncthreads();

    // ===== dy conv + BN: 2 pixels x 8 channels per thread =====
    {
        const int pp = tid & 63;
        const int cg = tid >> 6;
        u64 acc[16];
        #pragma unroll
        for (int k = 0; k < 16; k++) acc[k] = 0ull;

        #pragma unroll
        for (int s = 0; s < 16; s++) {
            const float* sb = (s < 8) ? scr : obs2;
            const int lc = s & 7;
            const ulonglong2 xvA =
                *(const ulonglong2*)(sb + pp * 32 + ((lc + pp) & 7) * 4);
            const ulonglong2 xvB =
                *(const ulonglong2*)(sb + (pp + 64) * 32 + ((lc + pp + 64) & 7) * 4);
            #pragma unroll
            for (int k = 0; k < 8; k++) {
                const ulonglong2 wv =
                    *(const ulonglong2*)(dyws + (cg * 8 + k) * 64 + s * 4);
                acc[k]     = ffma2(xvA.x, wv.x, acc[k]);
                acc[k]     = ffma2(xvA.y, wv.y, acc[k]);
                acc[8 + k] = ffma2(xvB.x, wv.x, acc[8 + k]);
                acc[8 + k] = ffma2(xvB.y, wv.y, acc[8 + k]);
            }
        }
        const int hA = h0 + (pp >> 3), wA = w0 + (pp & 7);
        const int hB = h0 + ((pp + 64) >> 3), wB = w0 + (pp & 7);
        float* outA = out + (size_t)b * 262144 + hA * 64 + wA;
        float* outB = out + (size_t)b * 262144 + hB * 64 + wB;
        #pragma unroll
        for (int k = 0; k < 8; k++) {
            const int oc = cg * 8 + k;
            const float2 fA = unpack2(acc[k]);
            const float2 fB = unpack2(acc[8 + k]);
            outA[(size_t)oc * 4096] = fA.x + fA.y + dybs[oc];
            outB[(size_t)oc * 4096] = fB.x + fB.y + dybs[oc];
        }
    }
    #undef PAIR_DOT
    #undef AGG

    // ================= phase 6: counter reset (graph-replay safe) ==========
    __syncthreads();
    if (tid == 0) {
        const unsigned old = atomicAdd(&g_done, 1u);
        if (old == 255u) {
            #pragma unroll
            for (int i = 0; i < 8; i++) {
                atomicExch(&g_arriveB[i], 0u);
                atomicExch(&g_readyB[i], 0u);
            }
            atomicExch(&g_done, 0u);
        }
    }
}

// ---------------------------------------------------------------------------
extern "C" void kernel_launch(void* const* d_in, const int* in_sizes, int n_in,
                              void* d_out, int out_size)
{
    const float* x      = (const float*)d_in[0];
    const float* wq_w   = (const float*)d_in[1];
    const float* wq_g   = (const float*)d_in[2];
    const float* wq_b   = (const float*)d_in[3];
    const float* wq_m   = (const float*)d_in[4];
    const float* wq_v   = (const float*)d_in[5];
    const float* wk_w   = (const float*)d_in[6];
    const float* wk_g   = (const float*)d_in[7];
    const float* wk_b   = (const float*)d_in[8];
    const float* wk_m   = (const float*)d_in[9];
    const float* wk_v   = (const float*)d_in[10];
    const float* proj_w = (const float*)d_in[11];
    const float* proj_b = (const float*)d_in[12];
    const float* rpb1   = (const float*)d_in[13];
    const float* rpb2   = (const float*)d_in[14];
    const float* dy_w   = (const float*)d_in[15];
    const float* dy_g   = (const float*)d_in[16];
    const float* dy_b   = (const float*)d_in[17];
    const float* dy_m   = (const float*)d_in[18];
    const float* dy_v   = (const float*)d_in[19];
    float* out = (float*)d_out;

    cudaFuncSetAttribute(mega_kernel,
                         cudaFuncAttributeMaxDynamicSharedMemorySize,
                         M_TOT * (int)sizeof(float));

    dim3 gm(8, 4, 8);
    mega_kernel<<<gm, 512, M_TOT * (int)sizeof(float)>>>(
        x, wq_w, wq_g, wq_b, wq_m, wq_v,
        wk_w, wk_g, wk_b, wk_m, wk_v,
        proj_w, proj_b, rpb1, rpb2,
        dy_w, dy_g, dy_b, dy_m, dy_v, out);
}